// round 5
// baseline (speedup 1.0000x reference)
#include <cuda_runtime.h>
#include <math.h>

#define NN 50000
#define NE 800000
#define AD 128
#define SD 64
#define NL 4

// ---------------- scratch (static device globals; no allocation) ----------------
__device__ float d_h2[NN * AD];     // GCN post-GEMM features, pre-scaled by dinv[row]
__device__ float d_hbuf[NN * AD];   // GCN inter-layer buffer
__device__ float d_t[NN * SD];      // GNA w2 output
__device__ float d_u[NN * SD];      // GNA w1 output (pre-attention)
__device__ float d_gbuf[NN * SD];   // GNA inter-layer buffer
__device__ float d_proj[NN];        // t . a
__device__ float d_dinv[NN];
__device__ int   d_deg[NN];
__device__ int   d_off[NN + 1];     // CSR offsets (dst-grouped)
__device__ int   d_cur[NN];
__device__ int   d_csrc[NE];        // CSR src per position

__device__ __forceinline__ float gelu_exact(float x) {
    return 0.5f * x * (1.0f + erff(x * 0.7071067811865476f));
}

// ---------------- degree / CSR build ----------------
__global__ void k_deg_count(const int* __restrict__ ei) {
    int i = blockIdx.x * blockDim.x + threadIdx.x;
    if (i < NE / 4) {
        int4 d4 = reinterpret_cast<const int4*>(ei + NE)[i];
        atomicAdd(&d_deg[d4.x], 1);
        atomicAdd(&d_deg[d4.y], 1);
        atomicAdd(&d_deg[d4.z], 1);
        atomicAdd(&d_deg[d4.w], 1);
    }
}

__global__ void k_dinv() {
    int n = blockIdx.x * blockDim.x + threadIdx.x;
    if (n < NN) d_dinv[n] = rsqrtf((float)(d_deg[n] + 1));
}

// single-block exclusive scan of d_deg into d_off; also seeds d_cur = d_off[n]
__global__ void k_scan() {
    __shared__ int warpsums[32];
    int tid = threadIdx.x, lane = tid & 31, wid = tid >> 5;
    int carry = 0;
    if (tid == 0) d_off[0] = 0;
    for (int base = 0; base < NN; base += 1024) {
        int idx = base + tid;
        int v = (idx < NN) ? d_deg[idx] : 0;
        int x = v;
        #pragma unroll
        for (int o = 1; o < 32; o <<= 1) {
            int y = __shfl_up_sync(0xffffffffu, x, o);
            if (lane >= o) x += y;
        }
        if (lane == 31) warpsums[wid] = x;
        __syncthreads();
        if (wid == 0) {
            int w = warpsums[lane];
            #pragma unroll
            for (int o = 1; o < 32; o <<= 1) {
                int y = __shfl_up_sync(0xffffffffu, w, o);
                if (lane >= o) w += y;
            }
            warpsums[lane] = w;
        }
        __syncthreads();
        int prev = (wid > 0) ? warpsums[wid - 1] : 0;
        if (idx < NN) {
            int incl = carry + prev + x;
            d_off[idx + 1] = incl;
            d_cur[idx] = incl - v;     // exclusive = start offset
        }
        int total = warpsums[31];
        __syncthreads();
        carry += total;
    }
}

__global__ void k_csr_scatter(const int* __restrict__ ei) {
    int i = blockIdx.x * blockDim.x + threadIdx.x;
    if (i < NE / 8) {
        int4 sa = reinterpret_cast<const int4*>(ei)[2 * i];
        int4 sb = reinterpret_cast<const int4*>(ei)[2 * i + 1];
        int4 da = reinterpret_cast<const int4*>(ei + NE)[2 * i];
        int4 db = reinterpret_cast<const int4*>(ei + NE)[2 * i + 1];
        d_csrc[atomicAdd(&d_cur[da.x], 1)] = sa.x;
        d_csrc[atomicAdd(&d_cur[da.y], 1)] = sa.y;
        d_csrc[atomicAdd(&d_cur[da.z], 1)] = sa.z;
        d_csrc[atomicAdd(&d_cur[da.w], 1)] = sa.w;
        d_csrc[atomicAdd(&d_cur[db.x], 1)] = sb.x;
        d_csrc[atomicAdd(&d_cur[db.y], 1)] = sb.y;
        d_csrc[atomicAdd(&d_cur[db.z], 1)] = sb.z;
        d_csrc[atomicAdd(&d_cur[db.w], 1)] = sb.w;
    }
}

// ---------------- GCN GEMM: 128x128 tile, 8x8 microkernel; epilogue scales by dinv ----------------
__global__ __launch_bounds__(256) void k_gemm128(const float* __restrict__ A,
                                                 const float* __restrict__ W) {
    __shared__ float sA[16][132];   // [k][row], padded (132*4 = 16B multiple)
    __shared__ float sW[16][128];   // [k][col]
    int tid = threadIdx.x;
    int tx = tid & 15;              // cols tx*8
    int ty = tid >> 4;              // rows ty*8
    int r0 = blockIdx.x * 128;

    float4 accA[8], accB[8];        // 8 rows x (4+4 cols)
    #pragma unroll
    for (int r = 0; r < 8; r++) {
        accA[r] = make_float4(0.f, 0.f, 0.f, 0.f);
        accB[r] = make_float4(0.f, 0.f, 0.f, 0.f);
    }

    int lrow = tid >> 1;            // 0..127
    int lks  = (tid & 1) * 8;       // 0 or 8
    int wk   = tid >> 4;            // 0..15
    int wc   = (tid & 15) * 8;

    for (int kc = 0; kc < 128; kc += 16) {
        int grow = r0 + lrow;
        float4 v0 = make_float4(0.f, 0.f, 0.f, 0.f);
        float4 v1 = make_float4(0.f, 0.f, 0.f, 0.f);
        if (grow < NN) {
            v0 = *reinterpret_cast<const float4*>(&A[grow * AD + kc + lks]);
            v1 = *reinterpret_cast<const float4*>(&A[grow * AD + kc + lks + 4]);
        }
        sA[lks + 0][lrow] = v0.x; sA[lks + 1][lrow] = v0.y;
        sA[lks + 2][lrow] = v0.z; sA[lks + 3][lrow] = v0.w;
        sA[lks + 4][lrow] = v1.x; sA[lks + 5][lrow] = v1.y;
        sA[lks + 6][lrow] = v1.z; sA[lks + 7][lrow] = v1.w;
        *reinterpret_cast<float4*>(&sW[wk][wc]) =
            *reinterpret_cast<const float4*>(&W[(kc + wk) * AD + wc]);
        *reinterpret_cast<float4*>(&sW[wk][wc + 4]) =
            *reinterpret_cast<const float4*>(&W[(kc + wk) * AD + wc + 4]);
        __syncthreads();

        #pragma unroll
        for (int k = 0; k < 16; k++) {
            float4 a0 = *reinterpret_cast<const float4*>(&sA[k][ty * 8]);
            float4 a1 = *reinterpret_cast<const float4*>(&sA[k][ty * 8 + 4]);
            float4 w0 = *reinterpret_cast<const float4*>(&sW[k][tx * 8]);
            float4 w1 = *reinterpret_cast<const float4*>(&sW[k][tx * 8 + 4]);
            float ar[8] = {a0.x, a0.y, a0.z, a0.w, a1.x, a1.y, a1.z, a1.w};
            #pragma unroll
            for (int r = 0; r < 8; r++) {
                accA[r].x += ar[r] * w0.x; accA[r].y += ar[r] * w0.y;
                accA[r].z += ar[r] * w0.z; accA[r].w += ar[r] * w0.w;
                accB[r].x += ar[r] * w1.x; accB[r].y += ar[r] * w1.y;
                accB[r].z += ar[r] * w1.z; accB[r].w += ar[r] * w1.w;
            }
        }
        __syncthreads();
    }
    #pragma unroll
    for (int r = 0; r < 8; r++) {
        int row = r0 + ty * 8 + r;
        if (row < NN) {
            float sc = d_dinv[row];
            float4 va = accA[r], vb = accB[r];
            va.x *= sc; va.y *= sc; va.z *= sc; va.w *= sc;
            vb.x *= sc; vb.y *= sc; vb.z *= sc; vb.w *= sc;
            *reinterpret_cast<float4*>(&d_h2[row * AD + tx * 8]) = va;
            *reinterpret_cast<float4*>(&d_h2[row * AD + tx * 8 + 4]) = vb;
        }
    }
}

// warp per node: acc = dinv[n] * (h2s[n] + sum h2s[src]) + b  (h2s already src-scaled)
__global__ void k_gcn_gather(const float* __restrict__ bias, float* __restrict__ out,
                             int apply_gelu) {
    int gid = blockIdx.x * blockDim.x + threadIdx.x;
    int n = gid >> 5;
    if (n >= NN) return;
    int lane = gid & 31;
    int beg = d_off[n], end = d_off[n + 1];
    float din = d_dinv[n];

    float4 acc = *reinterpret_cast<const float4*>(&d_h2[n * AD + lane * 4]);
    float4 acc2 = make_float4(0.f, 0.f, 0.f, 0.f);

    int e = beg;
    for (; e + 4 <= end; e += 4) {
        int s0 = d_csrc[e + 0];
        int s1 = d_csrc[e + 1];
        int s2 = d_csrc[e + 2];
        int s3 = d_csrc[e + 3];
        float4 v0 = *reinterpret_cast<const float4*>(&d_h2[s0 * AD + lane * 4]);
        float4 v1 = *reinterpret_cast<const float4*>(&d_h2[s1 * AD + lane * 4]);
        float4 v2 = *reinterpret_cast<const float4*>(&d_h2[s2 * AD + lane * 4]);
        float4 v3 = *reinterpret_cast<const float4*>(&d_h2[s3 * AD + lane * 4]);
        acc.x += v0.x; acc.y += v0.y; acc.z += v0.z; acc.w += v0.w;
        acc2.x += v1.x; acc2.y += v1.y; acc2.z += v1.z; acc2.w += v1.w;
        acc.x += v2.x; acc.y += v2.y; acc.z += v2.z; acc.w += v2.w;
        acc2.x += v3.x; acc2.y += v3.y; acc2.z += v3.z; acc2.w += v3.w;
    }
    for (; e < end; e++) {
        int s0 = d_csrc[e];
        float4 v0 = *reinterpret_cast<const float4*>(&d_h2[s0 * AD + lane * 4]);
        acc.x += v0.x; acc.y += v0.y; acc.z += v0.z; acc.w += v0.w;
    }
    acc.x += acc2.x; acc.y += acc2.y; acc.z += acc2.z; acc.w += acc2.w;

    float4 b = *reinterpret_cast<const float4*>(&bias[lane * 4]);
    acc.x = acc.x * din + b.x; acc.y = acc.y * din + b.y;
    acc.z = acc.z * din + b.z; acc.w = acc.w * din + b.w;
    if (apply_gelu) {
        acc.x = gelu_exact(acc.x); acc.y = gelu_exact(acc.y);
        acc.z = gelu_exact(acc.z); acc.w = gelu_exact(acc.w);
    }
    *reinterpret_cast<float4*>(&out[n * AD + lane * 4]) = acc;
}

// ---------------- GNA fused dual GEMM: 128x64 tile, 8x(4+4) microkernel ----------------
__global__ __launch_bounds__(256) void k_gna_gemm(const float* __restrict__ A,
                                                  const float* __restrict__ W2,
                                                  const float* __restrict__ b2,
                                                  const float* __restrict__ W1,
                                                  const float* __restrict__ b1,
                                                  const float* __restrict__ avec) {
    __shared__ float sA[16][132];
    __shared__ float sW2[16][64];
    __shared__ float sW1[16][64];
    int tid = threadIdx.x;
    int tx = tid & 15;              // cols tx*4
    int ty = tid >> 4;              // rows ty*8
    int r0 = blockIdx.x * 128;

    float4 at[8], au[8];
    #pragma unroll
    for (int r = 0; r < 8; r++) {
        at[r] = make_float4(0.f, 0.f, 0.f, 0.f);
        au[r] = make_float4(0.f, 0.f, 0.f, 0.f);
    }

    int lrow = tid >> 1;
    int lks  = (tid & 1) * 8;
    int wk   = tid >> 4;
    int wc   = (tid & 15) * 4;

    for (int kc = 0; kc < 64; kc += 16) {
        int grow = r0 + lrow;
        float4 v0 = make_float4(0.f, 0.f, 0.f, 0.f);
        float4 v1 = make_float4(0.f, 0.f, 0.f, 0.f);
        if (grow < NN) {
            v0 = *reinterpret_cast<const float4*>(&A[grow * SD + kc + lks]);
            v1 = *reinterpret_cast<const float4*>(&A[grow * SD + kc + lks + 4]);
        }
        sA[lks + 0][lrow] = v0.x; sA[lks + 1][lrow] = v0.y;
        sA[lks + 2][lrow] = v0.z; sA[lks + 3][lrow] = v0.w;
        sA[lks + 4][lrow] = v1.x; sA[lks + 5][lrow] = v1.y;
        sA[lks + 6][lrow] = v1.z; sA[lks + 7][lrow] = v1.w;
        *reinterpret_cast<float4*>(&sW2[wk][wc]) =
            *reinterpret_cast<const float4*>(&W2[(kc + wk) * SD + wc]);
        *reinterpret_cast<float4*>(&sW1[wk][wc]) =
            *reinterpret_cast<const float4*>(&W1[(kc + wk) * SD + wc]);
        __syncthreads();

        #pragma unroll
        for (int k = 0; k < 16; k++) {
            float4 a0 = *reinterpret_cast<const float4*>(&sA[k][ty * 8]);
            float4 a1 = *reinterpret_cast<const float4*>(&sA[k][ty * 8 + 4]);
            float4 w2v = *reinterpret_cast<const float4*>(&sW2[k][tx * 4]);
            float4 w1v = *reinterpret_cast<const float4*>(&sW1[k][tx * 4]);
            float ar[8] = {a0.x, a0.y, a0.z, a0.w, a1.x, a1.y, a1.z, a1.w};
            #pragma unroll
            for (int r = 0; r < 8; r++) {
                at[r].x += ar[r] * w2v.x; at[r].y += ar[r] * w2v.y;
                at[r].z += ar[r] * w2v.z; at[r].w += ar[r] * w2v.w;
                au[r].x += ar[r] * w1v.x; au[r].y += ar[r] * w1v.y;
                au[r].z += ar[r] * w1v.z; au[r].w += ar[r] * w1v.w;
            }
        }
        __syncthreads();
    }

    float4 bb2 = *reinterpret_cast<const float4*>(&b2[tx * 4]);
    float4 bb1 = *reinterpret_cast<const float4*>(&b1[tx * 4]);
    float4 av4 = *reinterpret_cast<const float4*>(&avec[tx * 4]);
    #pragma unroll
    for (int r = 0; r < 8; r++) {
        int row = r0 + ty * 8 + r;
        if (row >= NN) continue;
        float4 tv = at[r];
        tv.x += bb2.x; tv.y += bb2.y; tv.z += bb2.z; tv.w += bb2.w;
        *reinterpret_cast<float4*>(&d_t[row * SD + tx * 4]) = tv;
        float p = tv.x * av4.x + tv.y * av4.y + tv.z * av4.z + tv.w * av4.w;
        #pragma unroll
        for (int o = 1; o < 16; o <<= 1) p += __shfl_xor_sync(0xffffffffu, p, o);
        if (tx == 0) d_proj[row] = p;

        float4 uv = au[r];
        uv.x += bb1.x; uv.y += bb1.y; uv.z += bb1.z; uv.w += bb1.w;
        *reinterpret_cast<float4*>(&d_u[row * SD + tx * 4]) = uv;
    }
}

// warp per node: edge-softmax attention + epilogue out = gelu(u + msg/den)
__global__ void k_gna_attn(float* __restrict__ out) {
    int gid = blockIdx.x * blockDim.x + threadIdx.x;
    int n = gid >> 5;
    if (n >= NN) return;
    int lane = gid & 31;
    int beg = d_off[n], end = d_off[n + 1];
    float projd = d_proj[n];

    // pass 1: amax (self loop alpha = 0)
    float amax = 0.f;
    for (int c = beg; c < end; c += 32) {
        int i = c + lane;
        if (i < end) {
            float a = projd - d_proj[d_csrc[i]];
            amax = fmaxf(amax, a);
        }
    }
    #pragma unroll
    for (int o = 16; o > 0; o >>= 1)
        amax = fmaxf(amax, __shfl_xor_sync(0xffffffffu, amax, o));

    // pass 2: exp-weighted accumulation (self term first), 4-way unrolled broadcast
    float es = expf(-amax);
    float2 tn = *reinterpret_cast<const float2*>(&d_t[n * SD + lane * 2]);
    float mx = es * tn.x, my = es * tn.y;
    float den = es;

    for (int c = beg; c < end; c += 32) {
        int i = c + lane;
        int cnt = min(32, end - c);
        int srcl = (i < end) ? d_csrc[i] : 0;
        float al = (i < end) ? (projd - d_proj[srcl]) : 0.f;
        float ewl = expf(al - amax);
        int j = 0;
        for (; j + 4 <= cnt; j += 4) {
            float e0 = __shfl_sync(0xffffffffu, ewl, j + 0);
            float e1 = __shfl_sync(0xffffffffu, ewl, j + 1);
            float e2 = __shfl_sync(0xffffffffu, ewl, j + 2);
            float e3 = __shfl_sync(0xffffffffu, ewl, j + 3);
            int s0 = __shfl_sync(0xffffffffu, srcl, j + 0);
            int s1 = __shfl_sync(0xffffffffu, srcl, j + 1);
            int s2 = __shfl_sync(0xffffffffu, srcl, j + 2);
            int s3 = __shfl_sync(0xffffffffu, srcl, j + 3);
            float2 t0 = *reinterpret_cast<const float2*>(&d_t[s0 * SD + lane * 2]);
            float2 t1 = *reinterpret_cast<const float2*>(&d_t[s1 * SD + lane * 2]);
            float2 t2 = *reinterpret_cast<const float2*>(&d_t[s2 * SD + lane * 2]);
            float2 t3 = *reinterpret_cast<const float2*>(&d_t[s3 * SD + lane * 2]);
            mx += e0 * t0.x; my += e0 * t0.y;
            mx += e1 * t1.x; my += e1 * t1.y;
            mx += e2 * t2.x; my += e2 * t2.y;
            mx += e3 * t3.x; my += e3 * t3.y;
            den += e0 + e1 + e2 + e3;
        }
        for (; j < cnt; j++) {
            float ew = __shfl_sync(0xffffffffu, ewl, j);
            int sj = __shfl_sync(0xffffffffu, srcl, j);
            float2 tv = *reinterpret_cast<const float2*>(&d_t[sj * SD + lane * 2]);
            mx += ew * tv.x; my += ew * tv.y;
            den += ew;
        }
    }
    float inv = 1.f / (den + 1e-16f);
    float2 uv = *reinterpret_cast<const float2*>(&d_u[n * SD + lane * 2]);
    float2 res;
    res.x = gelu_exact(uv.x + mx * inv);
    res.y = gelu_exact(uv.y + my * inv);
    *reinterpret_cast<float2*>(&out[n * SD + lane * 2]) = res;
}

// ---------------- host launcher ----------------
extern "C" void kernel_launch(void* const* d_in, const int* in_sizes, int n_in,
                              void* d_out, int out_size) {
    const float* x     = (const float*)d_in[0];
    const float* s     = (const float*)d_in[1];
    const int*   ei    = (const int*)d_in[2];
    const float* gcnW  = (const float*)d_in[3];
    const float* gcnb  = (const float*)d_in[4];
    const float* w1W   = (const float*)d_in[5];
    const float* w1b   = (const float*)d_in[6];
    const float* w2W   = (const float*)d_in[7];
    const float* w2b   = (const float*)d_in[8];
    const float* ga    = (const float*)d_in[9];
    float* out = (float*)d_out;

    void* p;
    cudaGetSymbolAddress(&p, d_deg);  int*   degp = (int*)p;
    cudaGetSymbolAddress(&p, d_hbuf); float* hbufp = (float*)p;
    cudaGetSymbolAddress(&p, d_gbuf); float* gbufp = (float*)p;

    // ---- CSR build (cur seeded inside scan; launch #5 is now gemm128) ----
    cudaMemsetAsync(degp, 0, NN * sizeof(int));
    k_deg_count<<<(NE / 4 + 255) / 256, 256>>>(ei);
    k_dinv<<<(NN + 255) / 256, 256>>>();
    k_scan<<<1, 1024>>>();
    k_csr_scatter<<<(NE / 8 + 255) / 256, 256>>>(ei);

    const int GB = (NN + 127) / 128;
    const int WB = (NN * 32 + 255) / 256;

    // ---- GCN stack ----
    const float* hin = x;
    for (int i = 0; i < NL; i++) {
        k_gemm128<<<GB, 256>>>(hin, gcnW + i * AD * AD);
        float* hout = (i == NL - 1) ? out : hbufp;
        k_gcn_gather<<<WB, 256>>>(gcnb + i * AD, hout, (i < NL - 1) ? 1 : 0);
        hin = hbufp;
    }

    // ---- GNA stack ----
    const float* gin = s;
    for (int i = 0; i < NL; i++) {
        k_gna_gemm<<<GB, 256>>>(gin, w2W + i * SD * SD, w2b + i * SD,
                                w1W + i * SD * SD, w1b + i * SD, ga + i * SD);
        float* gout = (i == NL - 1) ? (out + NN * AD) : gbufp;
        k_gna_attn<<<WB, 256>>>(gout);
        gin = gbufp;
    }
}

// round 6
// speedup vs baseline: 1.0737x; 1.0737x over previous
#include <cuda_runtime.h>
#include <math.h>

#define NN 50000
#define NE 800000
#define AD 128
#define SD 64
#define NL 4

#define GB 782          // ceil(NN/64) 64-row gemm tiles
#define WB 6250         // ceil(NN/8)  8 warps (nodes) per 256-thr block

// ---------------- scratch (static device globals; no allocation) ----------------
__device__ float d_h2[NN * AD];     // GCN post-GEMM features, pre-scaled by dinv[row]
__device__ float d_hbuf[NN * AD];   // GCN inter-layer buffer
__device__ float d_t[NN * SD];      // GNA w2 output
__device__ float d_u[NN * SD];      // GNA w1 output (pre-attention)
__device__ float d_gbuf[NN * SD];   // GNA inter-layer buffer
__device__ float d_proj[NN];        // t . a
__device__ float d_dinv[NN];
__device__ int   d_deg[NN];
__device__ int   d_off[NN + 1];     // CSR offsets (dst-grouped)
__device__ int   d_cur[NN];
__device__ int   d_csrc[NE];        // CSR src per position

__device__ __forceinline__ float gelu_exact(float x) {
    return 0.5f * x * (1.0f + erff(x * 0.7071067811865476f));
}

// ---------------- degree / CSR build ----------------
__global__ void k_deg_count(const int* __restrict__ ei) {
    int i = blockIdx.x * blockDim.x + threadIdx.x;
    if (i < NE / 4) {
        int4 d4 = reinterpret_cast<const int4*>(ei + NE)[i];
        atomicAdd(&d_deg[d4.x], 1);
        atomicAdd(&d_deg[d4.y], 1);
        atomicAdd(&d_deg[d4.z], 1);
        atomicAdd(&d_deg[d4.w], 1);
    }
}

// single-block exclusive scan; also seeds d_cur and computes d_dinv
__global__ void k_scan() {
    __shared__ int warpsums[32];
    int tid = threadIdx.x, lane = tid & 31, wid = tid >> 5;
    int carry = 0;
    if (tid == 0) d_off[0] = 0;
    for (int base = 0; base < NN; base += 1024) {
        int idx = base + tid;
        int v = (idx < NN) ? d_deg[idx] : 0;
        int x = v;
        #pragma unroll
        for (int o = 1; o < 32; o <<= 1) {
            int y = __shfl_up_sync(0xffffffffu, x, o);
            if (lane >= o) x += y;
        }
        if (lane == 31) warpsums[wid] = x;
        __syncthreads();
        if (wid == 0) {
            int w = warpsums[lane];
            #pragma unroll
            for (int o = 1; o < 32; o <<= 1) {
                int y = __shfl_up_sync(0xffffffffu, w, o);
                if (lane >= o) w += y;
            }
            warpsums[lane] = w;
        }
        __syncthreads();
        int prev = (wid > 0) ? warpsums[wid - 1] : 0;
        if (idx < NN) {
            int incl = carry + prev + x;
            d_off[idx + 1] = incl;
            d_cur[idx] = incl - v;
            d_dinv[idx] = rsqrtf((float)(v + 1));
        }
        int total = warpsums[31];
        __syncthreads();
        carry += total;
    }
}

__global__ void k_csr_scatter(const int* __restrict__ ei) {
    int i = blockIdx.x * blockDim.x + threadIdx.x;
    if (i < NE / 4) {
        int4 s4 = reinterpret_cast<const int4*>(ei)[i];
        int4 d4 = reinterpret_cast<const int4*>(ei + NE)[i];
        d_csrc[atomicAdd(&d_cur[d4.x], 1)] = s4.x;
        d_csrc[atomicAdd(&d_cur[d4.y], 1)] = s4.y;
        d_csrc[atomicAdd(&d_cur[d4.z], 1)] = s4.z;
        d_csrc[atomicAdd(&d_cur[d4.w], 1)] = s4.w;
    }
}

// ================= megakernel A: GCN gemm (blocks [0,GB)) + GNA dual gemm (blocks [GB,2GB)) =================
__global__ __launch_bounds__(256) void k_mega_gemm(
    const float* __restrict__ hA, const float* __restrict__ W,      // GCN
    const float* __restrict__ gA, const float* __restrict__ W2,     // GNA
    const float* __restrict__ b2, const float* __restrict__ W1,
    const float* __restrict__ b1, const float* __restrict__ avec) {
    __shared__ float smem[3136];
    int tid = threadIdx.x;

    if (blockIdx.x < GB) {
        // ---- GCN GEMM: 64x128 tile, 8x4 microkernel; epilogue scales by dinv ----
        float (*sA)[68]  = reinterpret_cast<float(*)[68]>(smem);            // 16x68
        float (*sW)[128] = reinterpret_cast<float(*)[128]>(smem + 1088);    // 16x128
        int tx = tid & 31;             // cols tx*4
        int ty = tid >> 5;             // rows ty*8
        int r0 = blockIdx.x * 64;

        float4 acc[8];
        #pragma unroll
        for (int r = 0; r < 8; r++) acc[r] = make_float4(0.f, 0.f, 0.f, 0.f);

        int lrow = tid >> 2, lkq = tid & 3;
        int wkk = tid >> 4, wc = (tid & 15) * 8;

        for (int kc = 0; kc < 128; kc += 16) {
            int grow = r0 + lrow;
            float4 av = make_float4(0.f, 0.f, 0.f, 0.f);
            if (grow < NN) av = *reinterpret_cast<const float4*>(&hA[grow * AD + kc + lkq * 4]);
            sA[lkq * 4 + 0][lrow] = av.x;
            sA[lkq * 4 + 1][lrow] = av.y;
            sA[lkq * 4 + 2][lrow] = av.z;
            sA[lkq * 4 + 3][lrow] = av.w;
            *reinterpret_cast<float4*>(&sW[wkk][wc]) =
                *reinterpret_cast<const float4*>(&W[(kc + wkk) * AD + wc]);
            *reinterpret_cast<float4*>(&sW[wkk][wc + 4]) =
                *reinterpret_cast<const float4*>(&W[(kc + wkk) * AD + wc + 4]);
            __syncthreads();

            #pragma unroll
            for (int k2 = 0; k2 < 16; k2++) {
                float4 a0 = *reinterpret_cast<const float4*>(&sA[k2][ty * 8]);
                float4 a1 = *reinterpret_cast<const float4*>(&sA[k2][ty * 8 + 4]);
                float4 wv = *reinterpret_cast<const float4*>(&sW[k2][tx * 4]);
                acc[0].x += a0.x * wv.x; acc[0].y += a0.x * wv.y; acc[0].z += a0.x * wv.z; acc[0].w += a0.x * wv.w;
                acc[1].x += a0.y * wv.x; acc[1].y += a0.y * wv.y; acc[1].z += a0.y * wv.z; acc[1].w += a0.y * wv.w;
                acc[2].x += a0.z * wv.x; acc[2].y += a0.z * wv.y; acc[2].z += a0.z * wv.z; acc[2].w += a0.z * wv.w;
                acc[3].x += a0.w * wv.x; acc[3].y += a0.w * wv.y; acc[3].z += a0.w * wv.z; acc[3].w += a0.w * wv.w;
                acc[4].x += a1.x * wv.x; acc[4].y += a1.x * wv.y; acc[4].z += a1.x * wv.z; acc[4].w += a1.x * wv.w;
                acc[5].x += a1.y * wv.x; acc[5].y += a1.y * wv.y; acc[5].z += a1.y * wv.z; acc[5].w += a1.y * wv.w;
                acc[6].x += a1.z * wv.x; acc[6].y += a1.z * wv.y; acc[6].z += a1.z * wv.z; acc[6].w += a1.z * wv.w;
                acc[7].x += a1.w * wv.x; acc[7].y += a1.w * wv.y; acc[7].z += a1.w * wv.z; acc[7].w += a1.w * wv.w;
            }
            __syncthreads();
        }
        #pragma unroll
        for (int r = 0; r < 8; r++) {
            int row = r0 + ty * 8 + r;
            if (row < NN) {
                float sc = d_dinv[row];
                float4 v = acc[r];
                v.x *= sc; v.y *= sc; v.z *= sc; v.w *= sc;
                *reinterpret_cast<float4*>(&d_h2[row * AD + tx * 4]) = v;
            }
        }
    } else {
        // ---- GNA dual GEMM: 64x64 tile, 4x(4+4) microkernel; epilogue computes proj ----
        float (*sA)[68]  = reinterpret_cast<float(*)[68]>(smem);            // 16x68
        float (*sW2)[64] = reinterpret_cast<float(*)[64]>(smem + 1088);     // 16x64
        float (*sW1)[64] = reinterpret_cast<float(*)[64]>(smem + 2112);     // 16x64
        int tx = tid & 15;             // cols tx*4
        int ty = tid >> 4;             // rows ty*4
        int r0 = (blockIdx.x - GB) * 64;

        float4 at[4], au[4];
        #pragma unroll
        for (int r = 0; r < 4; r++) {
            at[r] = make_float4(0.f, 0.f, 0.f, 0.f);
            au[r] = make_float4(0.f, 0.f, 0.f, 0.f);
        }

        int lrow = tid >> 2, lkq = tid & 3;
        int wkk = tid >> 4, wc = (tid & 15) * 4;

        for (int kc = 0; kc < 64; kc += 16) {
            int grow = r0 + lrow;
            float4 av = make_float4(0.f, 0.f, 0.f, 0.f);
            if (grow < NN) av = *reinterpret_cast<const float4*>(&gA[grow * SD + kc + lkq * 4]);
            sA[lkq * 4 + 0][lrow] = av.x;
            sA[lkq * 4 + 1][lrow] = av.y;
            sA[lkq * 4 + 2][lrow] = av.z;
            sA[lkq * 4 + 3][lrow] = av.w;
            *reinterpret_cast<float4*>(&sW2[wkk][wc]) =
                *reinterpret_cast<const float4*>(&W2[(kc + wkk) * SD + wc]);
            *reinterpret_cast<float4*>(&sW1[wkk][wc]) =
                *reinterpret_cast<const float4*>(&W1[(kc + wkk) * SD + wc]);
            __syncthreads();

            #pragma unroll
            for (int k2 = 0; k2 < 16; k2++) {
                float4 a0 = *reinterpret_cast<const float4*>(&sA[k2][ty * 4]);
                float4 w2v = *reinterpret_cast<const float4*>(&sW2[k2][tx * 4]);
                float4 w1v = *reinterpret_cast<const float4*>(&sW1[k2][tx * 4]);
                at[0].x += a0.x * w2v.x; at[0].y += a0.x * w2v.y; at[0].z += a0.x * w2v.z; at[0].w += a0.x * w2v.w;
                at[1].x += a0.y * w2v.x; at[1].y += a0.y * w2v.y; at[1].z += a0.y * w2v.z; at[1].w += a0.y * w2v.w;
                at[2].x += a0.z * w2v.x; at[2].y += a0.z * w2v.y; at[2].z += a0.z * w2v.z; at[2].w += a0.z * w2v.w;
                at[3].x += a0.w * w2v.x; at[3].y += a0.w * w2v.y; at[3].z += a0.w * w2v.z; at[3].w += a0.w * w2v.w;
                au[0].x += a0.x * w1v.x; au[0].y += a0.x * w1v.y; au[0].z += a0.x * w1v.z; au[0].w += a0.x * w1v.w;
                au[1].x += a0.y * w1v.x; au[1].y += a0.y * w1v.y; au[1].z += a0.y * w1v.z; au[1].w += a0.y * w1v.w;
                au[2].x += a0.z * w1v.x; au[2].y += a0.z * w1v.y; au[2].z += a0.z * w1v.z; au[2].w += a0.z * w1v.w;
                au[3].x += a0.w * w1v.x; au[3].y += a0.w * w1v.y; au[3].z += a0.w * w1v.z; au[3].w += a0.w * w1v.w;
            }
            __syncthreads();
        }

        float4 bb2 = *reinterpret_cast<const float4*>(&b2[tx * 4]);
        float4 bb1 = *reinterpret_cast<const float4*>(&b1[tx * 4]);
        float4 av4 = *reinterpret_cast<const float4*>(&avec[tx * 4]);
        #pragma unroll
        for (int r = 0; r < 4; r++) {
            int row = r0 + ty * 4 + r;
            if (row >= NN) continue;
            float4 tv = at[r];
            tv.x += bb2.x; tv.y += bb2.y; tv.z += bb2.z; tv.w += bb2.w;
            *reinterpret_cast<float4*>(&d_t[row * SD + tx * 4]) = tv;
            float p = tv.x * av4.x + tv.y * av4.y + tv.z * av4.z + tv.w * av4.w;
            #pragma unroll
            for (int o = 1; o < 16; o <<= 1) p += __shfl_xor_sync(0xffffffffu, p, o);
            if (tx == 0) d_proj[row] = p;

            float4 uv = au[r];
            uv.x += bb1.x; uv.y += bb1.y; uv.z += bb1.z; uv.w += bb1.w;
            *reinterpret_cast<float4*>(&d_u[row * SD + tx * 4]) = uv;
        }
    }
}

// ================= megakernel B: GCN gather (blocks [0,WB)) + GNA attn (blocks [WB,2WB)) =================
__global__ void k_mega_edge(const float* __restrict__ bias, float* __restrict__ hout,
                            int apply_gelu, float* __restrict__ gout) {
    int tid = threadIdx.x;
    int lane = tid & 31;

    if (blockIdx.x < WB) {
        // ---- GCN gather: warp per node ----
        int n = blockIdx.x * 8 + (tid >> 5);
        if (n >= NN) return;
        int beg = d_off[n], end = d_off[n + 1];
        float din = d_dinv[n];

        float4 acc = *reinterpret_cast<const float4*>(&d_h2[n * AD + lane * 4]);
        float4 acc2 = make_float4(0.f, 0.f, 0.f, 0.f);

        int e = beg;
        for (; e + 4 <= end; e += 4) {
            int s0 = d_csrc[e + 0];
            int s1 = d_csrc[e + 1];
            int s2 = d_csrc[e + 2];
            int s3 = d_csrc[e + 3];
            float4 v0 = *reinterpret_cast<const float4*>(&d_h2[s0 * AD + lane * 4]);
            float4 v1 = *reinterpret_cast<const float4*>(&d_h2[s1 * AD + lane * 4]);
            float4 v2 = *reinterpret_cast<const float4*>(&d_h2[s2 * AD + lane * 4]);
            float4 v3 = *reinterpret_cast<const float4*>(&d_h2[s3 * AD + lane * 4]);
            acc.x += v0.x; acc.y += v0.y; acc.z += v0.z; acc.w += v0.w;
            acc2.x += v1.x; acc2.y += v1.y; acc2.z += v1.z; acc2.w += v1.w;
            acc.x += v2.x; acc.y += v2.y; acc.z += v2.z; acc.w += v2.w;
            acc2.x += v3.x; acc2.y += v3.y; acc2.z += v3.z; acc2.w += v3.w;
        }
        for (; e < end; e++) {
            int s0 = d_csrc[e];
            float4 v0 = *reinterpret_cast<const float4*>(&d_h2[s0 * AD + lane * 4]);
            acc.x += v0.x; acc.y += v0.y; acc.z += v0.z; acc.w += v0.w;
        }
        acc.x += acc2.x; acc.y += acc2.y; acc.z += acc2.z; acc.w += acc2.w;

        float4 b = *reinterpret_cast<const float4*>(&bias[lane * 4]);
        acc.x = acc.x * din + b.x; acc.y = acc.y * din + b.y;
        acc.z = acc.z * din + b.z; acc.w = acc.w * din + b.w;
        if (apply_gelu) {
            acc.x = gelu_exact(acc.x); acc.y = gelu_exact(acc.y);
            acc.z = gelu_exact(acc.z); acc.w = gelu_exact(acc.w);
        }
        *reinterpret_cast<float4*>(&hout[n * AD + lane * 4]) = acc;
    } else {
        // ---- GNA attention: warp per node ----
        int n = (blockIdx.x - WB) * 8 + (tid >> 5);
        if (n >= NN) return;
        int beg = d_off[n], end = d_off[n + 1];
        float projd = d_proj[n];

        float amax = 0.f;
        for (int c = beg; c < end; c += 32) {
            int i = c + lane;
            if (i < end) {
                float a = projd - d_proj[d_csrc[i]];
                amax = fmaxf(amax, a);
            }
        }
        #pragma unroll
        for (int o = 16; o > 0; o >>= 1)
            amax = fmaxf(amax, __shfl_xor_sync(0xffffffffu, amax, o));

        float es = expf(-amax);
        float2 tn = *reinterpret_cast<const float2*>(&d_t[n * SD + lane * 2]);
        float mx = es * tn.x, my = es * tn.y;
        float den = es;

        for (int c = beg; c < end; c += 32) {
            int i = c + lane;
            int cnt = min(32, end - c);
            int srcl = (i < end) ? d_csrc[i] : 0;
            float al = (i < end) ? (projd - d_proj[srcl]) : 0.f;
            float ewl = expf(al - amax);
            int j = 0;
            for (; j + 4 <= cnt; j += 4) {
                float e0 = __shfl_sync(0xffffffffu, ewl, j + 0);
                float e1 = __shfl_sync(0xffffffffu, ewl, j + 1);
                float e2 = __shfl_sync(0xffffffffu, ewl, j + 2);
                float e3 = __shfl_sync(0xffffffffu, ewl, j + 3);
                int s0 = __shfl_sync(0xffffffffu, srcl, j + 0);
                int s1 = __shfl_sync(0xffffffffu, srcl, j + 1);
                int s2 = __shfl_sync(0xffffffffu, srcl, j + 2);
                int s3 = __shfl_sync(0xffffffffu, srcl, j + 3);
                float2 t0 = *reinterpret_cast<const float2*>(&d_t[s0 * SD + lane * 2]);
                float2 t1 = *reinterpret_cast<const float2*>(&d_t[s1 * SD + lane * 2]);
                float2 t2 = *reinterpret_cast<const float2*>(&d_t[s2 * SD + lane * 2]);
                float2 t3 = *reinterpret_cast<const float2*>(&d_t[s3 * SD + lane * 2]);
                mx += e0 * t0.x; my += e0 * t0.y;
                mx += e1 * t1.x; my += e1 * t1.y;
                mx += e2 * t2.x; my += e2 * t2.y;
                mx += e3 * t3.x; my += e3 * t3.y;
                den += e0 + e1 + e2 + e3;
            }
            for (; j < cnt; j++) {
                float ew = __shfl_sync(0xffffffffu, ewl, j);
                int sj = __shfl_sync(0xffffffffu, srcl, j);
                float2 tv = *reinterpret_cast<const float2*>(&d_t[sj * SD + lane * 2]);
                mx += ew * tv.x; my += ew * tv.y;
                den += ew;
            }
        }
        float inv = 1.f / (den + 1e-16f);
        float2 uv = *reinterpret_cast<const float2*>(&d_u[n * SD + lane * 2]);
        float2 res;
        res.x = gelu_exact(uv.x + mx * inv);
        res.y = gelu_exact(uv.y + my * inv);
        *reinterpret_cast<float2*>(&gout[n * SD + lane * 2]) = res;
    }
}

// ---------------- host launcher ----------------
extern "C" void kernel_launch(void* const* d_in, const int* in_sizes, int n_in,
                              void* d_out, int out_size) {
    const float* x     = (const float*)d_in[0];
    const float* s     = (const float*)d_in[1];
    const int*   ei    = (const int*)d_in[2];
    const float* gcnW  = (const float*)d_in[3];
    const float* gcnb  = (const float*)d_in[4];
    const float* w1W   = (const float*)d_in[5];
    const float* w1b   = (const float*)d_in[6];
    const float* w2W   = (const float*)d_in[7];
    const float* w2b   = (const float*)d_in[8];
    const float* ga    = (const float*)d_in[9];
    float* out = (float*)d_out;

    void* p;
    cudaGetSymbolAddress(&p, d_deg);  int*   degp = (int*)p;
    cudaGetSymbolAddress(&p, d_hbuf); float* hbufp = (float*)p;
    cudaGetSymbolAddress(&p, d_gbuf); float* gbufp = (float*)p;

    // ---- CSR build: launches 1-4 (memset, deg, scan, csr); #5 = first megakernel A ----
    cudaMemsetAsync(degp, 0, NN * sizeof(int));
    k_deg_count<<<(NE / 4 + 255) / 256, 256>>>(ei);
    k_scan<<<1, 1024>>>();
    k_csr_scatter<<<(NE / 4 + 255) / 256, 256>>>(ei);

    // ---- fused GCN+GNA layer pipeline ----
    const float* hin = x;
    const float* gin = s;
    for (int i = 0; i < NL; i++) {
        k_mega_gemm<<<2 * GB, 256>>>(hin, gcnW + i * AD * AD,
                                     gin, w2W + i * SD * SD, w2b + i * SD,
                                     w1W + i * SD * SD, w1b + i * SD, ga + i * SD);
        float* hout = (i == NL - 1) ? out : hbufp;
        float* gout = (i == NL - 1) ? (out + NN * AD) : gbufp;
        k_mega_edge<<<2 * WB, 256>>>(gcnb + i * AD, hout, (i < NL - 1) ? 1 : 0, gout);
        hin = hbufp;
        gin = gbufp;
    }
}

// round 8
// speedup vs baseline: 1.1731x; 1.0925x over previous
#include <cuda_runtime.h>
#include <cuda_bf16.h>
#include <math.h>
#include <stdint.h>

#define NN 50000
#define NE 800000
#define AD 128
#define SD 64
#define NL 4

#define WB 6250           // ceil(NN/8): warp-per-node blocks
#define MMB 391           // ceil(NN/128): 128-row MMA tiles

// ---------------- scratch (static device globals; no allocation) ----------------
__device__ float d_h2[NN * AD];                // GCN post-GEMM (dinv-scaled), fp32 for gather
__device__ float d_t[NN * SD];
__device__ float d_u[NN * SD];
__device__ float d_proj[NN];
__device__ float d_dinv[NN];
__device__ int   d_deg[NN];
__device__ int   d_off[NN + 1];
__device__ int   d_cur[NN];
__device__ int   d_csrc[NE];
// bf16 split planes (activations)
__device__ __nv_bfloat16 d_hbf_hi[NN * AD];
__device__ __nv_bfloat16 d_hbf_lo[NN * AD];
__device__ __nv_bfloat16 d_gbf_hi[NN * SD];
__device__ __nv_bfloat16 d_gbf_lo[NN * SD];
// bf16 split planes (weights, transposed K-major: Wt[col][k])
__device__ __nv_bfloat16 d_wthi[NL * AD * AD];
__device__ __nv_bfloat16 d_wtlo[NL * AD * AD];
__device__ __nv_bfloat16 d_w2thi[NL * SD * SD];
__device__ __nv_bfloat16 d_w2tlo[NL * SD * SD];
__device__ __nv_bfloat16 d_w1thi[NL * SD * SD];
__device__ __nv_bfloat16 d_w1tlo[NL * SD * SD];

__device__ __forceinline__ float gelu_exact(float x) {
    return 0.5f * x * (1.0f + erff(x * 0.7071067811865476f));
}
__device__ __forceinline__ uint32_t bfpack(float a, float b) {
    __nv_bfloat162 h = __floats2bfloat162_rn(a, b);
    return *reinterpret_cast<uint32_t*>(&h);
}
__device__ __forceinline__ float bflo(float a) {
    __nv_bfloat16 h = __float2bfloat16(a);
    return a - __bfloat162float(h);
}

// mma.sync m16n8k16 bf16 -> f32 (baseline PTX, sm_80+)
__device__ __forceinline__ void mma_bf16(float* c, const uint32_t* a, const uint32_t* b) {
    asm volatile(
        "mma.sync.aligned.m16n8k16.row.col.f32.bf16.bf16.f32 "
        "{%0,%1,%2,%3}, {%4,%5,%6,%7}, {%8,%9}, {%0,%1,%2,%3};"
        : "+f"(c[0]), "+f"(c[1]), "+f"(c[2]), "+f"(c[3])
        : "r"(a[0]), "r"(a[1]), "r"(a[2]), "r"(a[3]), "r"(b[0]), "r"(b[1]));
}

// ---------------- prep: convert x/s/W planes + degree count (grid-fused) ----------------
#define PB_X 3125
#define PB_S 1563
#define PB_D 782
#define PB_WG 32
#define PB_W2 8
#define PB_W1 8
#define PB_TOT (PB_X + PB_S + PB_D + PB_WG + PB_W2 + PB_W1)

__global__ void k_prep(const float* __restrict__ x, const float* __restrict__ s,
                       const int* __restrict__ ei, const float* __restrict__ gcnW,
                       const float* __restrict__ w2W, const float* __restrict__ w1W) {
    int b = blockIdx.x, tid = threadIdx.x;
    if (b < PB_X) {
        int i8 = (b * 256 + tid) * 8;
        float4 f0 = *reinterpret_cast<const float4*>(x + i8);
        float4 f1 = *reinterpret_cast<const float4*>(x + i8 + 4);
        uint4 hv = make_uint4(bfpack(f0.x, f0.y), bfpack(f0.z, f0.w),
                              bfpack(f1.x, f1.y), bfpack(f1.z, f1.w));
        uint4 lv = make_uint4(bfpack(bflo(f0.x), bflo(f0.y)), bfpack(bflo(f0.z), bflo(f0.w)),
                              bfpack(bflo(f1.x), bflo(f1.y)), bfpack(bflo(f1.z), bflo(f1.w)));
        reinterpret_cast<uint4*>(d_hbf_hi)[i8 >> 3] = hv;
        reinterpret_cast<uint4*>(d_hbf_lo)[i8 >> 3] = lv;
    } else if (b < PB_X + PB_S) {
        int i8 = ((b - PB_X) * 256 + tid) * 8;
        if (i8 < NN * SD) {
            float4 f0 = *reinterpret_cast<const float4*>(s + i8);
            float4 f1 = *reinterpret_cast<const float4*>(s + i8 + 4);
            uint4 hv = make_uint4(bfpack(f0.x, f0.y), bfpack(f0.z, f0.w),
                                  bfpack(f1.x, f1.y), bfpack(f1.z, f1.w));
            uint4 lv = make_uint4(bfpack(bflo(f0.x), bflo(f0.y)), bfpack(bflo(f0.z), bflo(f0.w)),
                                  bfpack(bflo(f1.x), bflo(f1.y)), bfpack(bflo(f1.z), bflo(f1.w)));
            reinterpret_cast<uint4*>(d_gbf_hi)[i8 >> 3] = hv;
            reinterpret_cast<uint4*>(d_gbf_lo)[i8 >> 3] = lv;
        }
    } else if (b < PB_X + PB_S + PB_D) {
        int i = (b - PB_X - PB_S) * 256 + tid;
        if (i < NE / 4) {
            int4 d4 = reinterpret_cast<const int4*>(ei + NE)[i];
            atomicAdd(&d_deg[d4.x], 1);
            atomicAdd(&d_deg[d4.y], 1);
            atomicAdd(&d_deg[d4.z], 1);
            atomicAdd(&d_deg[d4.w], 1);
        }
    } else if (b < PB_X + PB_S + PB_D + PB_WG) {
        int base = ((b - PB_X - PB_S - PB_D) * 256 + tid) * 8;
        #pragma unroll
        for (int j = 0; j < 8; j++) {
            int e = base + j;
            int l = e >> 14, r = e & 16383, k = r >> 7, c = r & 127;
            float v = gcnW[e];
            __nv_bfloat16 h = __float2bfloat16(v);
            d_wthi[(l << 14) + c * 128 + k] = h;
            d_wtlo[(l << 14) + c * 128 + k] = __float2bfloat16(v - __bfloat162float(h));
        }
    } else {
        int isW1 = (b >= PB_X + PB_S + PB_D + PB_WG + PB_W2);
        int bb = b - PB_X - PB_S - PB_D - PB_WG - (isW1 ? PB_W2 : 0);
        const float* Wsrc = isW1 ? w1W : w2W;
        __nv_bfloat16* Phi = isW1 ? d_w1thi : d_w2thi;
        __nv_bfloat16* Plo = isW1 ? d_w1tlo : d_w2tlo;
        int base = (bb * 256 + tid) * 8;
        #pragma unroll
        for (int j = 0; j < 8; j++) {
            int e = base + j;
            int l = e >> 12, r = e & 4095, k = r >> 6, c = r & 63;
            float v = Wsrc[e];
            __nv_bfloat16 h = __float2bfloat16(v);
            Phi[(l << 12) + c * 64 + k] = h;
            Plo[(l << 12) + c * 64 + k] = __float2bfloat16(v - __bfloat162float(h));
        }
    }
}

// ---------------- scan (also dinv, cur) ----------------
__global__ void k_scan() {
    __shared__ int warpsums[32];
    int tid = threadIdx.x, lane = tid & 31, wid = tid >> 5;
    int carry = 0;
    if (tid == 0) d_off[0] = 0;
    for (int base = 0; base < NN; base += 1024) {
        int idx = base + tid;
        int v = (idx < NN) ? d_deg[idx] : 0;
        int x = v;
        #pragma unroll
        for (int o = 1; o < 32; o <<= 1) {
            int y = __shfl_up_sync(0xffffffffu, x, o);
            if (lane >= o) x += y;
        }
        if (lane == 31) warpsums[wid] = x;
        __syncthreads();
        if (wid == 0) {
            int w = warpsums[lane];
            #pragma unroll
            for (int o = 1; o < 32; o <<= 1) {
                int y = __shfl_up_sync(0xffffffffu, w, o);
                if (lane >= o) w += y;
            }
            warpsums[lane] = w;
        }
        __syncthreads();
        int prev = (wid > 0) ? warpsums[wid - 1] : 0;
        if (idx < NN) {
            int incl = carry + prev + x;
            d_off[idx + 1] = incl;
            d_cur[idx] = incl - v;
            d_dinv[idx] = rsqrtf((float)(v + 1));
        }
        int total = warpsums[31];
        __syncthreads();
        carry += total;
    }
}

__global__ void k_csr_scatter(const int* __restrict__ ei) {
    int i = blockIdx.x * blockDim.x + threadIdx.x;
    if (i < NE / 4) {
        int4 s4 = reinterpret_cast<const int4*>(ei)[i];
        int4 d4 = reinterpret_cast<const int4*>(ei + NE)[i];
        d_csrc[atomicAdd(&d_cur[d4.x], 1)] = s4.x;
        d_csrc[atomicAdd(&d_cur[d4.y], 1)] = s4.y;
        d_csrc[atomicAdd(&d_cur[d4.z], 1)] = s4.z;
        d_csrc[atomicAdd(&d_cur[d4.w], 1)] = s4.w;
    }
}

// ================= fused MMA megakernel =================
// GCN blocks [0,MMB): 128x128xK128, smem pitch 272B; planes AH/AL/BH/BL 34816B each.
// GNA blocks [MMB,2MMB): 128x128xK64 with B = [W2t ; W1t], pitch 144B, planes 18432B.
#define GC_PITCH 272
#define GC_PLANE 34816
#define GN_PITCH 144
#define GN_PLANE 18432
#define MM_SMEM (4 * GC_PLANE)   // 139264

__global__ __launch_bounds__(256) void k_mma(
    const __nv_bfloat16* __restrict__ wthi, const __nv_bfloat16* __restrict__ wtlo,
    const __nv_bfloat16* __restrict__ w2thi, const __nv_bfloat16* __restrict__ w2tlo,
    const __nv_bfloat16* __restrict__ w1thi, const __nv_bfloat16* __restrict__ w1tlo,
    const float* __restrict__ b2, const float* __restrict__ b1,
    const float* __restrict__ avec) {
    extern __shared__ char sm[];
    int tid = threadIdx.x;
    int wid = tid >> 5, lane = tid & 31;
    int g = lane >> 2, tg = lane & 3;
    int wm = wid & 3, wn = wid >> 2;       // 4 m-warps x 2 n-warps

    if (blockIdx.x < MMB) {
        // ================== GCN GEMM ==================
        int r0 = blockIdx.x * 128;
        char* AH = sm;
        char* AL = sm + GC_PLANE;
        char* BH = sm + 2 * GC_PLANE;
        char* BL = sm + 3 * GC_PLANE;
        const uint4* AHg = reinterpret_cast<const uint4*>(d_hbf_hi);
        const uint4* ALg = reinterpret_cast<const uint4*>(d_hbf_lo);
        const uint4* BHg = reinterpret_cast<const uint4*>(wthi);
        const uint4* BLg = reinterpret_cast<const uint4*>(wtlo);
        #pragma unroll
        for (int it = 0; it < 8; it++) {
            int gg = it * 256 + tid;          // 0..2047
            int row = gg >> 4, c16 = gg & 15;
            int off = row * GC_PITCH + c16 * 16;
            int grow = r0 + row;
            uint4 vh = make_uint4(0, 0, 0, 0), vl = make_uint4(0, 0, 0, 0);
            if (grow < NN) {
                vh = AHg[grow * 16 + c16];
                vl = ALg[grow * 16 + c16];
            }
            *reinterpret_cast<uint4*>(AH + off) = vh;
            *reinterpret_cast<uint4*>(AL + off) = vl;
            *reinterpret_cast<uint4*>(BH + off) = BHg[gg];
            *reinterpret_cast<uint4*>(BL + off) = BLg[gg];
        }
        __syncthreads();

        float acc[2][8][4];
        #pragma unroll
        for (int a = 0; a < 2; a++)
            #pragma unroll
            for (int b = 0; b < 8; b++)
                #pragma unroll
                for (int c = 0; c < 4; c++) acc[a][b][c] = 0.f;

        #pragma unroll
        for (int t = 0; t < 3; t++) {
            const char* pA = (t == 2) ? AL : AH;
            const char* pB = (t == 1) ? BL : BH;
            #pragma unroll
            for (int k0 = 0; k0 < 8; k0++) {
                int kb = (k0 * 16 + tg * 2) * 2;   // byte col offset
                uint32_t afr[2][4];
                #pragma unroll
                for (int tm = 0; tm < 2; tm++) {
                    int r = wm * 32 + tm * 16 + g;
                    const char* base = pA + r * GC_PITCH + kb;
                    afr[tm][0] = *reinterpret_cast<const uint32_t*>(base);
                    afr[tm][1] = *reinterpret_cast<const uint32_t*>(base + 8 * GC_PITCH);
                    afr[tm][2] = *reinterpret_cast<const uint32_t*>(base + 16);
                    afr[tm][3] = *reinterpret_cast<const uint32_t*>(base + 8 * GC_PITCH + 16);
                }
                uint32_t bfr[8][2];
                #pragma unroll
                for (int tn = 0; tn < 8; tn++) {
                    int n = wn * 64 + tn * 8 + g;
                    const char* base = pB + n * GC_PITCH + kb;
                    bfr[tn][0] = *reinterpret_cast<const uint32_t*>(base);
                    bfr[tn][1] = *reinterpret_cast<const uint32_t*>(base + 16);
                }
                #pragma unroll
                for (int tm = 0; tm < 2; tm++)
                    #pragma unroll
                    for (int tn = 0; tn < 8; tn++)
                        mma_bf16(acc[tm][tn], afr[tm], bfr[tn]);
            }
        }
        // epilogue: scale by dinv[row], store fp32 h2
        #pragma unroll
        for (int tm = 0; tm < 2; tm++) {
            int r1 = r0 + wm * 32 + tm * 16 + g;
            int r2 = r1 + 8;
            float s1 = (r1 < NN) ? d_dinv[r1] : 0.f;
            float s2 = (r2 < NN) ? d_dinv[r2] : 0.f;
            #pragma unroll
            for (int tn = 0; tn < 8; tn++) {
                int c = wn * 64 + tn * 8 + tg * 2;
                if (r1 < NN)
                    *reinterpret_cast<float2*>(&d_h2[r1 * AD + c]) =
                        make_float2(acc[tm][tn][0] * s1, acc[tm][tn][1] * s1);
                if (r2 < NN)
                    *reinterpret_cast<float2*>(&d_h2[r2 * AD + c]) =
                        make_float2(acc[tm][tn][2] * s2, acc[tm][tn][3] * s2);
            }
        }
    } else {
        // ================== GNA GEMM: D = A @ [W2t;W1t]^T -> [t | u] ==================
        int r0 = (blockIdx.x - MMB) * 128;
        char* AH = sm;
        char* AL = sm + GN_PLANE;
        char* BH = sm + 2 * GN_PLANE;
        char* BL = sm + 3 * GN_PLANE;
        const uint4* AHg = reinterpret_cast<const uint4*>(d_gbf_hi);
        const uint4* ALg = reinterpret_cast<const uint4*>(d_gbf_lo);
        const uint4* B2H = reinterpret_cast<const uint4*>(w2thi);
        const uint4* B2L = reinterpret_cast<const uint4*>(w2tlo);
        const uint4* B1H = reinterpret_cast<const uint4*>(w1thi);
        const uint4* B1L = reinterpret_cast<const uint4*>(w1tlo);
        #pragma unroll
        for (int it = 0; it < 4; it++) {
            int gg = it * 256 + tid;          // 0..1023
            int row = gg >> 3, c8 = gg & 7;
            int off = row * GN_PITCH + c8 * 16;
            int grow = r0 + row;
            uint4 vh = make_uint4(0, 0, 0, 0), vl = make_uint4(0, 0, 0, 0);
            if (grow < NN) {
                vh = AHg[grow * 8 + c8];
                vl = ALg[grow * 8 + c8];
            }
            *reinterpret_cast<uint4*>(AH + off) = vh;
            *reinterpret_cast<uint4*>(AL + off) = vl;
            uint4 bh, bl;
            if (row < 64) {
                bh = B2H[row * 8 + c8];
                bl = B2L[row * 8 + c8];
            } else {
                bh = B1H[(row - 64) * 8 + c8];
                bl = B1L[(row - 64) * 8 + c8];
            }
            *reinterpret_cast<uint4*>(BH + off) = bh;
            *reinterpret_cast<uint4*>(BL + off) = bl;
        }
        __syncthreads();

        float acc[2][8][4];
        #pragma unroll
        for (int a = 0; a < 2; a++)
            #pragma unroll
            for (int b = 0; b < 8; b++)
                #pragma unroll
                for (int c = 0; c < 4; c++) acc[a][b][c] = 0.f;

        #pragma unroll
        for (int t = 0; t < 3; t++) {
            const char* pA = (t == 2) ? AL : AH;
            const char* pB = (t == 1) ? BL : BH;
            #pragma unroll
            for (int k0 = 0; k0 < 4; k0++) {
                int kb = (k0 * 16 + tg * 2) * 2;
                uint32_t afr[2][4];
                #pragma unroll
                for (int tm = 0; tm < 2; tm++) {
                    int r = wm * 32 + tm * 16 + g;
                    const char* base = pA + r * GN_PITCH + kb;
                    afr[tm][0] = *reinterpret_cast<const uint32_t*>(base);
                    afr[tm][1] = *reinterpret_cast<const uint32_t*>(base + 8 * GN_PITCH);
                    afr[tm][2] = *reinterpret_cast<const uint32_t*>(base + 16);
                    afr[tm][3] = *reinterpret_cast<const uint32_t*>(base + 8 * GN_PITCH + 16);
                }
                uint32_t bfr[8][2];
                #pragma unroll
                for (int tn = 0; tn < 8; tn++) {
                    int n = wn * 64 + tn * 8 + g;
                    const char* base = pB + n * GN_PITCH + kb;
                    bfr[tn][0] = *reinterpret_cast<const uint32_t*>(base);
                    bfr[tn][1] = *reinterpret_cast<const uint32_t*>(base + 16);
                }
                #pragma unroll
                for (int tm = 0; tm < 2; tm++)
                    #pragma unroll
                    for (int tn = 0; tn < 8; tn++)
                        mma_bf16(acc[tm][tn], afr[tm], bfr[tn]);
            }
        }
        // epilogue: wn==0 -> t (+b2, proj); wn==1 -> u (+b1)
        const float* bias = wn ? b1 : b2;
        #pragma unroll
        for (int tm = 0; tm < 2; tm++) {
            int r1 = r0 + wm * 32 + tm * 16 + g;
            int r2 = r1 + 8;
            float p1 = 0.f, p2 = 0.f;
            #pragma unroll
            for (int tn = 0; tn < 8; tn++) {
                int c = tn * 8 + tg * 2;         // local 0..63
                float2 bb = *reinterpret_cast<const float2*>(&bias[c]);
                float v0 = acc[tm][tn][0] + bb.x;
                float v1 = acc[tm][tn][1] + bb.y;
                float v2 = acc[tm][tn][2] + bb.x;
                float v3 = acc[tm][tn][3] + bb.y;
                if (wn == 0) {
                    float2 av = *reinterpret_cast<const float2*>(&avec[c]);
                    p1 += v0 * av.x + v1 * av.y;
                    p2 += v2 * av.x + v3 * av.y;
                    if (r1 < NN) *reinterpret_cast<float2*>(&d_t[r1 * SD + c]) = make_float2(v0, v1);
                    if (r2 < NN) *reinterpret_cast<float2*>(&d_t[r2 * SD + c]) = make_float2(v2, v3);
                } else {
                    if (r1 < NN) *reinterpret_cast<float2*>(&d_u[r1 * SD + c]) = make_float2(v0, v1);
                    if (r2 < NN) *reinterpret_cast<float2*>(&d_u[r2 * SD + c]) = make_float2(v2, v3);
                }
            }
            if (wn == 0) {
                p1 += __shfl_xor_sync(0xffffffffu, p1, 1);
                p1 += __shfl_xor_sync(0xffffffffu, p1, 2);
                p2 += __shfl_xor_sync(0xffffffffu, p2, 1);
                p2 += __shfl_xor_sync(0xffffffffu, p2, 2);
                if (tg == 0) {
                    if (r1 < NN) d_proj[r1] = p1;
                    if (r2 < NN) d_proj[r2] = p2;
                }
            }
        }
    }
}

// ================= megakernel B: GCN gather + GNA attn (warp per node) =================
__global__ void k_mega_edge(const float* __restrict__ bias, float* __restrict__ hout,
                            int fin, float* __restrict__ gout) {
    int tid = threadIdx.x;
    int lane = tid & 31;

    if (blockIdx.x < WB) {
        int n = blockIdx.x * 8 + (tid >> 5);
        if (n >= NN) return;
        int beg = d_off[n], end = d_off[n + 1];
        float din = d_dinv[n];

        float4 acc = *reinterpret_cast<const float4*>(&d_h2[n * AD + lane * 4]);
        float4 acc2 = make_float4(0.f, 0.f, 0.f, 0.f);
        int e = beg;
        for (; e + 4 <= end; e += 4) {
            int s0 = d_csrc[e + 0];
            int s1 = d_csrc[e + 1];
            int s2 = d_csrc[e + 2];
            int s3 = d_csrc[e + 3];
            float4 v0 = *reinterpret_cast<const float4*>(&d_h2[s0 * AD + lane * 4]);
            float4 v1 = *reinterpret_cast<const float4*>(&d_h2[s1 * AD + lane * 4]);
            float4 v2 = *reinterpret_cast<const float4*>(&d_h2[s2 * AD + lane * 4]);
            float4 v3 = *reinterpret_cast<const float4*>(&d_h2[s3 * AD + lane * 4]);
            acc.x += v0.x; acc.y += v0.y; acc.z += v0.z; acc.w += v0.w;
            acc2.x += v1.x; acc2.y += v1.y; acc2.z += v1.z; acc2.w += v1.w;
            acc.x += v2.x; acc.y += v2.y; acc.z += v2.z; acc.w += v2.w;
            acc2.x += v3.x; acc2.y += v3.y; acc2.z += v3.z; acc2.w += v3.w;
        }
        for (; e < end; e++) {
            int s0 = d_csrc[e];
            float4 v0 = *reinterpret_cast<const float4*>(&d_h2[s0 * AD + lane * 4]);
            acc.x += v0.x; acc.y += v0.y; acc.z += v0.z; acc.w += v0.w;
        }
        acc.x += acc2.x; acc.y += acc2.y; acc.z += acc2.z; acc.w += acc2.w;

        float4 b = *reinterpret_cast<const float4*>(&bias[lane * 4]);
        acc.x = acc.x * din + b.x; acc.y = acc.y * din + b.y;
        acc.z = acc.z * din + b.z; acc.w = acc.w * din + b.w;
        if (!fin) {
            acc.x = gelu_exact(acc.x); acc.y = gelu_exact(acc.y);
            acc.z = gelu_exact(acc.z); acc.w = gelu_exact(acc.w);
            uint2 ph = make_uint2(bfpack(acc.x, acc.y), bfpack(acc.z, acc.w));
            uint2 pl = make_uint2(bfpack(bflo(acc.x), bflo(acc.y)),
                                  bfpack(bflo(acc.z), bflo(acc.w)));
            reinterpret_cast<uint2*>(d_hbf_hi)[n * 32 + lane] = ph;
            reinterpret_cast<uint2*>(d_hbf_lo)[n * 32 + lane] = pl;
        } else {
            *reinterpret_cast<float4*>(&hout[n * AD + lane * 4]) = acc;
        }
    } else {
        int n = (blockIdx.x - WB) * 8 + (tid >> 5);
        if (n >= NN) return;
        int beg = d_off[n], end = d_off[n + 1];
        float projd = d_proj[n];

        float amax = 0.f;
        for (int c = beg; c < end; c += 32) {
            int i = c + lane;
            if (i < end) {
                float a = projd - d_proj[d_csrc[i]];
                amax = fmaxf(amax, a);
            }
        }
        #pragma unroll
        for (int o = 16; o > 0; o >>= 1)
            amax = fmaxf(amax, __shfl_xor_sync(0xffffffffu, amax, o));

        float es = expf(-amax);
        float2 tn = *reinterpret_cast<const float2*>(&d_t[n * SD + lane * 2]);
        float mx = es * tn.x, my = es * tn.y;
        float den = es;

        for (int c = beg; c < end; c += 32) {
            int i = c + lane;
            int cnt = min(32, end - c);
            int srcl = (i < end) ? d_csrc[i] : 0;
            float al = (i < end) ? (projd - d_proj[srcl]) : 0.f;
            float ewl = expf(al - amax);
            int j = 0;
            for (; j + 4 <= cnt; j += 4) {
                float e0 = __shfl_sync(0xffffffffu, ewl, j + 0);
                float e1 = __shfl_sync(0xffffffffu, ewl, j + 1);
                float e2 = __shfl_sync(0xffffffffu, ewl, j + 2);
                float e3 = __shfl_sync(0xffffffffu, ewl, j + 3);
                int s0 = __shfl_sync(0xffffffffu, srcl, j + 0);
                int s1 = __shfl_sync(0xffffffffu, srcl, j + 1);
                int s2 = __shfl_sync(0xffffffffu, srcl, j + 2);
                int s3 = __shfl_sync(0xffffffffu, srcl, j + 3);
                float2 t0 = *reinterpret_cast<const float2*>(&d_t[s0 * SD + lane * 2]);
                float2 t1 = *reinterpret_cast<const float2*>(&d_t[s1 * SD + lane * 2]);
                float2 t2 = *reinterpret_cast<const float2*>(&d_t[s2 * SD + lane * 2]);
                float2 t3 = *reinterpret_cast<const float2*>(&d_t[s3 * SD + lane * 2]);
                mx += e0 * t0.x; my += e0 * t0.y;
                mx += e1 * t1.x; my += e1 * t1.y;
                mx += e2 * t2.x; my += e2 * t2.y;
                mx += e3 * t3.x; my += e3 * t3.y;
                den += e0 + e1 + e2 + e3;
            }
            for (; j < cnt; j++) {
                float ew = __shfl_sync(0xffffffffu, ewl, j);
                int sj = __shfl_sync(0xffffffffu, srcl, j);
                float2 tv = *reinterpret_cast<const float2*>(&d_t[sj * SD + lane * 2]);
                mx += ew * tv.x; my += ew * tv.y;
                den += ew;
            }
        }
        float inv = 1.f / (den + 1e-16f);
        float2 uv = *reinterpret_cast<const float2*>(&d_u[n * SD + lane * 2]);
        float2 res;
        res.x = gelu_exact(uv.x + mx * inv);
        res.y = gelu_exact(uv.y + my * inv);
        if (!fin) {
            reinterpret_cast<uint32_t*>(d_gbf_hi)[n * 32 + lane] = bfpack(res.x, res.y);
            reinterpret_cast<uint32_t*>(d_gbf_lo)[n * 32 + lane] = bfpack(bflo(res.x), bflo(res.y));
        } else {
            *reinterpret_cast<float2*>(&gout[n * SD + lane * 2]) = res;
        }
    }
}

// ---------------- host launcher ----------------
extern "C" void kernel_launch(void* const* d_in, const int* in_sizes, int n_in,
                              void* d_out, int out_size) {
    const float* x    = (const float*)d_in[0];
    const float* s    = (const float*)d_in[1];
    const int*   ei   = (const int*)d_in[2];
    const float* gcnW = (const float*)d_in[3];
    const float* gcnb = (const float*)d_in[4];
    const float* w1W  = (const float*)d_in[5];
    const float* w1b  = (const float*)d_in[6];
    const float* w2W  = (const float*)d_in[7];
    const float* w2b  = (const float*)d_in[8];
    const float* ga   = (const float*)d_in[9];
    float* out = (float*)d_out;

    cudaFuncSetAttribute(k_mma, cudaFuncAttributeMaxDynamicSharedMemorySize, MM_SMEM);

    void* p;
    cudaGetSymbolAddress(&p, d_deg);   int* degp = (int*)p;
    cudaGetSymbolAddress(&p, d_wthi);  __nv_bfloat16* wthi = (__nv_bfloat16*)p;
    cudaGetSymbolAddress(&p, d_wtlo);  __nv_bfloat16* wtlo = (__nv_bfloat16*)p;
    cudaGetSymbolAddress(&p, d_w2thi); __nv_bfloat16* w2thi = (__nv_bfloat16*)p;
    cudaGetSymbolAddress(&p, d_w2tlo); __nv_bfloat16* w2tlo = (__nv_bfloat16*)p;
    cudaGetSymbolAddress(&p, d_w1thi); __nv_bfloat16* w1thi = (__nv_bfloat16*)p;
    cudaGetSymbolAddress(&p, d_w1tlo); __nv_bfloat16* w1tlo = (__nv_bfloat16*)p;

    cudaMemsetAsync(degp, 0, NN * sizeof(int));
    k_prep<<<PB_TOT, 256>>>(x, s, ei, gcnW, w2W, w1W);
    k_scan<<<1, 1024>>>();
    k_csr_scatter<<<(NE / 4 + 255) / 256, 256>>>(ei);

    for (int i = 0; i < NL; i++) {
        k_mma<<<2 * MMB, 256, MM_SMEM>>>(wthi + i * AD * AD, wtlo + i * AD * AD,
                                         w2thi + i * SD * SD, w2tlo + i * SD * SD,
                                         w1thi + i * SD * SD, w1tlo + i * SD * SD,
                                         w2b + i * SD, w1b + i * SD, ga + i * SD);
        k_mega_edge<<<2 * WB, 256>>>(gcnb + i * AD, out, (i == NL - 1) ? 1 : 0, out + NN * AD);
    }
}

// round 9
// speedup vs baseline: 1.1894x; 1.0139x over previous
#include <cuda_runtime.h>
#include <cuda_bf16.h>
#include <math.h>
#include <stdint.h>

#define NN 50000
#define NE 800000
#define AD 128
#define SD 64
#define NL 4

#define WB 6250           // ceil(NN/8): warp-per-node blocks
#define MMB 391           // ceil(NN/128): 128-row MMA tiles

// ---------------- scratch (static device globals; no allocation) ----------------
__device__ float d_h2[NN * AD];                // GCN post-GEMM (dinv-scaled), fp32 for gather
__device__ float d_t[NN * SD];
__device__ float d_u[NN * SD];
__device__ float d_proj[NN];
__device__ float d_dinv[NN];
__device__ int   d_deg[NN];
__device__ int   d_off[NN + 1];
__device__ int   d_cur[NN];
__device__ int   d_csrc[NE];
// bf16 split planes (activations)
__device__ __nv_bfloat16 d_hbf_hi[NN * AD];
__device__ __nv_bfloat16 d_hbf_lo[NN * AD];
__device__ __nv_bfloat16 d_gbf_hi[NN * SD];
__device__ __nv_bfloat16 d_gbf_lo[NN * SD];
// bf16 split planes (weights, transposed K-major: Wt[col][k])
__device__ __nv_bfloat16 d_wthi[NL * AD * AD];
__device__ __nv_bfloat16 d_wtlo[NL * AD * AD];
__device__ __nv_bfloat16 d_w2thi[NL * SD * SD];
__device__ __nv_bfloat16 d_w2tlo[NL * SD * SD];
__device__ __nv_bfloat16 d_w1thi[NL * SD * SD];
__device__ __nv_bfloat16 d_w1tlo[NL * SD * SD];

__device__ __forceinline__ float gelu_exact(float x) {
    return 0.5f * x * (1.0f + erff(x * 0.7071067811865476f));
}
__device__ __forceinline__ uint32_t bfpack(float a, float b) {
    __nv_bfloat162 h = __floats2bfloat162_rn(a, b);
    return *reinterpret_cast<uint32_t*>(&h);
}
__device__ __forceinline__ float bflo(float a) {
    __nv_bfloat16 h = __float2bfloat16(a);
    return a - __bfloat162float(h);
}

// mma.sync m16n8k16 bf16 -> f32 (baseline PTX, sm_80+)
__device__ __forceinline__ void mma_bf16(float* c, const uint32_t* a, const uint32_t* b) {
    asm volatile(
        "mma.sync.aligned.m16n8k16.row.col.f32.bf16.bf16.f32 "
        "{%0,%1,%2,%3}, {%4,%5,%6,%7}, {%8,%9}, {%0,%1,%2,%3};"
        : "+f"(c[0]), "+f"(c[1]), "+f"(c[2]), "+f"(c[3])
        : "r"(a[0]), "r"(a[1]), "r"(a[2]), "r"(a[3]), "r"(b[0]), "r"(b[1]));
}

// ---------------- prep: convert x/s/W planes + degree count (grid-fused) ----------------
#define PB_X 3125
#define PB_S 1563
#define PB_D 782
#define PB_WG 32
#define PB_W2 8
#define PB_W1 8
#define PB_TOT (PB_X + PB_S + PB_D + PB_WG + PB_W2 + PB_W1)

__global__ void k_prep(const float* __restrict__ x, const float* __restrict__ s,
                       const int* __restrict__ ei, const float* __restrict__ gcnW,
                       const float* __restrict__ w2W, const float* __restrict__ w1W) {
    int b = blockIdx.x, tid = threadIdx.x;
    if (b < PB_X) {
        int i8 = (b * 256 + tid) * 8;
        float4 f0 = *reinterpret_cast<const float4*>(x + i8);
        float4 f1 = *reinterpret_cast<const float4*>(x + i8 + 4);
        uint4 hv = make_uint4(bfpack(f0.x, f0.y), bfpack(f0.z, f0.w),
                              bfpack(f1.x, f1.y), bfpack(f1.z, f1.w));
        uint4 lv = make_uint4(bfpack(bflo(f0.x), bflo(f0.y)), bfpack(bflo(f0.z), bflo(f0.w)),
                              bfpack(bflo(f1.x), bflo(f1.y)), bfpack(bflo(f1.z), bflo(f1.w)));
        reinterpret_cast<uint4*>(d_hbf_hi)[i8 >> 3] = hv;
        reinterpret_cast<uint4*>(d_hbf_lo)[i8 >> 3] = lv;
    } else if (b < PB_X + PB_S) {
        int i8 = ((b - PB_X) * 256 + tid) * 8;
        if (i8 < NN * SD) {
            float4 f0 = *reinterpret_cast<const float4*>(s + i8);
            float4 f1 = *reinterpret_cast<const float4*>(s + i8 + 4);
            uint4 hv = make_uint4(bfpack(f0.x, f0.y), bfpack(f0.z, f0.w),
                                  bfpack(f1.x, f1.y), bfpack(f1.z, f1.w));
            uint4 lv = make_uint4(bfpack(bflo(f0.x), bflo(f0.y)), bfpack(bflo(f0.z), bflo(f0.w)),
                                  bfpack(bflo(f1.x), bflo(f1.y)), bfpack(bflo(f1.z), bflo(f1.w)));
            reinterpret_cast<uint4*>(d_gbf_hi)[i8 >> 3] = hv;
            reinterpret_cast<uint4*>(d_gbf_lo)[i8 >> 3] = lv;
        }
    } else if (b < PB_X + PB_S + PB_D) {
        int i = (b - PB_X - PB_S) * 256 + tid;
        if (i < NE / 4) {
            int4 d4 = reinterpret_cast<const int4*>(ei + NE)[i];
            atomicAdd(&d_deg[d4.x], 1);
            atomicAdd(&d_deg[d4.y], 1);
            atomicAdd(&d_deg[d4.z], 1);
            atomicAdd(&d_deg[d4.w], 1);
        }
    } else if (b < PB_X + PB_S + PB_D + PB_WG) {
        int base = ((b - PB_X - PB_S - PB_D) * 256 + tid) * 8;
        #pragma unroll
        for (int j = 0; j < 8; j++) {
            int e = base + j;
            int l = e >> 14, r = e & 16383, k = r >> 7, c = r & 127;
            float v = gcnW[e];
            __nv_bfloat16 h = __float2bfloat16(v);
            d_wthi[(l << 14) + c * 128 + k] = h;
            d_wtlo[(l << 14) + c * 128 + k] = __float2bfloat16(v - __bfloat162float(h));
        }
    } else {
        int isW1 = (b >= PB_X + PB_S + PB_D + PB_WG + PB_W2);
        int bb = b - PB_X - PB_S - PB_D - PB_WG - (isW1 ? PB_W2 : 0);
        const float* Wsrc = isW1 ? w1W : w2W;
        __nv_bfloat16* Phi = isW1 ? d_w1thi : d_w2thi;
        __nv_bfloat16* Plo = isW1 ? d_w1tlo : d_w2tlo;
        int base = (bb * 256 + tid) * 8;
        #pragma unroll
        for (int j = 0; j < 8; j++) {
            int e = base + j;
            int l = e >> 12, r = e & 4095, k = r >> 6, c = r & 63;
            float v = Wsrc[e];
            __nv_bfloat16 h = __float2bfloat16(v);
            Phi[(l << 12) + c * 64 + k] = h;
            Plo[(l << 12) + c * 64 + k] = __float2bfloat16(v - __bfloat162float(h));
        }
    }
}

// ---------------- scan (also dinv, cur) ----------------
__global__ void k_scan() {
    __shared__ int warpsums[32];
    int tid = threadIdx.x, lane = tid & 31, wid = tid >> 5;
    int carry = 0;
    if (tid == 0) d_off[0] = 0;
    for (int base = 0; base < NN; base += 1024) {
        int idx = base + tid;
        int v = (idx < NN) ? d_deg[idx] : 0;
        int x = v;
        #pragma unroll
        for (int o = 1; o < 32; o <<= 1) {
            int y = __shfl_up_sync(0xffffffffu, x, o);
            if (lane >= o) x += y;
        }
        if (lane == 31) warpsums[wid] = x;
        __syncthreads();
        if (wid == 0) {
            int w = warpsums[lane];
            #pragma unroll
            for (int o = 1; o < 32; o <<= 1) {
                int y = __shfl_up_sync(0xffffffffu, w, o);
                if (lane >= o) w += y;
            }
            warpsums[lane] = w;
        }
        __syncthreads();
        int prev = (wid > 0) ? warpsums[wid - 1] : 0;
        if (idx < NN) {
            int incl = carry + prev + x;
            d_off[idx + 1] = incl;
            d_cur[idx] = incl - v;
            d_dinv[idx] = rsqrtf((float)(v + 1));
        }
        int total = warpsums[31];
        __syncthreads();
        carry += total;
    }
}

__global__ void k_csr_scatter(const int* __restrict__ ei) {
    int i = blockIdx.x * blockDim.x + threadIdx.x;
    if (i < NE / 4) {
        int4 s4 = reinterpret_cast<const int4*>(ei)[i];
        int4 d4 = reinterpret_cast<const int4*>(ei + NE)[i];
        d_csrc[atomicAdd(&d_cur[d4.x], 1)] = s4.x;
        d_csrc[atomicAdd(&d_cur[d4.y], 1)] = s4.y;
        d_csrc[atomicAdd(&d_cur[d4.z], 1)] = s4.z;
        d_csrc[atomicAdd(&d_cur[d4.w], 1)] = s4.w;
    }
}

// ================= fused MMA megakernel (512 threads, 16 warps, 32x32 warp tiles) =================
#define GC_PITCH 272
#define GC_PLANE 34816
#define GN_PITCH 144
#define GN_PLANE 18432
#define MM_SMEM (4 * GC_PLANE)   // 139264

__global__ __launch_bounds__(512) void k_mma(
    const __nv_bfloat16* __restrict__ wthi, const __nv_bfloat16* __restrict__ wtlo,
    const __nv_bfloat16* __restrict__ w2thi, const __nv_bfloat16* __restrict__ w2tlo,
    const __nv_bfloat16* __restrict__ w1thi, const __nv_bfloat16* __restrict__ w1tlo,
    const float* __restrict__ b2, const float* __restrict__ b1,
    const float* __restrict__ avec) {
    extern __shared__ char sm[];
    int tid = threadIdx.x;
    int wid = tid >> 5, lane = tid & 31;
    int g = lane >> 2, tg = lane & 3;
    int wm = wid & 3, wn = wid >> 2;       // 4 m-warps x 4 n-warps

    if (blockIdx.x < MMB) {
        // ================== GCN GEMM: 128x128, K=128 ==================
        int r0 = blockIdx.x * 128;
        char* AH = sm;
        char* AL = sm + GC_PLANE;
        char* BH = sm + 2 * GC_PLANE;
        char* BL = sm + 3 * GC_PLANE;
        const uint4* AHg = reinterpret_cast<const uint4*>(d_hbf_hi);
        const uint4* ALg = reinterpret_cast<const uint4*>(d_hbf_lo);
        const uint4* BHg = reinterpret_cast<const uint4*>(wthi);
        const uint4* BLg = reinterpret_cast<const uint4*>(wtlo);
        #pragma unroll
        for (int it = 0; it < 4; it++) {
            int gg = it * 512 + tid;          // 0..2047
            int row = gg >> 4, c16 = gg & 15;
            int off = row * GC_PITCH + c16 * 16;
            int grow = r0 + row;
            uint4 vh = make_uint4(0, 0, 0, 0), vl = make_uint4(0, 0, 0, 0);
            if (grow < NN) {
                vh = AHg[grow * 16 + c16];
                vl = ALg[grow * 16 + c16];
            }
            *reinterpret_cast<uint4*>(AH + off) = vh;
            *reinterpret_cast<uint4*>(AL + off) = vl;
            *reinterpret_cast<uint4*>(BH + off) = BHg[gg];
            *reinterpret_cast<uint4*>(BL + off) = BLg[gg];
        }
        __syncthreads();

        float acc[2][4][4];
        #pragma unroll
        for (int a = 0; a < 2; a++)
            #pragma unroll
            for (int b = 0; b < 4; b++)
                #pragma unroll
                for (int c = 0; c < 4; c++) acc[a][b][c] = 0.f;

        #pragma unroll
        for (int t = 0; t < 3; t++) {
            const char* pA = (t == 2) ? AL : AH;
            const char* pB = (t == 1) ? BL : BH;
            #pragma unroll
            for (int k0 = 0; k0 < 8; k0++) {
                int kb = (k0 * 16 + tg * 2) * 2;   // byte col offset
                uint32_t afr[2][4];
                #pragma unroll
                for (int tm = 0; tm < 2; tm++) {
                    int r = wm * 32 + tm * 16 + g;
                    const char* base = pA + r * GC_PITCH + kb;
                    afr[tm][0] = *reinterpret_cast<const uint32_t*>(base);
                    afr[tm][1] = *reinterpret_cast<const uint32_t*>(base + 8 * GC_PITCH);
                    afr[tm][2] = *reinterpret_cast<const uint32_t*>(base + 16);
                    afr[tm][3] = *reinterpret_cast<const uint32_t*>(base + 8 * GC_PITCH + 16);
                }
                uint32_t bfr[4][2];
                #pragma unroll
                for (int tn = 0; tn < 4; tn++) {
                    int n = wn * 32 + tn * 8 + g;
                    const char* base = pB + n * GC_PITCH + kb;
                    bfr[tn][0] = *reinterpret_cast<const uint32_t*>(base);
                    bfr[tn][1] = *reinterpret_cast<const uint32_t*>(base + 16);
                }
                #pragma unroll
                for (int tm = 0; tm < 2; tm++)
                    #pragma unroll
                    for (int tn = 0; tn < 4; tn++)
                        mma_bf16(acc[tm][tn], afr[tm], bfr[tn]);
            }
        }
        // epilogue: scale by dinv[row], store fp32 h2
        #pragma unroll
        for (int tm = 0; tm < 2; tm++) {
            int r1 = r0 + wm * 32 + tm * 16 + g;
            int r2 = r1 + 8;
            float s1 = (r1 < NN) ? d_dinv[r1] : 0.f;
            float s2 = (r2 < NN) ? d_dinv[r2] : 0.f;
            #pragma unroll
            for (int tn = 0; tn < 4; tn++) {
                int c = wn * 32 + tn * 8 + tg * 2;
                if (r1 < NN)
                    *reinterpret_cast<float2*>(&d_h2[r1 * AD + c]) =
                        make_float2(acc[tm][tn][0] * s1, acc[tm][tn][1] * s1);
                if (r2 < NN)
                    *reinterpret_cast<float2*>(&d_h2[r2 * AD + c]) =
                        make_float2(acc[tm][tn][2] * s2, acc[tm][tn][3] * s2);
            }
        }
    } else {
        // ================== GNA GEMM: D = A @ [W2t;W1t]^T -> [t | u], K=64 ==================
        int r0 = (blockIdx.x - MMB) * 128;
        char* AH = sm;
        char* AL = sm + GN_PLANE;
        char* BH = sm + 2 * GN_PLANE;
        char* BL = sm + 3 * GN_PLANE;
        const uint4* AHg = reinterpret_cast<const uint4*>(d_gbf_hi);
        const uint4* ALg = reinterpret_cast<const uint4*>(d_gbf_lo);
        const uint4* B2H = reinterpret_cast<const uint4*>(w2thi);
        const uint4* B2L = reinterpret_cast<const uint4*>(w2tlo);
        const uint4* B1H = reinterpret_cast<const uint4*>(w1thi);
        const uint4* B1L = reinterpret_cast<const uint4*>(w1tlo);
        #pragma unroll
        for (int it = 0; it < 2; it++) {
            int gg = it * 512 + tid;          // 0..1023
            int row = gg >> 3, c8 = gg & 7;
            int off = row * GN_PITCH + c8 * 16;
            int grow = r0 + row;
            uint4 vh = make_uint4(0, 0, 0, 0), vl = make_uint4(0, 0, 0, 0);
            if (grow < NN) {
                vh = AHg[grow * 8 + c8];
                vl = ALg[grow * 8 + c8];
            }
            *reinterpret_cast<uint4*>(AH + off) = vh;
            *reinterpret_cast<uint4*>(AL + off) = vl;
            uint4 bh, bl;
            if (row < 64) {
                bh = B2H[row * 8 + c8];
                bl = B2L[row * 8 + c8];
            } else {
                bh = B1H[(row - 64) * 8 + c8];
                bl = B1L[(row - 64) * 8 + c8];
            }
            *reinterpret_cast<uint4*>(BH + off) = bh;
            *reinterpret_cast<uint4*>(BL + off) = bl;
        }
        __syncthreads();

        float acc[2][4][4];
        #pragma unroll
        for (int a = 0; a < 2; a++)
            #pragma unroll
            for (int b = 0; b < 4; b++)
                #pragma unroll
                for (int c = 0; c < 4; c++) acc[a][b][c] = 0.f;

        #pragma unroll
        for (int t = 0; t < 3; t++) {
            const char* pA = (t == 2) ? AL : AH;
            const char* pB = (t == 1) ? BL : BH;
            #pragma unroll
            for (int k0 = 0; k0 < 4; k0++) {
                int kb = (k0 * 16 + tg * 2) * 2;
                uint32_t afr[2][4];
                #pragma unroll
                for (int tm = 0; tm < 2; tm++) {
                    int r = wm * 32 + tm * 16 + g;
                    const char* base = pA + r * GN_PITCH + kb;
                    afr[tm][0] = *reinterpret_cast<const uint32_t*>(base);
                    afr[tm][1] = *reinterpret_cast<const uint32_t*>(base + 8 * GN_PITCH);
                    afr[tm][2] = *reinterpret_cast<const uint32_t*>(base + 16);
                    afr[tm][3] = *reinterpret_cast<const uint32_t*>(base + 8 * GN_PITCH + 16);
                }
                uint32_t bfr[4][2];
                #pragma unroll
                for (int tn = 0; tn < 4; tn++) {
                    int n = wn * 32 + tn * 8 + g;
                    const char* base = pB + n * GN_PITCH + kb;
                    bfr[tn][0] = *reinterpret_cast<const uint32_t*>(base);
                    bfr[tn][1] = *reinterpret_cast<const uint32_t*>(base + 16);
                }
                #pragma unroll
                for (int tm = 0; tm < 2; tm++)
                    #pragma unroll
                    for (int tn = 0; tn < 4; tn++)
                        mma_bf16(acc[tm][tn], afr[tm], bfr[tn]);
            }
        }
        __syncthreads();   // compute done; smem reusable for proj partials

        float* sP = reinterpret_cast<float*>(sm);   // [128][2]
        int isT = (wn < 2);
        const float* bias = isT ? b2 : b1;
        #pragma unroll
        for (int tm = 0; tm < 2; tm++) {
            int rl1 = wm * 32 + tm * 16 + g;
            int r1 = r0 + rl1;
            int r2 = r1 + 8;
            float p1 = 0.f, p2 = 0.f;
            #pragma unroll
            for (int tn = 0; tn < 4; tn++) {
                int cg = wn * 32 + tn * 8 + tg * 2;       // 0..127 across [t|u]
                int c = isT ? cg : (cg - 64);             // local 0..63
                float2 bb = *reinterpret_cast<const float2*>(&bias[c]);
                float v0 = acc[tm][tn][0] + bb.x;
                float v1 = acc[tm][tn][1] + bb.y;
                float v2 = acc[tm][tn][2] + bb.x;
                float v3 = acc[tm][tn][3] + bb.y;
                if (isT) {
                    float2 av = *reinterpret_cast<const float2*>(&avec[c]);
                    p1 += v0 * av.x + v1 * av.y;
                    p2 += v2 * av.x + v3 * av.y;
                    if (r1 < NN) *reinterpret_cast<float2*>(&d_t[r1 * SD + c]) = make_float2(v0, v1);
                    if (r2 < NN) *reinterpret_cast<float2*>(&d_t[r2 * SD + c]) = make_float2(v2, v3);
                } else {
                    if (r1 < NN) *reinterpret_cast<float2*>(&d_u[r1 * SD + c]) = make_float2(v0, v1);
                    if (r2 < NN) *reinterpret_cast<float2*>(&d_u[r2 * SD + c]) = make_float2(v2, v3);
                }
            }
            if (isT) {
                p1 += __shfl_xor_sync(0xffffffffu, p1, 1);
                p1 += __shfl_xor_sync(0xffffffffu, p1, 2);
                p2 += __shfl_xor_sync(0xffffffffu, p2, 1);
                p2 += __shfl_xor_sync(0xffffffffu, p2, 2);
                if (tg == 0) {
                    sP[rl1 * 2 + wn] = p1;
                    sP[(rl1 + 8) * 2 + wn] = p2;
                }
            }
        }
        __syncthreads();
        if (tid < 128) {
            int row = r0 + tid;
            if (row < NN) d_proj[row] = sP[tid * 2] + sP[tid * 2 + 1];
        }
    }
}

// ================= megakernel B: GCN gather + GNA attn (warp per node) =================
__global__ void k_mega_edge(const float* __restrict__ bias, float* __restrict__ hout,
                            int fin, float* __restrict__ gout) {
    int tid = threadIdx.x;
    int lane = tid & 31;

    if (blockIdx.x < WB) {
        int n = blockIdx.x * 8 + (tid >> 5);
        if (n >= NN) return;
        int beg = d_off[n], end = d_off[n + 1];
        float din = d_dinv[n];

        float4 acc = *reinterpret_cast<const float4*>(&d_h2[n * AD + lane * 4]);
        float4 acc2 = make_float4(0.f, 0.f, 0.f, 0.f);
        int e = beg;
        for (; e + 4 <= end; e += 4) {
            int s0 = d_csrc[e + 0];
            int s1 = d_csrc[e + 1];
            int s2 = d_csrc[e + 2];
            int s3 = d_csrc[e + 3];
            float4 v0 = *reinterpret_cast<const float4*>(&d_h2[s0 * AD + lane * 4]);
            float4 v1 = *reinterpret_cast<const float4*>(&d_h2[s1 * AD + lane * 4]);
            float4 v2 = *reinterpret_cast<const float4*>(&d_h2[s2 * AD + lane * 4]);
            float4 v3 = *reinterpret_cast<const float4*>(&d_h2[s3 * AD + lane * 4]);
            acc.x += v0.x; acc.y += v0.y; acc.z += v0.z; acc.w += v0.w;
            acc2.x += v1.x; acc2.y += v1.y; acc2.z += v1.z; acc2.w += v1.w;
            acc.x += v2.x; acc.y += v2.y; acc.z += v2.z; acc.w += v2.w;
            acc2.x += v3.x; acc2.y += v3.y; acc2.z += v3.z; acc2.w += v3.w;
        }
        for (; e < end; e++) {
            int s0 = d_csrc[e];
            float4 v0 = *reinterpret_cast<const float4*>(&d_h2[s0 * AD + lane * 4]);
            acc.x += v0.x; acc.y += v0.y; acc.z += v0.z; acc.w += v0.w;
        }
        acc.x += acc2.x; acc.y += acc2.y; acc.z += acc2.z; acc.w += acc2.w;

        float4 b = *reinterpret_cast<const float4*>(&bias[lane * 4]);
        acc.x = acc.x * din + b.x; acc.y = acc.y * din + b.y;
        acc.z = acc.z * din + b.z; acc.w = acc.w * din + b.w;
        if (!fin) {
            acc.x = gelu_exact(acc.x); acc.y = gelu_exact(acc.y);
            acc.z = gelu_exact(acc.z); acc.w = gelu_exact(acc.w);
            uint2 ph = make_uint2(bfpack(acc.x, acc.y), bfpack(acc.z, acc.w));
            uint2 pl = make_uint2(bfpack(bflo(acc.x), bflo(acc.y)),
                                  bfpack(bflo(acc.z), bflo(acc.w)));
            reinterpret_cast<uint2*>(d_hbf_hi)[n * 32 + lane] = ph;
            reinterpret_cast<uint2*>(d_hbf_lo)[n * 32 + lane] = pl;
        } else {
            *reinterpret_cast<float4*>(&hout[n * AD + lane * 4]) = acc;
        }
    } else {
        int n = (blockIdx.x - WB) * 8 + (tid >> 5);
        if (n >= NN) return;
        int beg = d_off[n], end = d_off[n + 1];
        float projd = d_proj[n];

        float amax = 0.f;
        for (int c = beg; c < end; c += 32) {
            int i = c + lane;
            if (i < end) {
                float a = projd - d_proj[d_csrc[i]];
                amax = fmaxf(amax, a);
            }
        }
        #pragma unroll
        for (int o = 16; o > 0; o >>= 1)
            amax = fmaxf(amax, __shfl_xor_sync(0xffffffffu, amax, o));

        float es = expf(-amax);
        float2 tn = *reinterpret_cast<const float2*>(&d_t[n * SD + lane * 2]);
        float mx = es * tn.x, my = es * tn.y;
        float den = es;

        for (int c = beg; c < end; c += 32) {
            int i = c + lane;
            int cnt = min(32, end - c);
            int srcl = (i < end) ? d_csrc[i] : 0;
            float al = (i < end) ? (projd - d_proj[srcl]) : 0.f;
            float ewl = expf(al - amax);
            int j = 0;
            for (; j + 4 <= cnt; j += 4) {
                float e0 = __shfl_sync(0xffffffffu, ewl, j + 0);
                float e1 = __shfl_sync(0xffffffffu, ewl, j + 1);
                float e2 = __shfl_sync(0xffffffffu, ewl, j + 2);
                float e3 = __shfl_sync(0xffffffffu, ewl, j + 3);
                int s0 = __shfl_sync(0xffffffffu, srcl, j + 0);
                int s1 = __shfl_sync(0xffffffffu, srcl, j + 1);
                int s2 = __shfl_sync(0xffffffffu, srcl, j + 2);
                int s3 = __shfl_sync(0xffffffffu, srcl, j + 3);
                float2 t0 = *reinterpret_cast<const float2*>(&d_t[s0 * SD + lane * 2]);
                float2 t1 = *reinterpret_cast<const float2*>(&d_t[s1 * SD + lane * 2]);
                float2 t2 = *reinterpret_cast<const float2*>(&d_t[s2 * SD + lane * 2]);
                float2 t3 = *reinterpret_cast<const float2*>(&d_t[s3 * SD + lane * 2]);
                mx += e0 * t0.x; my += e0 * t0.y;
                mx += e1 * t1.x; my += e1 * t1.y;
                mx += e2 * t2.x; my += e2 * t2.y;
                mx += e3 * t3.x; my += e3 * t3.y;
                den += e0 + e1 + e2 + e3;
            }
            for (; j < cnt; j++) {
                float ew = __shfl_sync(0xffffffffu, ewl, j);
                int sj = __shfl_sync(0xffffffffu, srcl, j);
                float2 tv = *reinterpret_cast<const float2*>(&d_t[sj * SD + lane * 2]);
                mx += ew * tv.x; my += ew * tv.y;
                den += ew;
            }
        }
        float inv = 1.f / (den + 1e-16f);
        float2 uv = *reinterpret_cast<const float2*>(&d_u[n * SD + lane * 2]);
        float2 res;
        res.x = gelu_exact(uv.x + mx * inv);
        res.y = gelu_exact(uv.y + my * inv);
        if (!fin) {
            reinterpret_cast<uint32_t*>(d_gbf_hi)[n * 32 + lane] = bfpack(res.x, res.y);
            reinterpret_cast<uint32_t*>(d_gbf_lo)[n * 32 + lane] = bfpack(bflo(res.x), bflo(res.y));
        } else {
            *reinterpret_cast<float2*>(&gout[n * SD + lane * 2]) = res;
        }
    }
}

// ---------------- host launcher ----------------
extern "C" void kernel_launch(void* const* d_in, const int* in_sizes, int n_in,
                              void* d_out, int out_size) {
    const float* x    = (const float*)d_in[0];
    const float* s    = (const float*)d_in[1];
    const int*   ei   = (const int*)d_in[2];
    const float* gcnW = (const float*)d_in[3];
    const float* gcnb = (const float*)d_in[4];
    const float* w1W  = (const float*)d_in[5];
    const float* w1b  = (const float*)d_in[6];
    const float* w2W  = (const float*)d_in[7];
    const float* w2b  = (const float*)d_in[8];
    const float* ga   = (const float*)d_in[9];
    float* out = (float*)d_out;

    cudaFuncSetAttribute(k_mma, cudaFuncAttributeMaxDynamicSharedMemorySize, MM_SMEM);

    void* p;
    cudaGetSymbolAddress(&p, d_deg);   int* degp = (int*)p;
    cudaGetSymbolAddress(&p, d_wthi);  __nv_bfloat16* wthi = (__nv_bfloat16*)p;
    cudaGetSymbolAddress(&p, d_wtlo);  __nv_bfloat16* wtlo = (__nv_bfloat16*)p;
    cudaGetSymbolAddress(&p, d_w2thi); __nv_bfloat16* w2thi = (__nv_bfloat16*)p;
    cudaGetSymbolAddress(&p, d_w2tlo); __nv_bfloat16* w2tlo = (__nv_bfloat16*)p;
    cudaGetSymbolAddress(&p, d_w1thi); __nv_bfloat16* w1thi = (__nv_bfloat16*)p;
    cudaGetSymbolAddress(&p, d_w1tlo); __nv_bfloat16* w1tlo = (__nv_bfloat16*)p;

    cudaMemsetAsync(degp, 0, NN * sizeof(int));
    k_prep<<<PB_TOT, 256>>>(x, s, ei, gcnW, w2W, w1W);
    k_scan<<<1, 1024>>>();
    k_csr_scatter<<<(NE / 4 + 255) / 256, 256>>>(ei);

    for (int i = 0; i < NL; i++) {
        k_mma<<<2 * MMB, 512, MM_SMEM>>>(wthi + i * AD * AD, wtlo + i * AD * AD,
                                         w2thi + i * SD * SD, w2tlo + i * SD * SD,
                                         w1thi + i * SD * SD, w1tlo + i * SD * SD,
                                         w2b + i * SD, w1b + i * SD, ga + i * SD);
        k_mega_edge<<<2 * WB, 256>>>(gcnb + i * AD, out, (i == NL - 1) ? 1 : 0, out + NN * AD);
    }
}

// round 11
// speedup vs baseline: 1.2911x; 1.0855x over previous
#include <cuda_runtime.h>
#include <cuda_bf16.h>
#include <math.h>
#include <stdint.h>

#define NN 50000
#define NE 800000
#define AD 128
#define SD 64
#define NL 4

#define WB 6250           // ceil(NN/8): warp-per-node blocks
#define MMB 391           // ceil(NN/128): 128-row MMA tiles
#define SCB 196           // ceil(NN/256): scan blocks

// ---------------- scratch (static device globals; no allocation) ----------------
__device__ float d_h2[NN * AD];                // GCN post-GEMM (dinv-scaled), fp32 for gather
__device__ float d_t[NN * SD];
__device__ float d_u[NN * SD];
__device__ float d_proj[NN];
__device__ float d_dinv[NN];
__device__ int   d_deg[NN];
__device__ int   d_off[NN + 1];
__device__ int   d_cur[NN];
__device__ int   d_part[256];
__device__ int   d_csrc[NE];
// bf16 split planes (activations)
__device__ __nv_bfloat16 d_hbf_hi[NN * AD];
__device__ __nv_bfloat16 d_hbf_lo[NN * AD];
__device__ __nv_bfloat16 d_gbf_hi[NN * SD];
__device__ __nv_bfloat16 d_gbf_lo[NN * SD];
// bf16 split planes (weights, transposed K-major: Wt[col][k])
__device__ __nv_bfloat16 d_wthi[NL * AD * AD];
__device__ __nv_bfloat16 d_wtlo[NL * AD * AD];
__device__ __nv_bfloat16 d_w2thi[NL * SD * SD];
__device__ __nv_bfloat16 d_w2tlo[NL * SD * SD];
__device__ __nv_bfloat16 d_w1thi[NL * SD * SD];
__device__ __nv_bfloat16 d_w1tlo[NL * SD * SD];

__device__ __forceinline__ float gelu_exact(float x) {
    return 0.5f * x * (1.0f + erff(x * 0.7071067811865476f));
}
__device__ __forceinline__ uint32_t bfpack(float a, float b) {
    __nv_bfloat162 h = __floats2bfloat162_rn(a, b);
    return *reinterpret_cast<uint32_t*>(&h);
}
__device__ __forceinline__ float bflo(float a) {
    __nv_bfloat16 h = __float2bfloat16(a);
    return a - __bfloat162float(h);
}

// mma.sync m16n8k16 bf16 -> f32 (baseline PTX, sm_80+)
__device__ __forceinline__ void mma_bf16(float* c, const uint32_t* a, const uint32_t* b) {
    asm volatile(
        "mma.sync.aligned.m16n8k16.row.col.f32.bf16.bf16.f32 "
        "{%0,%1,%2,%3}, {%4,%5,%6,%7}, {%8,%9}, {%0,%1,%2,%3};"
        : "+f"(c[0]), "+f"(c[1]), "+f"(c[2]), "+f"(c[3])
        : "r"(a[0]), "r"(a[1]), "r"(a[2]), "r"(a[3]), "r"(b[0]), "r"(b[1]));
}

__device__ __forceinline__ uint32_t smem_to_u32(const void* p) {
    uint32_t a;
    asm("{ .reg .u64 t; cvta.to.shared.u64 t, %1; cvt.u32.u64 %0, t; }" : "=r"(a) : "l"(p));
    return a;
}
// cp.async 16B; pred==0 -> zero-fill (src still a valid clamped address)
__device__ __forceinline__ void cpa16(uint32_t saddr, const void* g, int pred) {
    asm volatile(
        "{\n\t.reg .pred p;\n\tsetp.ne.b32 p, %2, 0;\n\t"
        "@p cp.async.cg.shared.global [%0], [%1], 16;\n\t"
        "@!p cp.async.cg.shared.global [%0], [%1], 16, 0;\n\t}"
        :: "r"(saddr), "l"(g), "r"(pred));
}
#define CP_COMMIT() asm volatile("cp.async.commit_group;" ::: "memory")
#define CP_WAIT(n)  asm volatile("cp.async.wait_group %0;" :: "n"(n) : "memory")

// ---------------- prep: convert x/s/W planes + degree count (grid-fused) ----------------
#define PB_X 3125
#define PB_S 1563
#define PB_D 782
#define PB_WG 32
#define PB_W2 8
#define PB_W1 8
#define PB_TOT (PB_X + PB_S + PB_D + PB_WG + PB_W2 + PB_W1)

__global__ void k_prep(const float* __restrict__ x, const float* __restrict__ s,
                       const int* __restrict__ ei, const float* __restrict__ gcnW,
                       const float* __restrict__ w2W, const float* __restrict__ w1W) {
    int b = blockIdx.x, tid = threadIdx.x;
    if (b < PB_X) {
        int i8 = (b * 256 + tid) * 8;
        float4 f0 = *reinterpret_cast<const float4*>(x + i8);
        float4 f1 = *reinterpret_cast<const float4*>(x + i8 + 4);
        uint4 hv = make_uint4(bfpack(f0.x, f0.y), bfpack(f0.z, f0.w),
                              bfpack(f1.x, f1.y), bfpack(f1.z, f1.w));
        uint4 lv = make_uint4(bfpack(bflo(f0.x), bflo(f0.y)), bfpack(bflo(f0.z), bflo(f0.w)),
                              bfpack(bflo(f1.x), bflo(f1.y)), bfpack(bflo(f1.z), bflo(f1.w)));
        reinterpret_cast<uint4*>(d_hbf_hi)[i8 >> 3] = hv;
        reinterpret_cast<uint4*>(d_hbf_lo)[i8 >> 3] = lv;
    } else if (b < PB_X + PB_S) {
        int i8 = ((b - PB_X) * 256 + tid) * 8;
        if (i8 < NN * SD) {
            float4 f0 = *reinterpret_cast<const float4*>(s + i8);
            float4 f1 = *reinterpret_cast<const float4*>(s + i8 + 4);
            uint4 hv = make_uint4(bfpack(f0.x, f0.y), bfpack(f0.z, f0.w),
                                  bfpack(f1.x, f1.y), bfpack(f1.z, f1.w));
            uint4 lv = make_uint4(bfpack(bflo(f0.x), bflo(f0.y)), bfpack(bflo(f0.z), bflo(f0.w)),
                                  bfpack(bflo(f1.x), bflo(f1.y)), bfpack(bflo(f1.z), bflo(f1.w)));
            reinterpret_cast<uint4*>(d_gbf_hi)[i8 >> 3] = hv;
            reinterpret_cast<uint4*>(d_gbf_lo)[i8 >> 3] = lv;
        }
    } else if (b < PB_X + PB_S + PB_D) {
        int i = (b - PB_X - PB_S) * 256 + tid;
        if (i < NE / 4) {
            int4 d4 = reinterpret_cast<const int4*>(ei + NE)[i];
            atomicAdd(&d_deg[d4.x], 1);
            atomicAdd(&d_deg[d4.y], 1);
            atomicAdd(&d_deg[d4.z], 1);
            atomicAdd(&d_deg[d4.w], 1);
        }
    } else if (b < PB_X + PB_S + PB_D + PB_WG) {
        int base = ((b - PB_X - PB_S - PB_D) * 256 + tid) * 8;
        #pragma unroll
        for (int j = 0; j < 8; j++) {
            int e = base + j;
            int l = e >> 14, r = e & 16383, k = r >> 7, c = r & 127;
            float v = gcnW[e];
            __nv_bfloat16 h = __float2bfloat16(v);
            d_wthi[(l << 14) + c * 128 + k] = h;
            d_wtlo[(l << 14) + c * 128 + k] = __float2bfloat16(v - __bfloat162float(h));
        }
    } else {
        int isW1 = (b >= PB_X + PB_S + PB_D + PB_WG + PB_W2);
        int bb = b - PB_X - PB_S - PB_D - PB_WG - (isW1 ? PB_W2 : 0);
        const float* Wsrc = isW1 ? w1W : w2W;
        __nv_bfloat16* Phi = isW1 ? d_w1thi : d_w2thi;
        __nv_bfloat16* Plo = isW1 ? d_w1tlo : d_w2tlo;
        int base = (bb * 256 + tid) * 8;
        #pragma unroll
        for (int j = 0; j < 8; j++) {
            int e = base + j;
            int l = e >> 12, r = e & 4095, k = r >> 6, c = r & 63;
            float v = Wsrc[e];
            __nv_bfloat16 h = __float2bfloat16(v);
            Phi[(l << 12) + c * 64 + k] = h;
            Plo[(l << 12) + c * 64 + k] = __float2bfloat16(v - __bfloat162float(h));
        }
    }
}

// ---------------- 3-phase scan ----------------
__device__ __forceinline__ int block_incl_scan_256(int v, int* warpsums) {
    int lane = threadIdx.x & 31, wid = threadIdx.x >> 5;
    int x = v;
    #pragma unroll
    for (int o = 1; o < 32; o <<= 1) {
        int y = __shfl_up_sync(0xffffffffu, x, o);
        if (lane >= o) x += y;
    }
    if (lane == 31) warpsums[wid] = x;
    __syncthreads();
    if (wid == 0 && lane < 8) {
        int w = warpsums[lane];
        #pragma unroll
        for (int o = 1; o < 8; o <<= 1) {
            int y = __shfl_up_sync(0xffu, w, o);
            if (lane >= o) w += y;
        }
        warpsums[lane] = w;
    }
    __syncthreads();
    return x + (wid > 0 ? warpsums[wid - 1] : 0);
}

__global__ void k_scanA() {
    __shared__ int ws[8];
    int idx = blockIdx.x * 256 + threadIdx.x;
    int v = (idx < NN) ? d_deg[idx] : 0;
    int incl = block_incl_scan_256(v, ws);
    if (idx < NN) {
        d_off[idx + 1] = incl;                   // local inclusive, fixed up in C
        d_dinv[idx] = rsqrtf((float)(v + 1));
    }
    if (threadIdx.x == 255) d_part[blockIdx.x] = incl;
}

__global__ void k_scanB() {
    __shared__ int ws[8];
    int tid = threadIdx.x;
    int v = (tid < SCB) ? d_part[tid] : 0;
    int incl = block_incl_scan_256(v, ws);
    d_part[tid] = incl - v;                      // exclusive
    if (tid == 0) d_off[0] = 0;
}

__global__ void k_scanC() {
    int idx = blockIdx.x * 256 + threadIdx.x;
    if (idx < NN) {
        int base = d_part[blockIdx.x];
        int incl = d_off[idx + 1] + base;
        d_off[idx + 1] = incl;
        d_cur[idx] = incl - d_deg[idx];
    }
}

__global__ void k_csr_scatter(const int* __restrict__ ei) {
    int i = blockIdx.x * blockDim.x + threadIdx.x;
    if (i < NE / 4) {
        int4 s4 = reinterpret_cast<const int4*>(ei)[i];
        int4 d4 = reinterpret_cast<const int4*>(ei + NE)[i];
        d_csrc[atomicAdd(&d_cur[d4.x], 1)] = s4.x;
        d_csrc[atomicAdd(&d_cur[d4.y], 1)] = s4.y;
        d_csrc[atomicAdd(&d_cur[d4.z], 1)] = s4.z;
        d_csrc[atomicAdd(&d_cur[d4.w], 1)] = s4.w;
    }
}

// ================= fused MMA megakernel (512 thr, cp.async pipelined terms) =================
#define GC_PITCH 272
#define GC_PLANE 34816
#define GN_PITCH 144
#define GN_PLANE 18432
#define MM_SMEM (4 * GC_PLANE)   // 139264

__global__ __launch_bounds__(512) void k_mma(
    const __nv_bfloat16* __restrict__ wthi, const __nv_bfloat16* __restrict__ wtlo,
    const __nv_bfloat16* __restrict__ w2thi, const __nv_bfloat16* __restrict__ w2tlo,
    const __nv_bfloat16* __restrict__ w1thi, const __nv_bfloat16* __restrict__ w1tlo,
    const float* __restrict__ b2, const float* __restrict__ b1,
    const float* __restrict__ avec) {
    extern __shared__ char sm[];
    uint32_t sb = smem_to_u32(sm);
    int tid = threadIdx.x;
    int wid = tid >> 5, lane = tid & 31;
    int g = lane >> 2, tg = lane & 3;
    int wm = wid & 3, wn = wid >> 2;       // 4 m-warps x 4 n-warps

    if (blockIdx.x < MMB) {
        // ================== GCN GEMM: 128x128, K=128 ==================
        int r0 = blockIdx.x * 128;
        char* AH = sm;
        char* AL = sm + GC_PLANE;
        char* BH = sm + 2 * GC_PLANE;
        char* BL = sm + 3 * GC_PLANE;
        const uint4* AHg = reinterpret_cast<const uint4*>(d_hbf_hi);
        const uint4* ALg = reinterpret_cast<const uint4*>(d_hbf_lo);
        const uint4* BHg = reinterpret_cast<const uint4*>(wthi);
        const uint4* BLg = reinterpret_cast<const uint4*>(wtlo);
        // group 0: AH + BH
        #pragma unroll
        for (int it = 0; it < 4; it++) {
            int gg = it * 512 + tid;
            int row = gg >> 4, c16 = gg & 15;
            int off = row * GC_PITCH + c16 * 16;
            int grow = r0 + row;
            int inb = (grow < NN);
            int cg = inb ? grow : 0;
            cpa16(sb + (uint32_t)(AH - sm) + off, AHg + cg * 16 + c16, inb);
            cpa16(sb + (uint32_t)(BH - sm) + off, BHg + gg, 1);
        }
        CP_COMMIT();
        // group 1: AL + BL
        #pragma unroll
        for (int it = 0; it < 4; it++) {
            int gg = it * 512 + tid;
            int row = gg >> 4, c16 = gg & 15;
            int off = row * GC_PITCH + c16 * 16;
            int grow = r0 + row;
            int inb = (grow < NN);
            int cg = inb ? grow : 0;
            cpa16(sb + (uint32_t)(AL - sm) + off, ALg + cg * 16 + c16, inb);
            cpa16(sb + (uint32_t)(BL - sm) + off, BLg + gg, 1);
        }
        CP_COMMIT();
        CP_WAIT(1);
        __syncthreads();

        float acc[2][4][4];
        #pragma unroll
        for (int a = 0; a < 2; a++)
            #pragma unroll
            for (int b = 0; b < 4; b++)
                #pragma unroll
                for (int c = 0; c < 4; c++) acc[a][b][c] = 0.f;

        #pragma unroll
        for (int t = 0; t < 3; t++) {
            if (t == 1) {
                CP_WAIT(0);
                __syncthreads();
            }
            const char* pA = (t == 2) ? AL : AH;
            const char* pB = (t == 1) ? BL : BH;
            #pragma unroll
            for (int k0 = 0; k0 < 8; k0++) {
                int kb = (k0 * 16 + tg * 2) * 2;   // byte col offset
                uint32_t afr[2][4];
                #pragma unroll
                for (int tm = 0; tm < 2; tm++) {
                    int r = wm * 32 + tm * 16 + g;
                    const char* base = pA + r * GC_PITCH + kb;
                    afr[tm][0] = *reinterpret_cast<const uint32_t*>(base);
                    afr[tm][1] = *reinterpret_cast<const uint32_t*>(base + 8 * GC_PITCH);
                    afr[tm][2] = *reinterpret_cast<const uint32_t*>(base + 16);
                    afr[tm][3] = *reinterpret_cast<const uint32_t*>(base + 8 * GC_PITCH + 16);
                }
                uint32_t bfr[4][2];
                #pragma unroll
                for (int tn = 0; tn < 4; tn++) {
                    int n = wn * 32 + tn * 8 + g;
                    const char* base = pB + n * GC_PITCH + kb;
                    bfr[tn][0] = *reinterpret_cast<const uint32_t*>(base);
                    bfr[tn][1] = *reinterpret_cast<const uint32_t*>(base + 16);
                }
                #pragma unroll
                for (int tm = 0; tm < 2; tm++)
                    #pragma unroll
                    for (int tn = 0; tn < 4; tn++)
                        mma_bf16(acc[tm][tn], afr[tm], bfr[tn]);
            }
        }
        // epilogue: scale by dinv[row], store fp32 h2
        #pragma unroll
        for (int tm = 0; tm < 2; tm++) {
            int r1 = r0 + wm * 32 + tm * 16 + g;
            int r2 = r1 + 8;
            float s1 = (r1 < NN) ? d_dinv[r1] : 0.f;
            float s2 = (r2 < NN) ? d_dinv[r2] : 0.f;
            #pragma unroll
            for (int tn = 0; tn < 4; tn++) {
                int c = wn * 32 + tn * 8 + tg * 2;
                if (r1 < NN)
                    *reinterpret_cast<float2*>(&d_h2[r1 * AD + c]) =
                        make_float2(acc[tm][tn][0] * s1, acc[tm][tn][1] * s1);
                if (r2 < NN)
                    *reinterpret_cast<float2*>(&d_h2[r2 * AD + c]) =
                        make_float2(acc[tm][tn][2] * s2, acc[tm][tn][3] * s2);
            }
        }
    } else {
        // ================== GNA GEMM: D = A @ [W2t;W1t]^T -> [t | u], K=64 ==================
        int r0 = (blockIdx.x - MMB) * 128;
        char* AH = sm;
        char* AL = sm + GN_PLANE;
        char* BH = sm + 2 * GN_PLANE;
        char* BL = sm + 3 * GN_PLANE;
        const uint4* AHg = reinterpret_cast<const uint4*>(d_gbf_hi);
        const uint4* ALg = reinterpret_cast<const uint4*>(d_gbf_lo);
        const uint4* B2H = reinterpret_cast<const uint4*>(w2thi);
        const uint4* B2L = reinterpret_cast<const uint4*>(w2tlo);
        const uint4* B1H = reinterpret_cast<const uint4*>(w1thi);
        const uint4* B1L = reinterpret_cast<const uint4*>(w1tlo);
        // group 0: AH + BH
        #pragma unroll
        for (int it = 0; it < 2; it++) {
            int gg = it * 512 + tid;
            int row = gg >> 3, c8 = gg & 7;
            int off = row * GN_PITCH + c8 * 16;
            int grow = r0 + row;
            int inb = (grow < NN);
            int cg = inb ? grow : 0;
            cpa16(sb + (uint32_t)(AH - sm) + off, AHg + cg * 8 + c8, inb);
            const uint4* bsrc = (row < 64) ? (B2H + row * 8 + c8) : (B1H + (row - 64) * 8 + c8);
            cpa16(sb + (uint32_t)(BH - sm) + off, bsrc, 1);
        }
        CP_COMMIT();
        // group 1: AL + BL
        #pragma unroll
        for (int it = 0; it < 2; it++) {
            int gg = it * 512 + tid;
            int row = gg >> 3, c8 = gg & 7;
            int off = row * GN_PITCH + c8 * 16;
            int grow = r0 + row;
            int inb = (grow < NN);
            int cg = inb ? grow : 0;
            cpa16(sb + (uint32_t)(AL - sm) + off, ALg + cg * 8 + c8, inb);
            const uint4* bsrc = (row < 64) ? (B2L + row * 8 + c8) : (B1L + (row - 64) * 8 + c8);
            cpa16(sb + (uint32_t)(BL - sm) + off, bsrc, 1);
        }
        CP_COMMIT();
        CP_WAIT(1);
        __syncthreads();

        float acc[2][4][4];
        #pragma unroll
        for (int a = 0; a < 2; a++)
            #pragma unroll
            for (int b = 0; b < 4; b++)
                #pragma unroll
                for (int c = 0; c < 4; c++) acc[a][b][c] = 0.f;

        #pragma unroll
        for (int t = 0; t < 3; t++) {
            if (t == 1) {
                CP_WAIT(0);
                __syncthreads();
            }
            const char* pA = (t == 2) ? AL : AH;
            const char* pB = (t == 1) ? BL : BH;
            #pragma unroll
            for (int k0 = 0; k0 < 4; k0++) {
                int kb = (k0 * 16 + tg * 2) * 2;
                uint32_t afr[2][4];
                #pragma unroll
                for (int tm = 0; tm < 2; tm++) {
                    int r = wm * 32 + tm * 16 + g;
                    const char* base = pA + r * GN_PITCH + kb;
                    afr[tm][0] = *reinterpret_cast<const uint32_t*>(base);
                    afr[tm][1] = *reinterpret_cast<const uint32_t*>(base + 8 * GN_PITCH);
                    afr[tm][2] = *reinterpret_cast<const uint32_t*>(base + 16);
                    afr[tm][3] = *reinterpret_cast<const uint32_t*>(base + 8 * GN_PITCH + 16);
                }
                uint32_t bfr[4][2];
                #pragma unroll
                for (int tn = 0; tn < 4; tn++) {
                    int n = wn * 32 + tn * 8 + g;
                    const char* base = pB + n * GN_PITCH + kb;
                    bfr[tn][0] = *reinterpret_cast<const uint32_t*>(base);
                    bfr[tn][1] = *reinterpret_cast<const uint32_t*>(base + 16);
                }
                #pragma unroll
                for (int tm = 0; tm < 2; tm++)
                    #pragma unroll
                    for (int tn = 0; tn < 4; tn++)
                        mma_bf16(acc[tm][tn], afr[tm], bfr[tn]);
            }
        }
        __syncthreads();   // compute done; smem reusable for proj partials

        float* sP = reinterpret_cast<float*>(sm);   // [128][2]
        int isT = (wn < 2);
        const float* bias = isT ? b2 : b1;
        #pragma unroll
        for (int tm = 0; tm < 2; tm++) {
            int rl1 = wm * 32 + tm * 16 + g;
            int r1 = r0 + rl1;
            int r2 = r1 + 8;
            float p1 = 0.f, p2 = 0.f;
            #pragma unroll
            for (int tn = 0; tn < 4; tn++) {
                int cg = wn * 32 + tn * 8 + tg * 2;       // 0..127 across [t|u]
                int c = isT ? cg : (cg - 64);             // local 0..63
                float2 bb = *reinterpret_cast<const float2*>(&bias[c]);
                float v0 = acc[tm][tn][0] + bb.x;
                float v1 = acc[tm][tn][1] + bb.y;
                float v2 = acc[tm][tn][2] + bb.x;
                float v3 = acc[tm][tn][3] + bb.y;
                if (isT) {
                    float2 av = *reinterpret_cast<const float2*>(&avec[c]);
                    p1 += v0 * av.x + v1 * av.y;
                    p2 += v2 * av.x + v3 * av.y;
                    if (r1 < NN) *reinterpret_cast<float2*>(&d_t[r1 * SD + c]) = make_float2(v0, v1);
                    if (r2 < NN) *reinterpret_cast<float2*>(&d_t[r2 * SD + c]) = make_float2(v2, v3);
                } else {
                    if (r1 < NN) *reinterpret_cast<float2*>(&d_u[r1 * SD + c]) = make_float2(v0, v1);
                    if (r2 < NN) *reinterpret_cast<float2*>(&d_u[r2 * SD + c]) = make_float2(v2, v3);
                }
            }
            if (isT) {
                p1 += __shfl_xor_sync(0xffffffffu, p1, 1);
                p1 += __shfl_xor_sync(0xffffffffu, p1, 2);
                p2 += __shfl_xor_sync(0xffffffffu, p2, 1);
                p2 += __shfl_xor_sync(0xffffffffu, p2, 2);
                if (tg == 0) {
                    sP[rl1 * 2 + wn] = p1;
                    sP[(rl1 + 8) * 2 + wn] = p2;
                }
            }
        }
        __syncthreads();
        if (tid < 128) {
            int row = r0 + tid;
            if (row < NN) d_proj[row] = sP[tid * 2] + sP[tid * 2 + 1];
        }
    }
}

// ================= megakernel B: GCN gather + GNA attn (warp per node) =================
__global__ void k_mega_edge(const float* __restrict__ bias, float* __restrict__ hout,
                            int fin, float* __restrict__ gout) {
    int tid = threadIdx.x;
    int lane = tid & 31;

    if (blockIdx.x < WB) {
        int n = blockIdx.x * 8 + (tid >> 5);
        if (n >= NN) return;
        int beg = d_off[n], end = d_off[n + 1];
        float din = d_dinv[n];

        float4 acc = *reinterpret_cast<const float4*>(&d_h2[n * AD + lane * 4]);
        float4 acc2 = make_float4(0.f, 0.f, 0.f, 0.f);
        int e = beg;
        for (; e + 4 <= end; e += 4) {
            int s0 = d_csrc[e + 0];
            int s1 = d_csrc[e + 1];
            int s2 = d_csrc[e + 2];
            int s3 = d_csrc[e + 3];
            float4 v0 = *reinterpret_cast<const float4*>(&d_h2[s0 * AD + lane * 4]);
            float4 v1 = *reinterpret_cast<const float4*>(&d_h2[s1 * AD + lane * 4]);
            float4 v2 = *reinterpret_cast<const float4*>(&d_h2[s2 * AD + lane * 4]);
            float4 v3 = *reinterpret_cast<const float4*>(&d_h2[s3 * AD + lane * 4]);
            acc.x += v0.x; acc.y += v0.y; acc.z += v0.z; acc.w += v0.w;
            acc2.x += v1.x; acc2.y += v1.y; acc2.z += v1.z; acc2.w += v1.w;
            acc.x += v2.x; acc.y += v2.y; acc.z += v2.z; acc.w += v2.w;
            acc2.x += v3.x; acc2.y += v3.y; acc2.z += v3.z; acc2.w += v3.w;
        }
        for (; e < end; e++) {
            int s0 = d_csrc[e];
            float4 v0 = *reinterpret_cast<const float4*>(&d_h2[s0 * AD + lane * 4]);
            acc.x += v0.x; acc.y += v0.y; acc.z += v0.z; acc.w += v0.w;
        }
        acc.x += acc2.x; acc.y += acc2.y; acc.z += acc2.z; acc.w += acc2.w;

        float4 b = *reinterpret_cast<const float4*>(&bias[lane * 4]);
        acc.x = acc.x * din + b.x; acc.y = acc.y * din + b.y;
        acc.z = acc.z * din + b.z; acc.w = acc.w * din + b.w;
        if (!fin) {
            acc.x = gelu_exact(acc.x); acc.y = gelu_exact(acc.y);
            acc.z = gelu_exact(acc.z); acc.w = gelu_exact(acc.w);
            uint2 ph = make_uint2(bfpack(acc.x, acc.y), bfpack(acc.z, acc.w));
            uint2 pl = make_uint2(bfpack(bflo(acc.x), bflo(acc.y)),
                                  bfpack(bflo(acc.z), bflo(acc.w)));
            reinterpret_cast<uint2*>(d_hbf_hi)[n * 32 + lane] = ph;
            reinterpret_cast<uint2*>(d_hbf_lo)[n * 32 + lane] = pl;
        } else {
            *reinterpret_cast<float4*>(&hout[n * AD + lane * 4]) = acc;
        }
    } else {
        int n = (blockIdx.x - WB) * 8 + (tid >> 5);
        if (n >= NN) return;
        int beg = d_off[n], end = d_off[n + 1];
        float projd = d_proj[n];

        float amax = 0.f;
        for (int c = beg; c < end; c += 32) {
            int i = c + lane;
            if (i < end) {
                float a = projd - d_proj[d_csrc[i]];
                amax = fmaxf(amax, a);
            }
        }
        #pragma unroll
        for (int o = 16; o > 0; o >>= 1)
            amax = fmaxf(amax, __shfl_xor_sync(0xffffffffu, amax, o));

        float es = expf(-amax);
        float2 tn = *reinterpret_cast<const float2*>(&d_t[n * SD + lane * 2]);
        float mx = es * tn.x, my = es * tn.y;
        float den = es;

        for (int c = beg; c < end; c += 32) {
            int i = c + lane;
            int cnt = min(32, end - c);
            int srcl = (i < end) ? d_csrc[i] : 0;
            float al = (i < end) ? (projd - d_proj[srcl]) : 0.f;
            float ewl = expf(al - amax);
            int j = 0;
            for (; j + 4 <= cnt; j += 4) {
                float e0 = __shfl_sync(0xffffffffu, ewl, j + 0);
                float e1 = __shfl_sync(0xffffffffu, ewl, j + 1);
                float e2 = __shfl_sync(0xffffffffu, ewl, j + 2);
                float e3 = __shfl_sync(0xffffffffu, ewl, j + 3);
                int s0 = __shfl_sync(0xffffffffu, srcl, j + 0);
                int s1 = __shfl_sync(0xffffffffu, srcl, j + 1);
                int s2 = __shfl_sync(0xffffffffu, srcl, j + 2);
                int s3 = __shfl_sync(0xffffffffu, srcl, j + 3);
                float2 t0 = *reinterpret_cast<const float2*>(&d_t[s0 * SD + lane * 2]);
                float2 t1 = *reinterpret_cast<const float2*>(&d_t[s1 * SD + lane * 2]);
                float2 t2 = *reinterpret_cast<const float2*>(&d_t[s2 * SD + lane * 2]);
                float2 t3 = *reinterpret_cast<const float2*>(&d_t[s3 * SD + lane * 2]);
                mx += e0 * t0.x; my += e0 * t0.y;
                mx += e1 * t1.x; my += e1 * t1.y;
                mx += e2 * t2.x; my += e2 * t2.y;
                mx += e3 * t3.x; my += e3 * t3.y;
                den += e0 + e1 + e2 + e3;
            }
            for (; j < cnt; j++) {
                float ew = __shfl_sync(0xffffffffu, ewl, j);
                int sj = __shfl_sync(0xffffffffu, srcl, j);
                float2 tv = *reinterpret_cast<const float2*>(&d_t[sj * SD + lane * 2]);
                mx += ew * tv.x; my += ew * tv.y;
                den += ew;
            }
        }
        float inv = 1.f / (den + 1e-16f);
        float2 uv = *reinterpret_cast<const float2*>(&d_u[n * SD + lane * 2]);
        float2 res;
        res.x = gelu_exact(uv.x + mx * inv);
        res.y = gelu_exact(uv.y + my * inv);
        if (!fin) {
            reinterpret_cast<uint32_t*>(d_gbf_hi)[n * 32 + lane] = bfpack(res.x, res.y);
            reinterpret_cast<uint32_t*>(d_gbf_lo)[n * 32 + lane] = bfpack(bflo(res.x), bflo(res.y));
        } else {
            *reinterpret_cast<float2*>(&gout[n * SD + lane * 2]) = res;
        }
    }
}

// ---------------- host launcher ----------------
extern "C" void kernel_launch(void* const* d_in, const int* in_sizes, int n_in,
                              void* d_out, int out_size) {
    const float* x    = (const float*)d_in[0];
    const float* s    = (const float*)d_in[1];
    const int*   ei   = (const int*)d_in[2];
    const float* gcnW = (const float*)d_in[3];
    const float* gcnb = (const float*)d_in[4];
    const float* w1W  = (const float*)d_in[5];
    const float* w1b  = (const float*)d_in[6];
    const float* w2W  = (const float*)d_in[7];
    const float* w2b  = (const float*)d_in[8];
    const float* ga   = (const float*)d_in[9];
    float* out = (float*)d_out;

    cudaFuncSetAttribute(k_mma, cudaFuncAttributeMaxDynamicSharedMemorySize, MM_SMEM);

    void* p;
    cudaGetSymbolAddress(&p, d_deg);   int* degp = (int*)p;
    cudaGetSymbolAddress(&p, d_wthi);  __nv_bfloat16* wthi = (__nv_bfloat16*)p;
    cudaGetSymbolAddress(&p, d_wtlo);  __nv_bfloat16* wtlo = (__nv_bfloat16*)p;
    cudaGetSymbolAddress(&p, d_w2thi); __nv_bfloat16* w2thi = (__nv_bfloat16*)p;
    cudaGetSymbolAddress(&p, d_w2tlo); __nv_bfloat16* w2tlo = (__nv_bfloat16*)p;
    cudaGetSymbolAddress(&p, d_w1thi); __nv_bfloat16* w1thi = (__nv_bfloat16*)p;
    cudaGetSymbolAddress(&p, d_w1tlo); __nv_bfloat16* w1tlo = (__nv_bfloat16*)p;

    cudaMemsetAsync(degp, 0, NN * sizeof(int));
    k_prep<<<PB_TOT, 256>>>(x, s, ei, gcnW, w2W, w1W);
    k_scanA<<<SCB, 256>>>();
    k_scanB<<<1, 256>>>();
    k_scanC<<<SCB, 256>>>();
    k_csr_scatter<<<(NE / 4 + 255) / 256, 256>>>(ei);

    for (int i = 0; i < NL; i++) {
        k_mma<<<2 * MMB, 512, MM_SMEM>>>(wthi + i * AD * AD, wtlo + i * AD * AD,
                                         w2thi + i * SD * SD, w2tlo + i * SD * SD,
                                         w1thi + i * SD * SD, w1tlo + i * SD * SD,
                                         w2b + i * SD, w1b + i * SD, ga + i * SD);
        k_mega_edge<<<2 * WB, 256>>>(gcnb + i * AD, out, (i == NL - 1) ? 1 : 0, out + NN * AD);
    }
}

// round 12
// speedup vs baseline: 1.3212x; 1.0233x over previous
#include <cuda_runtime.h>
#include <cuda_bf16.h>
#include <math.h>
#include <stdint.h>

#define NN 50000
#define NE 800000
#define AD 128
#define SD 64
#define NL 4

#define WB 6250           // ceil(NN/8): warp-per-node blocks
#define GCB 782           // ceil(NN/64): 64-row MMA tiles
#define SCB 196           // ceil(NN/256): scan blocks

// ---------------- scratch (static device globals; no allocation) ----------------
__device__ float d_h2[NN * AD];                // GCN post-GEMM (dinv-scaled), fp32 for gather
__device__ float d_t[NN * SD];
__device__ float d_u[NN * SD];
__device__ float d_proj[NN];
__device__ float d_dinv[NN];
__device__ int   d_deg[NN];
__device__ int   d_off[NN + 1];
__device__ int   d_cur[NN];
__device__ int   d_part[256];
__device__ int   d_csrc[NE];
// bf16 split planes (activations)
__device__ __nv_bfloat16 d_hbf_hi[NN * AD];
__device__ __nv_bfloat16 d_hbf_lo[NN * AD];
__device__ __nv_bfloat16 d_gbf_hi[NN * SD];
__device__ __nv_bfloat16 d_gbf_lo[NN * SD];
// bf16 split planes (weights, transposed K-major: Wt[col][k])
__device__ __nv_bfloat16 d_wthi[NL * AD * AD];
__device__ __nv_bfloat16 d_wtlo[NL * AD * AD];
__device__ __nv_bfloat16 d_w2thi[NL * SD * SD];
__device__ __nv_bfloat16 d_w2tlo[NL * SD * SD];
__device__ __nv_bfloat16 d_w1thi[NL * SD * SD];
__device__ __nv_bfloat16 d_w1tlo[NL * SD * SD];

__device__ __forceinline__ float gelu_exact(float x) {
    return 0.5f * x * (1.0f + erff(x * 0.7071067811865476f));
}
__device__ __forceinline__ uint32_t bfpack(float a, float b) {
    __nv_bfloat162 h = __floats2bfloat162_rn(a, b);
    return *reinterpret_cast<uint32_t*>(&h);
}
__device__ __forceinline__ float bflo(float a) {
    __nv_bfloat16 h = __float2bfloat16(a);
    return a - __bfloat162float(h);
}

// mma.sync m16n8k16 bf16 -> f32 (baseline PTX, sm_80+)
__device__ __forceinline__ void mma_bf16(float* c, const uint32_t* a, const uint32_t* b) {
    asm volatile(
        "mma.sync.aligned.m16n8k16.row.col.f32.bf16.bf16.f32 "
        "{%0,%1,%2,%3}, {%4,%5,%6,%7}, {%8,%9}, {%0,%1,%2,%3};"
        : "+f"(c[0]), "+f"(c[1]), "+f"(c[2]), "+f"(c[3])
        : "r"(a[0]), "r"(a[1]), "r"(a[2]), "r"(a[3]), "r"(b[0]), "r"(b[1]));
}

__device__ __forceinline__ uint32_t smem_to_u32(const void* p) {
    uint32_t a;
    asm("{ .reg .u64 t; cvta.to.shared.u64 t, %1; cvt.u32.u64 %0, t; }" : "=r"(a) : "l"(p));
    return a;
}
// cp.async 16B; pred==0 -> zero-fill (src still a valid clamped address)
__device__ __forceinline__ void cpa16(uint32_t saddr, const void* g, int pred) {
    asm volatile(
        "{\n\t.reg .pred p;\n\tsetp.ne.b32 p, %2, 0;\n\t"
        "@p cp.async.cg.shared.global [%0], [%1], 16;\n\t"
        "@!p cp.async.cg.shared.global [%0], [%1], 16, 0;\n\t}"
        :: "r"(saddr), "l"(g), "r"(pred));
}
#define CP_COMMIT() asm volatile("cp.async.commit_group;" ::: "memory")
#define CP_WAIT(n)  asm volatile("cp.async.wait_group %0;" :: "n"(n) : "memory")

// ---------------- prep: convert x/s/W planes + degree count (grid-fused) ----------------
#define PB_X 3125
#define PB_S 1563
#define PB_D 782
#define PB_WG 32
#define PB_W2 8
#define PB_W1 8
#define PB_TOT (PB_X + PB_S + PB_D + PB_WG + PB_W2 + PB_W1)

__global__ void k_prep(const float* __restrict__ x, const float* __restrict__ s,
                       const int* __restrict__ ei, const float* __restrict__ gcnW,
                       const float* __restrict__ w2W, const float* __restrict__ w1W) {
    int b = blockIdx.x, tid = threadIdx.x;
    if (b < PB_X) {
        int i8 = (b * 256 + tid) * 8;
        float4 f0 = *reinterpret_cast<const float4*>(x + i8);
        float4 f1 = *reinterpret_cast<const float4*>(x + i8 + 4);
        uint4 hv = make_uint4(bfpack(f0.x, f0.y), bfpack(f0.z, f0.w),
                              bfpack(f1.x, f1.y), bfpack(f1.z, f1.w));
        uint4 lv = make_uint4(bfpack(bflo(f0.x), bflo(f0.y)), bfpack(bflo(f0.z), bflo(f0.w)),
                              bfpack(bflo(f1.x), bflo(f1.y)), bfpack(bflo(f1.z), bflo(f1.w)));
        reinterpret_cast<uint4*>(d_hbf_hi)[i8 >> 3] = hv;
        reinterpret_cast<uint4*>(d_hbf_lo)[i8 >> 3] = lv;
    } else if (b < PB_X + PB_S) {
        int i8 = ((b - PB_X) * 256 + tid) * 8;
        if (i8 < NN * SD) {
            float4 f0 = *reinterpret_cast<const float4*>(s + i8);
            float4 f1 = *reinterpret_cast<const float4*>(s + i8 + 4);
            uint4 hv = make_uint4(bfpack(f0.x, f0.y), bfpack(f0.z, f0.w),
                                  bfpack(f1.x, f1.y), bfpack(f1.z, f1.w));
            uint4 lv = make_uint4(bfpack(bflo(f0.x), bflo(f0.y)), bfpack(bflo(f0.z), bflo(f0.w)),
                                  bfpack(bflo(f1.x), bflo(f1.y)), bfpack(bflo(f1.z), bflo(f1.w)));
            reinterpret_cast<uint4*>(d_gbf_hi)[i8 >> 3] = hv;
            reinterpret_cast<uint4*>(d_gbf_lo)[i8 >> 3] = lv;
        }
    } else if (b < PB_X + PB_S + PB_D) {
        int i = (b - PB_X - PB_S) * 256 + tid;
        if (i < NE / 4) {
            int4 d4 = reinterpret_cast<const int4*>(ei + NE)[i];
            atomicAdd(&d_deg[d4.x], 1);
            atomicAdd(&d_deg[d4.y], 1);
            atomicAdd(&d_deg[d4.z], 1);
            atomicAdd(&d_deg[d4.w], 1);
        }
    } else if (b < PB_X + PB_S + PB_D + PB_WG) {
        int base = ((b - PB_X - PB_S - PB_D) * 256 + tid) * 8;
        #pragma unroll
        for (int j = 0; j < 8; j++) {
            int e = base + j;
            int l = e >> 14, r = e & 16383, k = r >> 7, c = r & 127;
            float v = gcnW[e];
            __nv_bfloat16 h = __float2bfloat16(v);
            d_wthi[(l << 14) + c * 128 + k] = h;
            d_wtlo[(l << 14) + c * 128 + k] = __float2bfloat16(v - __bfloat162float(h));
        }
    } else {
        int isW1 = (b >= PB_X + PB_S + PB_D + PB_WG + PB_W2);
        int bb = b - PB_X - PB_S - PB_D - PB_WG - (isW1 ? PB_W2 : 0);
        const float* Wsrc = isW1 ? w1W : w2W;
        __nv_bfloat16* Phi = isW1 ? d_w1thi : d_w2thi;
        __nv_bfloat16* Plo = isW1 ? d_w1tlo : d_w2tlo;
        int base = (bb * 256 + tid) * 8;
        #pragma unroll
        for (int j = 0; j < 8; j++) {
            int e = base + j;
            int l = e >> 12, r = e & 4095, k = r >> 6, c = r & 63;
            float v = Wsrc[e];
            __nv_bfloat16 h = __float2bfloat16(v);
            Phi[(l << 12) + c * 64 + k] = h;
            Plo[(l << 12) + c * 64 + k] = __float2bfloat16(v - __bfloat162float(h));
        }
    }
}

// ---------------- 3-phase scan ----------------
__device__ __forceinline__ int block_incl_scan_256(int v, int* warpsums) {
    int lane = threadIdx.x & 31, wid = threadIdx.x >> 5;
    int x = v;
    #pragma unroll
    for (int o = 1; o < 32; o <<= 1) {
        int y = __shfl_up_sync(0xffffffffu, x, o);
        if (lane >= o) x += y;
    }
    if (lane == 31) warpsums[wid] = x;
    __syncthreads();
    if (wid == 0 && lane < 8) {
        int w = warpsums[lane];
        #pragma unroll
        for (int o = 1; o < 8; o <<= 1) {
            int y = __shfl_up_sync(0xffu, w, o);
            if (lane >= o) w += y;
        }
        warpsums[lane] = w;
    }
    __syncthreads();
    return x + (wid > 0 ? warpsums[wid - 1] : 0);
}

__global__ void k_scanA() {
    __shared__ int ws[8];
    int idx = blockIdx.x * 256 + threadIdx.x;
    int v = (idx < NN) ? d_deg[idx] : 0;
    int incl = block_incl_scan_256(v, ws);
    if (idx < NN) {
        d_off[idx + 1] = incl;                   // local inclusive, fixed up in C
        d_dinv[idx] = rsqrtf((float)(v + 1));
    }
    if (threadIdx.x == 255) d_part[blockIdx.x] = incl;
}

__global__ void k_scanB() {
    __shared__ int ws[8];
    int tid = threadIdx.x;
    int v = (tid < SCB) ? d_part[tid] : 0;
    int incl = block_incl_scan_256(v, ws);
    d_part[tid] = incl - v;                      // exclusive
    if (tid == 0) d_off[0] = 0;
}

__global__ void k_scanC() {
    int idx = blockIdx.x * 256 + threadIdx.x;
    if (idx < NN) {
        int base = d_part[blockIdx.x];
        int incl = d_off[idx + 1] + base;
        d_off[idx + 1] = incl;
        d_cur[idx] = incl - d_deg[idx];
    }
}

__global__ void k_csr_scatter(const int* __restrict__ ei) {
    int i = blockIdx.x * blockDim.x + threadIdx.x;
    if (i < NE / 4) {
        int4 s4 = reinterpret_cast<const int4*>(ei)[i];
        int4 d4 = reinterpret_cast<const int4*>(ei + NE)[i];
        d_csrc[atomicAdd(&d_cur[d4.x], 1)] = s4.x;
        d_csrc[atomicAdd(&d_cur[d4.y], 1)] = s4.y;
        d_csrc[atomicAdd(&d_cur[d4.z], 1)] = s4.z;
        d_csrc[atomicAdd(&d_cur[d4.w], 1)] = s4.w;
    }
}

// ================= fused MMA megakernel: 64-row tiles, 256 thr, 2 blocks/SM =================
#define GC_PITCH 272
#define GC_APLANE 17408          // 64 rows
#define GC_BPLANE 34816          // 128 cols
#define GN_PITCH 144
#define GN_APLANE 9216           // 64 rows
#define GN_BPLANE 18432          // 128 rows ([W2t;W1t])
#define MM_SMEM (2 * GC_APLANE + 2 * GC_BPLANE)   // 104448 -> 2 blocks/SM

__global__ __launch_bounds__(256) void k_mma(
    const __nv_bfloat16* __restrict__ wthi, const __nv_bfloat16* __restrict__ wtlo,
    const __nv_bfloat16* __restrict__ w2thi, const __nv_bfloat16* __restrict__ w2tlo,
    const __nv_bfloat16* __restrict__ w1thi, const __nv_bfloat16* __restrict__ w1tlo,
    const float* __restrict__ b2, const float* __restrict__ b1,
    const float* __restrict__ avec) {
    extern __shared__ char sm[];
    uint32_t sb = smem_to_u32(sm);
    int tid = threadIdx.x;
    int wid = tid >> 5, lane = tid & 31;
    int g = lane >> 2, tg = lane & 3;
    int wm = wid & 1, wn = wid >> 1;       // 2 m-warps x 4 n-warps

    if (blockIdx.x < GCB) {
        // ================== GCN GEMM: 64x128, K=128 ==================
        int r0 = blockIdx.x * 64;
        char* AH = sm;
        char* AL = sm + GC_APLANE;
        char* BH = sm + 2 * GC_APLANE;
        char* BL = sm + 2 * GC_APLANE + GC_BPLANE;
        const uint4* AHg = reinterpret_cast<const uint4*>(d_hbf_hi);
        const uint4* ALg = reinterpret_cast<const uint4*>(d_hbf_lo);
        const uint4* BHg = reinterpret_cast<const uint4*>(wthi);
        const uint4* BLg = reinterpret_cast<const uint4*>(wtlo);
        // group 0: AH + BH
        #pragma unroll
        for (int it = 0; it < 4; it++) {
            int gg = it * 256 + tid;              // 0..1023: A groups
            int row = gg >> 4, c16 = gg & 15;
            int off = row * GC_PITCH + c16 * 16;
            int grow = r0 + row;
            int inb = (grow < NN);
            int cg = inb ? grow : 0;
            cpa16(sb + (uint32_t)(AH - sm) + off, AHg + cg * 16 + c16, inb);
        }
        #pragma unroll
        for (int it = 0; it < 8; it++) {
            int gg = it * 256 + tid;              // 0..2047: B groups
            int row = gg >> 4, c16 = gg & 15;
            int off = row * GC_PITCH + c16 * 16;
            cpa16(sb + (uint32_t)(BH - sm) + off, BHg + gg, 1);
        }
        CP_COMMIT();
        // group 1: AL + BL
        #pragma unroll
        for (int it = 0; it < 4; it++) {
            int gg = it * 256 + tid;
            int row = gg >> 4, c16 = gg & 15;
            int off = row * GC_PITCH + c16 * 16;
            int grow = r0 + row;
            int inb = (grow < NN);
            int cg = inb ? grow : 0;
            cpa16(sb + (uint32_t)(AL - sm) + off, ALg + cg * 16 + c16, inb);
        }
        #pragma unroll
        for (int it = 0; it < 8; it++) {
            int gg = it * 256 + tid;
            int row = gg >> 4, c16 = gg & 15;
            int off = row * GC_PITCH + c16 * 16;
            cpa16(sb + (uint32_t)(BL - sm) + off, BLg + gg, 1);
        }
        CP_COMMIT();
        CP_WAIT(1);
        __syncthreads();

        float acc[2][4][4];
        #pragma unroll
        for (int a = 0; a < 2; a++)
            #pragma unroll
            for (int b = 0; b < 4; b++)
                #pragma unroll
                for (int c = 0; c < 4; c++) acc[a][b][c] = 0.f;

        #pragma unroll
        for (int t = 0; t < 3; t++) {
            if (t == 1) {
                CP_WAIT(0);
                __syncthreads();
            }
            const char* pA = (t == 2) ? AL : AH;
            const char* pB = (t == 1) ? BL : BH;
            #pragma unroll
            for (int k0 = 0; k0 < 8; k0++) {
                int kb = (k0 * 16 + tg * 2) * 2;   // byte col offset
                uint32_t afr[2][4];
                #pragma unroll
                for (int tm = 0; tm < 2; tm++) {
                    int r = wm * 32 + tm * 16 + g;
                    const char* base = pA + r * GC_PITCH + kb;
                    afr[tm][0] = *reinterpret_cast<const uint32_t*>(base);
                    afr[tm][1] = *reinterpret_cast<const uint32_t*>(base + 8 * GC_PITCH);
                    afr[tm][2] = *reinterpret_cast<const uint32_t*>(base + 16);
                    afr[tm][3] = *reinterpret_cast<const uint32_t*>(base + 8 * GC_PITCH + 16);
                }
                uint32_t bfr[4][2];
                #pragma unroll
                for (int tn = 0; tn < 4; tn++) {
                    int n = wn * 32 + tn * 8 + g;
                    const char* base = pB + n * GC_PITCH + kb;
                    bfr[tn][0] = *reinterpret_cast<const uint32_t*>(base);
                    bfr[tn][1] = *reinterpret_cast<const uint32_t*>(base + 16);
                }
                #pragma unroll
                for (int tm = 0; tm < 2; tm++)
                    #pragma unroll
                    for (int tn = 0; tn < 4; tn++)
                        mma_bf16(acc[tm][tn], afr[tm], bfr[tn]);
            }
        }
        // epilogue: scale by dinv[row], store fp32 h2
        #pragma unroll
        for (int tm = 0; tm < 2; tm++) {
            int r1 = r0 + wm * 32 + tm * 16 + g;
            int r2 = r1 + 8;
            float s1 = (r1 < NN) ? d_dinv[r1] : 0.f;
            float s2 = (r2 < NN) ? d_dinv[r2] : 0.f;
            #pragma unroll
            for (int tn = 0; tn < 4; tn++) {
                int c = wn * 32 + tn * 8 + tg * 2;
                if (r1 < NN)
                    *reinterpret_cast<float2*>(&d_h2[r1 * AD + c]) =
                        make_float2(acc[tm][tn][0] * s1, acc[tm][tn][1] * s1);
                if (r2 < NN)
                    *reinterpret_cast<float2*>(&d_h2[r2 * AD + c]) =
                        make_float2(acc[tm][tn][2] * s2, acc[tm][tn][3] * s2);
            }
        }
    } else {
        // ================== GNA GEMM: D = A @ [W2t;W1t]^T -> [t | u], K=64 ==================
        int r0 = (blockIdx.x - GCB) * 64;
        char* AH = sm;
        char* AL = sm + GN_APLANE;
        char* BH = sm + 2 * GN_APLANE;
        char* BL = sm + 2 * GN_APLANE + GN_BPLANE;
        const uint4* AHg = reinterpret_cast<const uint4*>(d_gbf_hi);
        const uint4* ALg = reinterpret_cast<const uint4*>(d_gbf_lo);
        const uint4* B2H = reinterpret_cast<const uint4*>(w2thi);
        const uint4* B2L = reinterpret_cast<const uint4*>(w2tlo);
        const uint4* B1H = reinterpret_cast<const uint4*>(w1thi);
        const uint4* B1L = reinterpret_cast<const uint4*>(w1tlo);
        // group 0: AH + BH
        #pragma unroll
        for (int it = 0; it < 2; it++) {
            int gg = it * 256 + tid;              // 0..511: A groups
            int row = gg >> 3, c8 = gg & 7;
            int off = row * GN_PITCH + c8 * 16;
            int grow = r0 + row;
            int inb = (grow < NN);
            int cg = inb ? grow : 0;
            cpa16(sb + (uint32_t)(AH - sm) + off, AHg + cg * 8 + c8, inb);
        }
        #pragma unroll
        for (int it = 0; it < 4; it++) {
            int gg = it * 256 + tid;              // 0..1023: B groups
            int row = gg >> 3, c8 = gg & 7;
            int off = row * GN_PITCH + c8 * 16;
            const uint4* bsrc = (row < 64) ? (B2H + row * 8 + c8) : (B1H + (row - 64) * 8 + c8);
            cpa16(sb + (uint32_t)(BH - sm) + off, bsrc, 1);
        }
        CP_COMMIT();
        // group 1: AL + BL
        #pragma unroll
        for (int it = 0; it < 2; it++) {
            int gg = it * 256 + tid;
            int row = gg >> 3, c8 = gg & 7;
            int off = row * GN_PITCH + c8 * 16;
            int grow = r0 + row;
            int inb = (grow < NN);
            int cg = inb ? grow : 0;
            cpa16(sb + (uint32_t)(AL - sm) + off, ALg + cg * 8 + c8, inb);
        }
        #pragma unroll
        for (int it = 0; it < 4; it++) {
            int gg = it * 256 + tid;
            int row = gg >> 3, c8 = gg & 7;
            int off = row * GN_PITCH + c8 * 16;
            const uint4* bsrc = (row < 64) ? (B2L + row * 8 + c8) : (B1L + (row - 64) * 8 + c8);
            cpa16(sb + (uint32_t)(BL - sm) + off, bsrc, 1);
        }
        CP_COMMIT();
        CP_WAIT(1);
        __syncthreads();

        float acc[2][4][4];
        #pragma unroll
        for (int a = 0; a < 2; a++)
            #pragma unroll
            for (int b = 0; b < 4; b++)
                #pragma unroll
                for (int c = 0; c < 4; c++) acc[a][b][c] = 0.f;

        #pragma unroll
        for (int t = 0; t < 3; t++) {
            if (t == 1) {
                CP_WAIT(0);
                __syncthreads();
            }
            const char* pA = (t == 2) ? AL : AH;
            const char* pB = (t == 1) ? BL : BH;
            #pragma unroll
            for (int k0 = 0; k0 < 4; k0++) {
                int kb = (k0 * 16 + tg * 2) * 2;
                uint32_t afr[2][4];
                #pragma unroll
                for (int tm = 0; tm < 2; tm++) {
                    int r = wm * 32 + tm * 16 + g;
                    const char* base = pA + r * GN_PITCH + kb;
                    afr[tm][0] = *reinterpret_cast<const uint32_t*>(base);
                    afr[tm][1] = *reinterpret_cast<const uint32_t*>(base + 8 * GN_PITCH);
                    afr[tm][2] = *reinterpret_cast<const uint32_t*>(base + 16);
                    afr[tm][3] = *reinterpret_cast<const uint32_t*>(base + 8 * GN_PITCH + 16);
                }
                uint32_t bfr[4][2];
                #pragma unroll
                for (int tn = 0; tn < 4; tn++) {
                    int n = wn * 32 + tn * 8 + g;
                    const char* base = pB + n * GN_PITCH + kb;
                    bfr[tn][0] = *reinterpret_cast<const uint32_t*>(base);
                    bfr[tn][1] = *reinterpret_cast<const uint32_t*>(base + 16);
                }
                #pragma unroll
                for (int tm = 0; tm < 2; tm++)
                    #pragma unroll
                    for (int tn = 0; tn < 4; tn++)
                        mma_bf16(acc[tm][tn], afr[tm], bfr[tn]);
            }
        }
        __syncthreads();   // compute done; smem reusable for proj partials

        float* sP = reinterpret_cast<float*>(sm);   // [64][2]
        int isT = (wn < 2);
        const float* bias = isT ? b2 : b1;
        #pragma unroll
        for (int tm = 0; tm < 2; tm++) {
            int rl1 = wm * 32 + tm * 16 + g;
            int r1 = r0 + rl1;
            int r2 = r1 + 8;
            float p1 = 0.f, p2 = 0.f;
            #pragma unroll
            for (int tn = 0; tn < 4; tn++) {
                int cg = wn * 32 + tn * 8 + tg * 2;       // 0..127 across [t|u]
                int c = isT ? cg : (cg - 64);             // local 0..63
                float2 bb = *reinterpret_cast<const float2*>(&bias[c]);
                float v0 = acc[tm][tn][0] + bb.x;
                float v1 = acc[tm][tn][1] + bb.y;
                float v2 = acc[tm][tn][2] + bb.x;
                float v3 = acc[tm][tn][3] + bb.y;
                if (isT) {
                    float2 av = *reinterpret_cast<const float2*>(&avec[c]);
                    p1 += v0 * av.x + v1 * av.y;
                    p2 += v2 * av.x + v3 * av.y;
                    if (r1 < NN) *reinterpret_cast<float2*>(&d_t[r1 * SD + c]) = make_float2(v0, v1);
                    if (r2 < NN) *reinterpret_cast<float2*>(&d_t[r2 * SD + c]) = make_float2(v2, v3);
                } else {
                    if (r1 < NN) *reinterpret_cast<float2*>(&d_u[r1 * SD + c]) = make_float2(v0, v1);
                    if (r2 < NN) *reinterpret_cast<float2*>(&d_u[r2 * SD + c]) = make_float2(v2, v3);
                }
            }
            if (isT) {
                p1 += __shfl_xor_sync(0xffffffffu, p1, 1);
                p1 += __shfl_xor_sync(0xffffffffu, p1, 2);
                p2 += __shfl_xor_sync(0xffffffffu, p2, 1);
                p2 += __shfl_xor_sync(0xffffffffu, p2, 2);
                if (tg == 0) {
                    sP[rl1 * 2 + wn] = p1;
                    sP[(rl1 + 8) * 2 + wn] = p2;
                }
            }
        }
        __syncthreads();
        if (tid < 64) {
            int row = r0 + tid;
            if (row < NN) d_proj[row] = sP[tid * 2] + sP[tid * 2 + 1];
        }
    }
}

// ================= megakernel B: GCN gather + GNA attn (warp per node) =================
__global__ void k_mega_edge(const float* __restrict__ bias, float* __restrict__ hout,
                            int fin, float* __restrict__ gout) {
    int tid = threadIdx.x;
    int lane = tid & 31;

    if (blockIdx.x < WB) {
        int n = blockIdx.x * 8 + (tid >> 5);
        if (n >= NN) return;
        int beg = d_off[n], end = d_off[n + 1];
        float din = d_dinv[n];

        float4 acc = *reinterpret_cast<const float4*>(&d_h2[n * AD + lane * 4]);
        float4 acc2 = make_float4(0.f, 0.f, 0.f, 0.f);
        int e = beg;
        for (; e + 4 <= end; e += 4) {
            int s0 = d_csrc[e + 0];
            int s1 = d_csrc[e + 1];
            int s2 = d_csrc[e + 2];
            int s3 = d_csrc[e + 3];
            float4 v0 = *reinterpret_cast<const float4*>(&d_h2[s0 * AD + lane * 4]);
            float4 v1 = *reinterpret_cast<const float4*>(&d_h2[s1 * AD + lane * 4]);
            float4 v2 = *reinterpret_cast<const float4*>(&d_h2[s2 * AD + lane * 4]);
            float4 v3 = *reinterpret_cast<const float4*>(&d_h2[s3 * AD + lane * 4]);
            acc.x += v0.x; acc.y += v0.y; acc.z += v0.z; acc.w += v0.w;
            acc2.x += v1.x; acc2.y += v1.y; acc2.z += v1.z; acc2.w += v1.w;
            acc.x += v2.x; acc.y += v2.y; acc.z += v2.z; acc.w += v2.w;
            acc2.x += v3.x; acc2.y += v3.y; acc2.z += v3.z; acc2.w += v3.w;
        }
        for (; e < end; e++) {
            int s0 = d_csrc[e];
            float4 v0 = *reinterpret_cast<const float4*>(&d_h2[s0 * AD + lane * 4]);
            acc.x += v0.x; acc.y += v0.y; acc.z += v0.z; acc.w += v0.w;
        }
        acc.x += acc2.x; acc.y += acc2.y; acc.z += acc2.z; acc.w += acc2.w;

        float4 b = *reinterpret_cast<const float4*>(&bias[lane * 4]);
        acc.x = acc.x * din + b.x; acc.y = acc.y * din + b.y;
        acc.z = acc.z * din + b.z; acc.w = acc.w * din + b.w;
        if (!fin) {
            acc.x = gelu_exact(acc.x); acc.y = gelu_exact(acc.y);
            acc.z = gelu_exact(acc.z); acc.w = gelu_exact(acc.w);
            uint2 ph = make_uint2(bfpack(acc.x, acc.y), bfpack(acc.z, acc.w));
            uint2 pl = make_uint2(bfpack(bflo(acc.x), bflo(acc.y)),
                                  bfpack(bflo(acc.z), bflo(acc.w)));
            reinterpret_cast<uint2*>(d_hbf_hi)[n * 32 + lane] = ph;
            reinterpret_cast<uint2*>(d_hbf_lo)[n * 32 + lane] = pl;
        } else {
            *reinterpret_cast<float4*>(&hout[n * AD + lane * 4]) = acc;
        }
    } else {
        int n = (blockIdx.x - WB) * 8 + (tid >> 5);
        if (n >= NN) return;
        int beg = d_off[n], end = d_off[n + 1];
        float projd = d_proj[n];

        float amax = 0.f;
        for (int c = beg; c < end; c += 32) {
            int i = c + lane;
            if (i < end) {
                float a = projd - d_proj[d_csrc[i]];
                amax = fmaxf(amax, a);
            }
        }
        #pragma unroll
        for (int o = 16; o > 0; o >>= 1)
            amax = fmaxf(amax, __shfl_xor_sync(0xffffffffu, amax, o));

        float es = expf(-amax);
        float2 tn = *reinterpret_cast<const float2*>(&d_t[n * SD + lane * 2]);
        float mx = es * tn.x, my = es * tn.y;
        float den = es;

        for (int c = beg; c < end; c += 32) {
            int i = c + lane;
            int cnt = min(32, end - c);
            int srcl = (i < end) ? d_csrc[i] : 0;
            float al = (i < end) ? (projd - d_proj[srcl]) : 0.f;
            float ewl = expf(al - amax);
            int j = 0;
            for (; j + 4 <= cnt; j += 4) {
                float e0 = __shfl_sync(0xffffffffu, ewl, j + 0);
                float e1 = __shfl_sync(0xffffffffu, ewl, j + 1);
                float e2 = __shfl_sync(0xffffffffu, ewl, j + 2);
                float e3 = __shfl_sync(0xffffffffu, ewl, j + 3);
                int s0 = __shfl_sync(0xffffffffu, srcl, j + 0);
                int s1 = __shfl_sync(0xffffffffu, srcl, j + 1);
                int s2 = __shfl_sync(0xffffffffu, srcl, j + 2);
                int s3 = __shfl_sync(0xffffffffu, srcl, j + 3);
                float2 t0 = *reinterpret_cast<const float2*>(&d_t[s0 * SD + lane * 2]);
                float2 t1 = *reinterpret_cast<const float2*>(&d_t[s1 * SD + lane * 2]);
                float2 t2 = *reinterpret_cast<const float2*>(&d_t[s2 * SD + lane * 2]);
                float2 t3 = *reinterpret_cast<const float2*>(&d_t[s3 * SD + lane * 2]);
                mx += e0 * t0.x; my += e0 * t0.y;
                mx += e1 * t1.x; my += e1 * t1.y;
                mx += e2 * t2.x; my += e2 * t2.y;
                mx += e3 * t3.x; my += e3 * t3.y;
                den += e0 + e1 + e2 + e3;
            }
            for (; j < cnt; j++) {
                float ew = __shfl_sync(0xffffffffu, ewl, j);
                int sj = __shfl_sync(0xffffffffu, srcl, j);
                float2 tv = *reinterpret_cast<const float2*>(&d_t[sj * SD + lane * 2]);
                mx += ew * tv.x; my += ew * tv.y;
                den += ew;
            }
        }
        float inv = 1.f / (den + 1e-16f);
        float2 uv = *reinterpret_cast<const float2*>(&d_u[n * SD + lane * 2]);
        float2 res;
        res.x = gelu_exact(uv.x + mx * inv);
        res.y = gelu_exact(uv.y + my * inv);
        if (!fin) {
            reinterpret_cast<uint32_t*>(d_gbf_hi)[n * 32 + lane] = bfpack(res.x, res.y);
            reinterpret_cast<uint32_t*>(d_gbf_lo)[n * 32 + lane] = bfpack(bflo(res.x), bflo(res.y));
        } else {
            *reinterpret_cast<float2*>(&gout[n * SD + lane * 2]) = res;
        }
    }
}

// ---------------- host launcher ----------------
extern "C" void kernel_launch(void* const* d_in, const int* in_sizes, int n_in,
                              void* d_out, int out_size) {
    const float* x    = (const float*)d_in[0];
    const float* s    = (const float*)d_in[1];
    const int*   ei   = (const int*)d_in[2];
    const float* gcnW = (const float*)d_in[3];
    const float* gcnb = (const float*)d_in[4];
    const float* w1W  = (const float*)d_in[5];
    const float* w1b  = (const float*)d_in[6];
    const float* w2W  = (const float*)d_in[7];
    const float* w2b  = (const float*)d_in[8];
    const float* ga   = (const float*)d_in[9];
    float* out = (float*)d_out;

    cudaFuncSetAttribute(k_mma, cudaFuncAttributeMaxDynamicSharedMemorySize, MM_SMEM);

    void* p;
    cudaGetSymbolAddress(&p, d_deg);   int* degp = (int*)p;
    cudaGetSymbolAddress(&p, d_wthi);  __nv_bfloat16* wthi = (__nv_bfloat16*)p;
    cudaGetSymbolAddress(&p, d_wtlo);  __nv_bfloat16* wtlo = (__nv_bfloat16*)p;
    cudaGetSymbolAddress(&p, d_w2thi); __nv_bfloat16* w2thi = (__nv_bfloat16*)p;
    cudaGetSymbolAddress(&p, d_w2tlo); __nv_bfloat16* w2tlo = (__nv_bfloat16*)p;
    cudaGetSymbolAddress(&p, d_w1thi); __nv_bfloat16* w1thi = (__nv_bfloat16*)p;
    cudaGetSymbolAddress(&p, d_w1tlo); __nv_bfloat16* w1tlo = (__nv_bfloat16*)p;

    cudaMemsetAsync(degp, 0, NN * sizeof(int));
    k_prep<<<PB_TOT, 256>>>(x, s, ei, gcnW, w2W, w1W);
    k_scanA<<<SCB, 256>>>();
    k_scanB<<<1, 256>>>();
    k_scanC<<<SCB, 256>>>();
    k_csr_scatter<<<(NE / 4 + 255) / 256, 256>>>(ei);

    for (int i = 0; i < NL; i++) {
        k_mma<<<2 * GCB, 256, MM_SMEM>>>(wthi + i * AD * AD, wtlo + i * AD * AD,
                                         w2thi + i * SD * SD, w2tlo + i * SD * SD,
                                         w1thi + i * SD * SD, w1tlo + i * SD * SD,
                                         w2b + i * SD, w1b + i * SD, ga + i * SD);
        k_mega_edge<<<2 * WB, 256>>>(gcnb + i * AD, out, (i == NL - 1) ? 1 : 0, out + NN * AD);
    }
}

// round 14
// speedup vs baseline: 1.6408x; 1.2419x over previous
#include <cuda_runtime.h>
#include <cuda_bf16.h>
#include <cuda_fp16.h>
#include <math.h>
#include <stdint.h>

#define NN 50000
#define NE 800000
#define AD 128
#define SD 64
#define NL 4

#define WB 6250           // ceil(NN/8): warp-per-node blocks
#define GCB 782           // ceil(NN/64): 64-row MMA tiles
#define SCB 196           // ceil(NN/256): scan blocks

// ---------------- scratch (static device globals; no allocation) ----------------
__device__ __half d_h2h[NN * AD];              // GCN post-GEMM (dinv-scaled), fp16 for gather
__device__ __half d_th[NN * SD];               // GNA t, fp16 for attention gather
__device__ float d_u[NN * SD];
__device__ float d_proj[NN];
__device__ float d_dinv[NN];
__device__ int   d_deg[NN];
__device__ int   d_off[NN + 1];
__device__ int   d_cur[NN];
__device__ int   d_part[256];
__device__ int   d_csrc[NE];
// bf16 split planes (activations)
__device__ __nv_bfloat16 d_hbf_hi[NN * AD];
__device__ __nv_bfloat16 d_hbf_lo[NN * AD];
__device__ __nv_bfloat16 d_gbf_hi[NN * SD];
__device__ __nv_bfloat16 d_gbf_lo[NN * SD];
// bf16 split planes (weights, transposed K-major: Wt[col][k])
__device__ __nv_bfloat16 d_wthi[NL * AD * AD];
__device__ __nv_bfloat16 d_wtlo[NL * AD * AD];
__device__ __nv_bfloat16 d_w2thi[NL * SD * SD];
__device__ __nv_bfloat16 d_w2tlo[NL * SD * SD];
__device__ __nv_bfloat16 d_w1thi[NL * SD * SD];
__device__ __nv_bfloat16 d_w1tlo[NL * SD * SD];

__device__ __forceinline__ float gelu_exact(float x) {
    return 0.5f * x * (1.0f + erff(x * 0.7071067811865476f));
}
__device__ __forceinline__ uint32_t bfpack(float a, float b) {
    __nv_bfloat162 h = __floats2bfloat162_rn(a, b);
    return *reinterpret_cast<uint32_t*>(&h);
}
__device__ __forceinline__ float bflo(float a) {
    __nv_bfloat16 h = __float2bfloat16(a);
    return a - __bfloat162float(h);
}

// mma.sync m16n8k16 bf16 -> f32 (baseline PTX, sm_80+)
__device__ __forceinline__ void mma_bf16(float* c, const uint32_t* a, const uint32_t* b) {
    asm volatile(
        "mma.sync.aligned.m16n8k16.row.col.f32.bf16.bf16.f32 "
        "{%0,%1,%2,%3}, {%4,%5,%6,%7}, {%8,%9}, {%0,%1,%2,%3};"
        : "+f"(c[0]), "+f"(c[1]), "+f"(c[2]), "+f"(c[3])
        : "r"(a[0]), "r"(a[1]), "r"(a[2]), "r"(a[3]), "r"(b[0]), "r"(b[1]));
}

__device__ __forceinline__ uint32_t smem_to_u32(const void* p) {
    uint32_t a;
    asm("{ .reg .u64 t; cvta.to.shared.u64 t, %1; cvt.u32.u64 %0, t; }" : "=r"(a) : "l"(p));
    return a;
}
// cp.async 16B; pred==0 -> zero-fill (src still a valid clamped address)
__device__ __forceinline__ void cpa16(uint32_t saddr, const void* g, int pred) {
    asm volatile(
        "{\n\t.reg .pred p;\n\tsetp.ne.b32 p, %2, 0;\n\t"
        "@p cp.async.cg.shared.global [%0], [%1], 16;\n\t"
        "@!p cp.async.cg.shared.global [%0], [%1], 16, 0;\n\t}"
        :: "r"(saddr), "l"(g), "r"(pred));
}
#define CP_COMMIT() asm volatile("cp.async.commit_group;" ::: "memory")
#define CP_WAIT(n)  asm volatile("cp.async.wait_group %0;" :: "n"(n) : "memory")

// ---------------- prep: convert x/s/W planes + degree count (grid-fused) ----------------
#define PB_X 3125
#define PB_S 1563
#define PB_D 782
#define PB_WG 32
#define PB_W2 8
#define PB_W1 8
#define PB_TOT (PB_X + PB_S + PB_D + PB_WG + PB_W2 + PB_W1)

__global__ void k_prep(const float* __restrict__ x, const float* __restrict__ s,
                       const int* __restrict__ ei, const float* __restrict__ gcnW,
                       const float* __restrict__ w2W, const float* __restrict__ w1W) {
    int b = blockIdx.x, tid = threadIdx.x;
    if (b < PB_X) {
        int i8 = (b * 256 + tid) * 8;
        float4 f0 = *reinterpret_cast<const float4*>(x + i8);
        float4 f1 = *reinterpret_cast<const float4*>(x + i8 + 4);
        uint4 hv = make_uint4(bfpack(f0.x, f0.y), bfpack(f0.z, f0.w),
                              bfpack(f1.x, f1.y), bfpack(f1.z, f1.w));
        uint4 lv = make_uint4(bfpack(bflo(f0.x), bflo(f0.y)), bfpack(bflo(f0.z), bflo(f0.w)),
                              bfpack(bflo(f1.x), bflo(f1.y)), bfpack(bflo(f1.z), bflo(f1.w)));
        reinterpret_cast<uint4*>(d_hbf_hi)[i8 >> 3] = hv;
        reinterpret_cast<uint4*>(d_hbf_lo)[i8 >> 3] = lv;
    } else if (b < PB_X + PB_S) {
        int i8 = ((b - PB_X) * 256 + tid) * 8;
        if (i8 < NN * SD) {
            float4 f0 = *reinterpret_cast<const float4*>(s + i8);
            float4 f1 = *reinterpret_cast<const float4*>(s + i8 + 4);
            uint4 hv = make_uint4(bfpack(f0.x, f0.y), bfpack(f0.z, f0.w),
                                  bfpack(f1.x, f1.y), bfpack(f1.z, f1.w));
            uint4 lv = make_uint4(bfpack(bflo(f0.x), bflo(f0.y)), bfpack(bflo(f0.z), bflo(f0.w)),
                                  bfpack(bflo(f1.x), bflo(f1.y)), bfpack(bflo(f1.z), bflo(f1.w)));
            reinterpret_cast<uint4*>(d_gbf_hi)[i8 >> 3] = hv;
            reinterpret_cast<uint4*>(d_gbf_lo)[i8 >> 3] = lv;
        }
    } else if (b < PB_X + PB_S + PB_D) {
        int i = (b - PB_X - PB_S) * 256 + tid;
        if (i < NE / 4) {
            int4 d4 = reinterpret_cast<const int4*>(ei + NE)[i];
            atomicAdd(&d_deg[d4.x], 1);
            atomicAdd(&d_deg[d4.y], 1);
            atomicAdd(&d_deg[d4.z], 1);
            atomicAdd(&d_deg[d4.w], 1);
        }
    } else if (b < PB_X + PB_S + PB_D + PB_WG) {
        int base = ((b - PB_X - PB_S - PB_D) * 256 + tid) * 8;
        #pragma unroll
        for (int j = 0; j < 8; j++) {
            int e = base + j;
            int l = e >> 14, r = e & 16383, k = r >> 7, c = r & 127;
            float v = gcnW[e];
            __nv_bfloat16 h = __float2bfloat16(v);
            d_wthi[(l << 14) + c * 128 + k] = h;
            d_wtlo[(l << 14) + c * 128 + k] = __float2bfloat16(v - __bfloat162float(h));
        }
    } else {
        int isW1 = (b >= PB_X + PB_S + PB_D + PB_WG + PB_W2);
        int bb = b - PB_X - PB_S - PB_D - PB_WG - (isW1 ? PB_W2 : 0);
        const float* Wsrc = isW1 ? w1W : w2W;
        __nv_bfloat16* Phi = isW1 ? d_w1thi : d_w2thi;
        __nv_bfloat16* Plo = isW1 ? d_w1tlo : d_w2tlo;
        int base = (bb * 256 + tid) * 8;
        #pragma unroll
        for (int j = 0; j < 8; j++) {
            int e = base + j;
            int l = e >> 12, r = e & 4095, k = r >> 6, c = r & 63;
            float v = Wsrc[e];
            __nv_bfloat16 h = __float2bfloat16(v);
            Phi[(l << 12) + c * 64 + k] = h;
            Plo[(l << 12) + c * 64 + k] = __float2bfloat16(v - __bfloat162float(h));
        }
    }
}

// ---------------- 3-phase scan ----------------
__device__ __forceinline__ int block_incl_scan_256(int v, int* warpsums) {
    int lane = threadIdx.x & 31, wid = threadIdx.x >> 5;
    int x = v;
    #pragma unroll
    for (int o = 1; o < 32; o <<= 1) {
        int y = __shfl_up_sync(0xffffffffu, x, o);
        if (lane >= o) x += y;
    }
    if (lane == 31) warpsums[wid] = x;
    __syncthreads();
    if (wid == 0 && lane < 8) {
        int w = warpsums[lane];
        #pragma unroll
        for (int o = 1; o < 8; o <<= 1) {
            int y = __shfl_up_sync(0xffu, w, o);
            if (lane >= o) w += y;
        }
        warpsums[lane] = w;
    }
    __syncthreads();
    return x + (wid > 0 ? warpsums[wid - 1] : 0);
}

__global__ void k_scanA() {
    __shared__ int ws[8];
    int idx = blockIdx.x * 256 + threadIdx.x;
    int v = (idx < NN) ? d_deg[idx] : 0;
    int incl = block_incl_scan_256(v, ws);
    if (idx < NN) {
        d_off[idx + 1] = incl;                   // local inclusive, fixed up in C
        d_dinv[idx] = rsqrtf((float)(v + 1));
    }
    if (threadIdx.x == 255) d_part[blockIdx.x] = incl;
}

__global__ void k_scanB() {
    __shared__ int ws[8];
    int tid = threadIdx.x;
    int v = (tid < SCB) ? d_part[tid] : 0;
    int incl = block_incl_scan_256(v, ws);
    d_part[tid] = incl - v;                      // exclusive
    if (tid == 0) d_off[0] = 0;
}

__global__ void k_scanC() {
    int idx = blockIdx.x * 256 + threadIdx.x;
    if (idx < NN) {
        int base = d_part[blockIdx.x];
        int incl = d_off[idx + 1] + base;
        d_off[idx + 1] = incl;
        d_cur[idx] = incl - d_deg[idx];
    }
}

__global__ void k_csr_scatter(const int* __restrict__ ei) {
    int i = blockIdx.x * blockDim.x + threadIdx.x;
    if (i < NE / 4) {
        int4 s4 = reinterpret_cast<const int4*>(ei)[i];
        int4 d4 = reinterpret_cast<const int4*>(ei + NE)[i];
        d_csrc[atomicAdd(&d_cur[d4.x], 1)] = s4.x;
        d_csrc[atomicAdd(&d_cur[d4.y], 1)] = s4.y;
        d_csrc[atomicAdd(&d_cur[d4.z], 1)] = s4.z;
        d_csrc[atomicAdd(&d_cur[d4.w], 1)] = s4.w;
    }
}

// ================= fused MMA megakernel: 64-row tiles, 256 thr, 2 blocks/SM =================
#define GC_PITCH 272
#define GC_APLANE 17408          // 64 rows
#define GC_BPLANE 34816          // 128 cols
#define GN_PITCH 144
#define GN_APLANE 9216           // 64 rows
#define GN_BPLANE 18432          // 128 rows ([W2t;W1t])
#define MM_SMEM (2 * GC_APLANE + 2 * GC_BPLANE)   // 104448 -> 2 blocks/SM

__global__ __launch_bounds__(256) void k_mma(
    const __nv_bfloat16* __restrict__ wthi, const __nv_bfloat16* __restrict__ wtlo,
    const __nv_bfloat16* __restrict__ w2thi, const __nv_bfloat16* __restrict__ w2tlo,
    const __nv_bfloat16* __restrict__ w1thi, const __nv_bfloat16* __restrict__ w1tlo,
    const float* __restrict__ b2, const float* __restrict__ b1,
    const float* __restrict__ avec) {
    extern __shared__ char sm[];
    uint32_t sb = smem_to_u32(sm);
    int tid = threadIdx.x;
    int wid = tid >> 5, lane = tid & 31;
    int g = lane >> 2, tg = lane & 3;
    int wm = wid & 1, wn = wid >> 1;       // 2 m-warps x 4 n-warps

    if (blockIdx.x < GCB) {
        // ================== GCN GEMM: 64x128, K=128 ==================
        int r0 = blockIdx.x * 64;
        char* AH = sm;
        char* AL = sm + GC_APLANE;
        char* BH = sm + 2 * GC_APLANE;
        char* BL = sm + 2 * GC_APLANE + GC_BPLANE;
        const uint4* AHg = reinterpret_cast<const uint4*>(d_hbf_hi);
        const uint4* ALg = reinterpret_cast<const uint4*>(d_hbf_lo);
        const uint4* BHg = reinterpret_cast<const uint4*>(wthi);
        const uint4* BLg = reinterpret_cast<const uint4*>(wtlo);
        // group 0: AH + BH
        #pragma unroll
        for (int it = 0; it < 4; it++) {
            int gg = it * 256 + tid;              // 0..1023: A groups
            int row = gg >> 4, c16 = gg & 15;
            int off = row * GC_PITCH + c16 * 16;
            int grow = r0 + row;
            int inb = (grow < NN);
            int cg = inb ? grow : 0;
            cpa16(sb + (uint32_t)(AH - sm) + off, AHg + cg * 16 + c16, inb);
        }
        #pragma unroll
        for (int it = 0; it < 8; it++) {
            int gg = it * 256 + tid;              // 0..2047: B groups
            int row = gg >> 4, c16 = gg & 15;
            int off = row * GC_PITCH + c16 * 16;
            cpa16(sb + (uint32_t)(BH - sm) + off, BHg + gg, 1);
        }
        CP_COMMIT();
        // group 1: AL + BL
        #pragma unroll
        for (int it = 0; it < 4; it++) {
            int gg = it * 256 + tid;
            int row = gg >> 4, c16 = gg & 15;
            int off = row * GC_PITCH + c16 * 16;
            int grow = r0 + row;
            int inb = (grow < NN);
            int cg = inb ? grow : 0;
            cpa16(sb + (uint32_t)(AL - sm) + off, ALg + cg * 16 + c16, inb);
        }
        #pragma unroll
        for (int it = 0; it < 8; it++) {
            int gg = it * 256 + tid;
            int row = gg >> 4, c16 = gg & 15;
            int off = row * GC_PITCH + c16 * 16;
            cpa16(sb + (uint32_t)(BL - sm) + off, BLg + gg, 1);
        }
        CP_COMMIT();
        CP_WAIT(1);
        __syncthreads();

        float acc[2][4][4];
        #pragma unroll
        for (int a = 0; a < 2; a++)
            #pragma unroll
            for (int b = 0; b < 4; b++)
                #pragma unroll
                for (int c = 0; c < 4; c++) acc[a][b][c] = 0.f;

        #pragma unroll
        for (int t = 0; t < 3; t++) {
            if (t == 1) {
                CP_WAIT(0);
                __syncthreads();
            }
            const char* pA = (t == 2) ? AL : AH;
            const char* pB = (t == 1) ? BL : BH;
            #pragma unroll
            for (int k0 = 0; k0 < 8; k0++) {
                int kb = (k0 * 16 + tg * 2) * 2;   // byte col offset
                uint32_t afr[2][4];
                #pragma unroll
                for (int tm = 0; tm < 2; tm++) {
                    int r = wm * 32 + tm * 16 + g;
                    const char* base = pA + r * GC_PITCH + kb;
                    afr[tm][0] = *reinterpret_cast<const uint32_t*>(base);
                    afr[tm][1] = *reinterpret_cast<const uint32_t*>(base + 8 * GC_PITCH);
                    afr[tm][2] = *reinterpret_cast<const uint32_t*>(base + 16);
                    afr[tm][3] = *reinterpret_cast<const uint32_t*>(base + 8 * GC_PITCH + 16);
                }
                uint32_t bfr[4][2];
                #pragma unroll
                for (int tn = 0; tn < 4; tn++) {
                    int n = wn * 32 + tn * 8 + g;
                    const char* base = pB + n * GC_PITCH + kb;
                    bfr[tn][0] = *reinterpret_cast<const uint32_t*>(base);
                    bfr[tn][1] = *reinterpret_cast<const uint32_t*>(base + 16);
                }
                #pragma unroll
                for (int tm = 0; tm < 2; tm++)
                    #pragma unroll
                    for (int tn = 0; tn < 4; tn++)
                        mma_bf16(acc[tm][tn], afr[tm], bfr[tn]);
            }
        }
        // epilogue: scale by dinv[row], store fp16 h2
        #pragma unroll
        for (int tm = 0; tm < 2; tm++) {
            int r1 = r0 + wm * 32 + tm * 16 + g;
            int r2 = r1 + 8;
            float s1 = (r1 < NN) ? d_dinv[r1] : 0.f;
            float s2 = (r2 < NN) ? d_dinv[r2] : 0.f;
            #pragma unroll
            for (int tn = 0; tn < 4; tn++) {
                int c = wn * 32 + tn * 8 + tg * 2;
                if (r1 < NN)
                    *reinterpret_cast<__half2*>(&d_h2h[r1 * AD + c]) =
                        __floats2half2_rn(acc[tm][tn][0] * s1, acc[tm][tn][1] * s1);
                if (r2 < NN)
                    *reinterpret_cast<__half2*>(&d_h2h[r2 * AD + c]) =
                        __floats2half2_rn(acc[tm][tn][2] * s2, acc[tm][tn][3] * s2);
            }
        }
    } else {
        // ================== GNA GEMM: D = A @ [W2t;W1t]^T -> [t | u], K=64 ==================
        int r0 = (blockIdx.x - GCB) * 64;
        char* AH = sm;
        char* AL = sm + GN_APLANE;
        char* BH = sm + 2 * GN_APLANE;
        char* BL = sm + 2 * GN_APLANE + GN_BPLANE;
        const uint4* AHg = reinterpret_cast<const uint4*>(d_gbf_hi);
        const uint4* ALg = reinterpret_cast<const uint4*>(d_gbf_lo);
        const uint4* B2H = reinterpret_cast<const uint4*>(w2thi);
        const uint4* B2L = reinterpret_cast<const uint4*>(w2tlo);
        const uint4* B1H = reinterpret_cast<const uint4*>(w1thi);
        const uint4* B1L = reinterpret_cast<const uint4*>(w1tlo);
        // group 0: AH + BH
        #pragma unroll
        for (int it = 0; it < 2; it++) {
            int gg = it * 256 + tid;              // 0..511: A groups
            int row = gg >> 3, c8 = gg & 7;
            int off = row * GN_PITCH + c8 * 16;
            int grow = r0 + row;
            int inb = (grow < NN);
            int cg = inb ? grow : 0;
            cpa16(sb + (uint32_t)(AH - sm) + off, AHg + cg * 8 + c8, inb);
        }
        #pragma unroll
        for (int it = 0; it < 4; it++) {
            int gg = it * 256 + tid;              // 0..1023: B groups
            int row = gg >> 3, c8 = gg & 7;
            int off = row * GN_PITCH + c8 * 16;
            const uint4* bsrc = (row < 64) ? (B2H + row * 8 + c8) : (B1H + (row - 64) * 8 + c8);
            cpa16(sb + (uint32_t)(BH - sm) + off, bsrc, 1);
        }
        CP_COMMIT();
        // group 1: AL + BL
        #pragma unroll
        for (int it = 0; it < 2; it++) {
            int gg = it * 256 + tid;
            int row = gg >> 3, c8 = gg & 7;
            int off = row * GN_PITCH + c8 * 16;
            int grow = r0 + row;
            int inb = (grow < NN);
            int cg = inb ? grow : 0;
            cpa16(sb + (uint32_t)(AL - sm) + off, ALg + cg * 8 + c8, inb);
        }
        #pragma unroll
        for (int it = 0; it < 4; it++) {
            int gg = it * 256 + tid;
            int row = gg >> 3, c8 = gg & 7;
            int off = row * GN_PITCH + c8 * 16;
            const uint4* bsrc = (row < 64) ? (B2L + row * 8 + c8) : (B1L + (row - 64) * 8 + c8);
            cpa16(sb + (uint32_t)(BL - sm) + off, bsrc, 1);
        }
        CP_COMMIT();
        CP_WAIT(1);
        __syncthreads();

        float acc[2][4][4];
        #pragma unroll
        for (int a = 0; a < 2; a++)
            #pragma unroll
            for (int b = 0; b < 4; b++)
                #pragma unroll
                for (int c = 0; c < 4; c++) acc[a][b][c] = 0.f;

        #pragma unroll
        for (int t = 0; t < 3; t++) {
            if (t == 1) {
                CP_WAIT(0);
                __syncthreads();
            }
            const char* pA = (t == 2) ? AL : AH;
            const char* pB = (t == 1) ? BL : BH;
            #pragma unroll
            for (int k0 = 0; k0 < 4; k0++) {
                int kb = (k0 * 16 + tg * 2) * 2;
                uint32_t afr[2][4];
                #pragma unroll
                for (int tm = 0; tm < 2; tm++) {
                    int r = wm * 32 + tm * 16 + g;
                    const char* base = pA + r * GN_PITCH + kb;
                    afr[tm][0] = *reinterpret_cast<const uint32_t*>(base);
                    afr[tm][1] = *reinterpret_cast<const uint32_t*>(base + 8 * GN_PITCH);
                    afr[tm][2] = *reinterpret_cast<const uint32_t*>(base + 16);
                    afr[tm][3] = *reinterpret_cast<const uint32_t*>(base + 8 * GN_PITCH + 16);
                }
                uint32_t bfr[4][2];
                #pragma unroll
                for (int tn = 0; tn < 4; tn++) {
                    int n = wn * 32 + tn * 8 + g;
                    const char* base = pB + n * GN_PITCH + kb;
                    bfr[tn][0] = *reinterpret_cast<const uint32_t*>(base);
                    bfr[tn][1] = *reinterpret_cast<const uint32_t*>(base + 16);
                }
                #pragma unroll
                for (int tm = 0; tm < 2; tm++)
                    #pragma unroll
                    for (int tn = 0; tn < 4; tn++)
                        mma_bf16(acc[tm][tn], afr[tm], bfr[tn]);
            }
        }
        __syncthreads();   // compute done; smem reusable for proj partials

        float* sP = reinterpret_cast<float*>(sm);   // [64][2]
        int isT = (wn < 2);
        const float* bias = isT ? b2 : b1;
        #pragma unroll
        for (int tm = 0; tm < 2; tm++) {
            int rl1 = wm * 32 + tm * 16 + g;
            int r1 = r0 + rl1;
            int r2 = r1 + 8;
            float p1 = 0.f, p2 = 0.f;
            #pragma unroll
            for (int tn = 0; tn < 4; tn++) {
                int cg = wn * 32 + tn * 8 + tg * 2;       // 0..127 across [t|u]
                int c = isT ? cg : (cg - 64);             // local 0..63
                float2 bb = *reinterpret_cast<const float2*>(&bias[c]);
                float v0 = acc[tm][tn][0] + bb.x;
                float v1 = acc[tm][tn][1] + bb.y;
                float v2 = acc[tm][tn][2] + bb.x;
                float v3 = acc[tm][tn][3] + bb.y;
                if (isT) {
                    float2 av = *reinterpret_cast<const float2*>(&avec[c]);
                    p1 += v0 * av.x + v1 * av.y;
                    p2 += v2 * av.x + v3 * av.y;
                    if (r1 < NN) *reinterpret_cast<__half2*>(&d_th[r1 * SD + c]) = __floats2half2_rn(v0, v1);
                    if (r2 < NN) *reinterpret_cast<__half2*>(&d_th[r2 * SD + c]) = __floats2half2_rn(v2, v3);
                } else {
                    if (r1 < NN) *reinterpret_cast<float2*>(&d_u[r1 * SD + c]) = make_float2(v0, v1);
                    if (r2 < NN) *reinterpret_cast<float2*>(&d_u[r2 * SD + c]) = make_float2(v2, v3);
                }
            }
            if (isT) {
                p1 += __shfl_xor_sync(0xffffffffu, p1, 1);
                p1 += __shfl_xor_sync(0xffffffffu, p1, 2);
                p2 += __shfl_xor_sync(0xffffffffu, p2, 1);
                p2 += __shfl_xor_sync(0xffffffffu, p2, 2);
                if (tg == 0) {
                    sP[rl1 * 2 + wn] = p1;
                    sP[(rl1 + 8) * 2 + wn] = p2;
                }
            }
        }
        __syncthreads();
        if (tid < 64) {
            int row = r0 + tid;
            if (row < NN) d_proj[row] = sP[tid * 2] + sP[tid * 2 + 1];
        }
    }
}

// ================= megakernel B: GCN gather + GNA attn (warp per node), fp16 tables =================
__global__ void k_mega_edge(const float* __restrict__ bias, float* __restrict__ hout,
                            int fin, float* __restrict__ gout) {
    int tid = threadIdx.x;
    int lane = tid & 31;

    if (blockIdx.x < WB) {
        int n = blockIdx.x * 8 + (tid >> 5);
        if (n >= NN) return;
        int beg = d_off[n], end = d_off[n + 1];
        float din = d_dinv[n];

        // each lane covers 4 cols: load 2x half2 (8 bytes)
        const __half2* H2 = reinterpret_cast<const __half2*>(d_h2h);
        int cbase = lane * 2;   // in half2 units (4 halves = 2 half2)
        float4 acc, acc2 = make_float4(0.f, 0.f, 0.f, 0.f);
        {
            __half2 a0 = H2[n * 64 + cbase];
            __half2 a1 = H2[n * 64 + cbase + 1];
            float2 f0 = __half22float2(a0), f1 = __half22float2(a1);
            acc = make_float4(f0.x, f0.y, f1.x, f1.y);
        }
        int e = beg;
        for (; e + 4 <= end; e += 4) {
            int s0 = d_csrc[e + 0];
            int s1 = d_csrc[e + 1];
            int s2 = d_csrc[e + 2];
            int s3 = d_csrc[e + 3];
            uint2 v0 = *reinterpret_cast<const uint2*>(&H2[s0 * 64 + cbase]);
            uint2 v1 = *reinterpret_cast<const uint2*>(&H2[s1 * 64 + cbase]);
            uint2 v2 = *reinterpret_cast<const uint2*>(&H2[s2 * 64 + cbase]);
            uint2 v3 = *reinterpret_cast<const uint2*>(&H2[s3 * 64 + cbase]);
            float2 a, b;
            a = __half22float2(*reinterpret_cast<__half2*>(&v0.x));
            b = __half22float2(*reinterpret_cast<__half2*>(&v0.y));
            acc.x += a.x; acc.y += a.y; acc.z += b.x; acc.w += b.y;
            a = __half22float2(*reinterpret_cast<__half2*>(&v1.x));
            b = __half22float2(*reinterpret_cast<__half2*>(&v1.y));
            acc2.x += a.x; acc2.y += a.y; acc2.z += b.x; acc2.w += b.y;
            a = __half22float2(*reinterpret_cast<__half2*>(&v2.x));
            b = __half22float2(*reinterpret_cast<__half2*>(&v2.y));
            acc.x += a.x; acc.y += a.y; acc.z += b.x; acc.w += b.y;
            a = __half22float2(*reinterpret_cast<__half2*>(&v3.x));
            b = __half22float2(*reinterpret_cast<__half2*>(&v3.y));
            acc2.x += a.x; acc2.y += a.y; acc2.z += b.x; acc2.w += b.y;
        }
        for (; e < end; e++) {
            int s0 = d_csrc[e];
            uint2 v0 = *reinterpret_cast<const uint2*>(&H2[s0 * 64 + cbase]);
            float2 a = __half22float2(*reinterpret_cast<__half2*>(&v0.x));
            float2 b = __half22float2(*reinterpret_cast<__half2*>(&v0.y));
            acc.x += a.x; acc.y += a.y; acc.z += b.x; acc.w += b.y;
        }
        acc.x += acc2.x; acc.y += acc2.y; acc.z += acc2.z; acc.w += acc2.w;

        float4 b = *reinterpret_cast<const float4*>(&bias[lane * 4]);
        acc.x = acc.x * din + b.x; acc.y = acc.y * din + b.y;
        acc.z = acc.z * din + b.z; acc.w = acc.w * din + b.w;
        if (!fin) {
            acc.x = gelu_exact(acc.x); acc.y = gelu_exact(acc.y);
            acc.z = gelu_exact(acc.z); acc.w = gelu_exact(acc.w);
            uint2 ph = make_uint2(bfpack(acc.x, acc.y), bfpack(acc.z, acc.w));
            uint2 pl = make_uint2(bfpack(bflo(acc.x), bflo(acc.y)),
                                  bfpack(bflo(acc.z), bflo(acc.w)));
            reinterpret_cast<uint2*>(d_hbf_hi)[n * 32 + lane] = ph;
            reinterpret_cast<uint2*>(d_hbf_lo)[n * 32 + lane] = pl;
        } else {
            *reinterpret_cast<float4*>(&hout[n * AD + lane * 4]) = acc;
        }
    } else {
        int n = (blockIdx.x - WB) * 8 + (tid >> 5);
        if (n >= NN) return;
        int beg = d_off[n], end = d_off[n + 1];
        float projd = d_proj[n];

        float amax = 0.f;
        for (int c = beg; c < end; c += 32) {
            int i = c + lane;
            if (i < end) {
                float a = projd - d_proj[d_csrc[i]];
                amax = fmaxf(amax, a);
            }
        }
        #pragma unroll
        for (int o = 16; o > 0; o >>= 1)
            amax = fmaxf(amax, __shfl_xor_sync(0xffffffffu, amax, o));

        const __half2* TH = reinterpret_cast<const __half2*>(d_th);
        float es = expf(-amax);
        float2 tn = __half22float2(TH[n * 32 + lane]);
        float mx = es * tn.x, my = es * tn.y;
        float den = es;

        for (int c = beg; c < end; c += 32) {
            int i = c + lane;
            int cnt = min(32, end - c);
            int srcl = (i < end) ? d_csrc[i] : 0;
            float al = (i < end) ? (projd - d_proj[srcl]) : 0.f;
            float ewl = expf(al - amax);
            int j = 0;
            for (; j + 4 <= cnt; j += 4) {
                float e0 = __shfl_sync(0xffffffffu, ewl, j + 0);
                float e1 = __shfl_sync(0xffffffffu, ewl, j + 1);
                float e2 = __shfl_sync(0xffffffffu, ewl, j + 2);
                float e3 = __shfl_sync(0xffffffffu, ewl, j + 3);
                int s0 = __shfl_sync(0xffffffffu, srcl, j + 0);
                int s1 = __shfl_sync(0xffffffffu, srcl, j + 1);
                int s2 = __shfl_sync(0xffffffffu, srcl, j + 2);
                int s3 = __shfl_sync(0xffffffffu, srcl, j + 3);
                float2 t0 = __half22float2(TH[s0 * 32 + lane]);
                float2 t1 = __half22float2(TH[s1 * 32 + lane]);
                float2 t2 = __half22float2(TH[s2 * 32 + lane]);
                float2 t3 = __half22float2(TH[s3 * 32 + lane]);
                mx += e0 * t0.x; my += e0 * t0.y;
                mx += e1 * t1.x; my += e1 * t1.y;
                mx += e2 * t2.x; my += e2 * t2.y;
                mx += e3 * t3.x; my += e3 * t3.y;
                den += e0 + e1 + e2 + e3;
            }
            for (; j < cnt; j++) {
                float ew = __shfl_sync(0xffffffffu, ewl, j);
                int sj = __shfl_sync(0xffffffffu, srcl, j);
                float2 tv = __half22float2(TH[sj * 32 + lane]);
                mx += ew * tv.x; my += ew * tv.y;
                den += ew;
            }
        }
        float inv = 1.f / (den + 1e-16f);
        float2 uv = *reinterpret_cast<const float2*>(&d_u[n * SD + lane * 2]);
        float2 res;
        res.x = gelu_exact(uv.x + mx * inv);
        res.y = gelu_exact(uv.y + my * inv);
        if (!fin) {
            reinterpret_cast<uint32_t*>(d_gbf_hi)[n * 32 + lane] = bfpack(res.x, res.y);
            reinterpret_cast<uint32_t*>(d_gbf_lo)[n * 32 + lane] = bfpack(bflo(res.x), bflo(res.y));
        } else {
            *reinterpret_cast<float2*>(&gout[n * SD + lane * 2]) = res;
        }
    }
}

// ---------------- host launcher ----------------
extern "C" void kernel_launch(void* const* d_in, const int* in_sizes, int n_in,
                              void* d_out, int out_size) {
    const float* x    = (const float*)d_in[0];
    const float* s    = (const float*)d_in[1];
    const int*   ei   = (const int*)d_in[2];
    const float* gcnW = (const float*)d_in[3];
    const float* gcnb = (const float*)d_in[4];
    const float* w1W  = (const float*)d_in[5];
    const float* w1b  = (const float*)d_in[6];
    const float* w2W  = (const float*)d_in[7];
    const float* w2b  = (const float*)d_in[8];
    const float* ga   = (const float*)d_in[9];
    float* out = (float*)d_out;

    cudaFuncSetAttribute(k_mma, cudaFuncAttributeMaxDynamicSharedMemorySize, MM_SMEM);

    void* p;
    cudaGetSymbolAddress(&p, d_deg);   int* degp = (int*)p;
    cudaGetSymbolAddress(&p, d_wthi);  __nv_bfloat16* wthi = (__nv_bfloat16*)p;
    cudaGetSymbolAddress(&p, d_wtlo);  __nv_bfloat16* wtlo = (__nv_bfloat16*)p;
    cudaGetSymbolAddress(&p, d_w2thi); __nv_bfloat16* w2thi = (__nv_bfloat16*)p;
    cudaGetSymbolAddress(&p, d_w2tlo); __nv_bfloat16* w2tlo = (__nv_bfloat16*)p;
    cudaGetSymbolAddress(&p, d_w1thi); __nv_bfloat16* w1thi = (__nv_bfloat16*)p;
    cudaGetSymbolAddress(&p, d_w1tlo); __nv_bfloat16* w1tlo = (__nv_bfloat16*)p;

    cudaMemsetAsync(degp, 0, NN * sizeof(int));
    k_prep<<<PB_TOT, 256>>>(x, s, ei, gcnW, w2W, w1W);
    k_scanA<<<SCB, 256>>>();
    k_scanB<<<1, 256>>>();
    k_scanC<<<SCB, 256>>>();
    k_csr_scatter<<<(NE / 4 + 255) / 256, 256>>>(ei);

    for (int i = 0; i < NL; i++) {
        k_mma<<<2 * GCB, 256, MM_SMEM>>>(wthi + i * AD * AD, wtlo + i * AD * AD,
                                         w2thi + i * SD * SD, w2tlo + i * SD * SD,
                                         w1thi + i * SD * SD, w1tlo + i * SD * SD,
                                         w2b + i * SD, w1b + i * SD, ga + i * SD);
        k_mega_edge<<<2 * WB, 256>>>(gcnb + i * AD, out, (i == NL - 1) ? 1 : 0, out + NN * AD);
    }
}